// round 10
// baseline (speedup 1.0000x reference)
#include <cuda_runtime.h>
#include <math.h>

// ---------------- problem constants ----------------
#define Bz   4
#define Sz   256
#define Dz   300
#define Hz   256
#define H4z  1024
#define Lz   10
#define AGGz 62
#define NCLSz 22
#define FEATN 1626          // 4*H + 2 + 2*D
#define BSH  (Bz*Sz*Hz)     // 262144
#define BSS  (Bz*Sz*Sz)     // 262144
#define EPSf 1e-8f

// ---------------- scratch layout (floats) ----------------
constexpr long long OFF_WIHT_CF = 0;
constexpr long long OFF_WIHT_CB = OFF_WIHT_CF + (long long)Dz*H4z;
constexpr long long OFF_WIHT_AF = OFF_WIHT_CB + (long long)Dz*H4z;
constexpr long long OFF_WIHT_AB = OFF_WIHT_AF + (long long)AGGz*H4z;
constexpr long long OFF_FC1WT   = OFF_WIHT_AB + (long long)AGGz*H4z;
constexpr long long OFF_PRE_CTX = OFF_FC1WT + (long long)FEATN*512;
constexpr long long OFF_HS      = OFF_PRE_CTX + 4LL*Bz*Sz*H4z;   // p_fw,p_bw,h_fw,h_bw
constexpr long long OFF_NRM     = OFF_HS + 4LL*BSH;              // (4,B,S)
constexpr long long OFF_ATT     = OFF_NRM + 4LL*Bz*Sz;           // (2,B,S,S)
constexpr long long OFF_ROWSUM  = OFF_ATT + 2LL*BSS;             // (2,B,S)
constexpr long long OFF_COLSUM  = OFF_ROWSUM + 2LL*Bz*Sz;        // (2,B,S)
constexpr long long OFF_STATS   = OFF_COLSUM + 2LL*Bz*Sz;        // (4 kinds x 2 dirs, B,S,H)
constexpr long long OFF_NLW     = OFF_STATS + 8LL*BSH;           // (arr, B,S,L)
constexpr long long OFF_MVP     = OFF_NLW + 4LL*Bz*Sz*Lz;        // (B,S,62)
constexpr long long OFF_MVH     = OFF_MVP + (long long)Bz*Sz*AGGz;
constexpr long long OFF_PRE_AGG = OFF_MVH + (long long)Bz*Sz*AGGz;
constexpr long long OFF_HT      = OFF_PRE_AGG + 4LL*Bz*Sz*H4z;   // (4,B,H)
constexpr long long OFF_MEANS   = OFF_HT + 4LL*Bz*Hz;            // (2,B,D)
constexpr long long OFF_FC1O    = OFF_MEANS + 2LL*Bz*Dz;         // (B,512)
constexpr long long OFF_MMS     = OFF_FC1O + (long long)Bz*512;  // (2,B,L,P,Q) mm spill
constexpr long long SCRATCH_N   = OFF_MMS + 2LL*Bz*Lz*Sz*Sz + 64;

__device__ __align__(256) float g_s[SCRATCH_N];

__device__ __forceinline__ float sigmf_(float x){ return 1.f/(1.f+expf(-x)); }

__device__ __forceinline__ float warp_sum(float v){
    #pragma unroll
    for (int o = 16; o > 0; o >>= 1) v += __shfl_down_sync(0xffffffffu, v, o);
    return v;
}
__device__ __forceinline__ float warp_max(float v){
    #pragma unroll
    for (int o = 16; o > 0; o >>= 1) v = fmaxf(v, __shfl_down_sync(0xffffffffu, v, o));
    return v;
}
__device__ __forceinline__ unsigned smem_u32(const void* p){
    unsigned r;
    asm("{ .reg .u64 t; cvta.to.shared.u64 t, %1; cvt.u32.u64 %0, t; }" : "=r"(r) : "l"(p));
    return r;
}

// two transposes in one launch: z selects (src, dst); src (R,C) -> g_s[dst] as (C,R)
__global__ void transpose2_kernel(const float* __restrict__ s0, const float* __restrict__ s1,
                                  long long d0, long long d1, int R, int C){
    const float* src = blockIdx.z ? s1 : s0;
    long long dst = blockIdx.z ? d1 : d0;
    long long total = (long long)R*C;
    for (long long i = blockIdx.x*(long long)blockDim.x + threadIdx.x; i < total;
         i += (long long)gridDim.x*blockDim.x){
        int r = (int)(i / C), c = (int)(i % C);
        g_s[dst + (long long)c*R + r] = src[i];
    }
}

// three transposes in one launch (agg_f, agg_b, fc1)
__global__ void transpose3_kernel(const float* __restrict__ s0, const float* __restrict__ s1,
                                  const float* __restrict__ s2,
                                  long long d0, long long d1, long long d2,
                                  int R01, int C01, int R2, int C2){
    int z = blockIdx.z;
    const float* src = (z==0) ? s0 : (z==1) ? s1 : s2;
    long long dst = (z==0) ? d0 : (z==1) ? d1 : d2;
    int R = (z<2) ? R01 : R2, C = (z<2) ? C01 : C2;
    long long total = (long long)R*C;
    for (long long i = blockIdx.x*(long long)blockDim.x + threadIdx.x; i < total;
         i += (long long)gridDim.x*blockDim.x){
        int r = (int)(i / C), c = (int)(i % C);
        g_s[dst + (long long)c*R + r] = src[i];
    }
}

// Batched GEMM over z=0..3 with register double-buffered tile loads.
__global__ void __launch_bounds__(256) gemm4_kernel(
        const float* __restrict__ A0, const float* __restrict__ A1,
        long long a0_off, long long a1_off,
        long long bt_base, long long bt_stride,
        const float* __restrict__ biasF, const float* __restrict__ biasB,
        long long c_off, int M, int N, int K){
    int z = blockIdx.z;
    const float* A  = (z < 2) ? (A0 ? A0 : (g_s + a0_off)) : (A1 ? A1 : (g_s + a1_off));
    const float* Bt = g_s + bt_base + (long long)(z & 1)*bt_stride;
    const float* bias = (z & 1) ? biasB : biasF;
    float* C = g_s + c_off + (long long)z*M*N;
    __shared__ float As[16][68];
    __shared__ float Bs[16][68];
    int bm = blockIdx.y*64, bn = blockIdx.x*64;
    int tid = threadIdx.x;
    int tr = tid >> 4, tc = tid & 15;
    float acc[4][4] = {};
    float ra[4], rb[4];

    // prologue load k0 = 0
    #pragma unroll
    for (int ii = 0; ii < 4; ii++){
        int i = tid + ii*256;
        int m = i >> 4, k = i & 15;
        ra[ii] = (k < K) ? A[(long long)(bm+m)*K + k] : 0.f;
    }
    #pragma unroll
    for (int ii = 0; ii < 4; ii++){
        int i = tid + ii*256;
        int k = i >> 6, n = i & 63;
        rb[ii] = (k < K) ? Bt[(long long)k*N + bn + n] : 0.f;
    }

    for (int k0 = 0; k0 < K; k0 += 16){
        #pragma unroll
        for (int ii = 0; ii < 4; ii++){
            int i = tid + ii*256;
            As[i & 15][i >> 4] = ra[ii];
        }
        #pragma unroll
        for (int ii = 0; ii < 4; ii++){
            int i = tid + ii*256;
            Bs[i >> 6][i & 63] = rb[ii];
        }
        __syncthreads();
        int kn = k0 + 16;
        if (kn < K){
            #pragma unroll
            for (int ii = 0; ii < 4; ii++){
                int i = tid + ii*256;
                int m = i >> 4, k = i & 15;
                ra[ii] = (kn+k < K) ? A[(long long)(bm+m)*K + kn + k] : 0.f;
            }
            #pragma unroll
            for (int ii = 0; ii < 4; ii++){
                int i = tid + ii*256;
                int k = i >> 6, n = i & 63;
                rb[ii] = (kn+k < K) ? Bt[(long long)(kn+k)*N + bn + n] : 0.f;
            }
        }
        #pragma unroll
        for (int k = 0; k < 16; k++){
            float4 av = *(const float4*)&As[k][tr*4];
            float4 bv = *(const float4*)&Bs[k][tc*4];
            float a[4] = {av.x, av.y, av.z, av.w};
            float bb[4] = {bv.x, bv.y, bv.z, bv.w};
            #pragma unroll
            for (int i = 0; i < 4; i++)
                #pragma unroll
                for (int j = 0; j < 4; j++) acc[i][j] = fmaf(a[i], bb[j], acc[i][j]);
        }
        __syncthreads();
    }
    #pragma unroll
    for (int i = 0; i < 4; i++){
        int m = bm + tr*4 + i;
        #pragma unroll
        for (int j = 0; j < 4; j++){
            int n = bn + tc*4 + j;
            C[(long long)m*N + n] = acc[i][j] + bias[n];
        }
    }
}

// Cluster LSTM: 8-CTA cluster per unit; grid=128, 256 thr. (unchanged from R8)
__global__ void __cluster_dims__(8,1,1) __launch_bounds__(256,1) lstm3_kernel(int stage,
        const float* __restrict__ Whh_f, const float* __restrict__ Whh_b){
    int slice;
    asm("mov.u32 %0, %%cluster_ctarank;" : "=r"(slice));
    int unit = blockIdx.x >> 3;
    int grp = unit >> 3, dir = (unit >> 2) & 1, b = unit & 3;
    long long chunk = (long long)(grp*2 + dir)*Bz + b;
    const float* pre = g_s + (stage ? OFF_PRE_AGG : OFF_PRE_CTX) + chunk*(long long)Sz*H4z;
    const float* Whh = dir ? Whh_b : Whh_f;
    float* hs = g_s + OFF_HS + chunk*(long long)Sz*Hz;

    int t = threadIdx.x;
    int kw = t >> 5, l = t & 31;

    float wr[4][32];
    #pragma unroll
    for (int j = 0; j < 4; j++){
        int rho = 4*l + j;
        int G = (rho >> 5)*Hz + slice*32 + (rho & 31);
        const float4* row = (const float4*)(Whh + (long long)G*Hz) + kw*8;
        #pragma unroll
        for (int k4 = 0; k4 < 8; k4++){
            float4 v = row[k4];
            wr[j][4*k4+0]=v.x; wr[j][4*k4+1]=v.y; wr[j][4*k4+2]=v.z; wr[j][4*k4+3]=v.w;
        }
    }

    __shared__ float hsm[2][Hz];
    __shared__ float part[8][128];

    hsm[0][t] = 0.f;

    unsigned rbase[8];
    if (t < 32){
        unsigned lbase = smem_u32(&hsm[0][0]);
        #pragma unroll
        for (int rb = 0; rb < 8; rb++){
            asm("mapa.shared::cluster.u32 %0, %1, %2;"
                : "=r"(rbase[rb]) : "r"(lbase), "r"(rb));
        }
    }
    float c = 0.f, hlast = 0.f;
    __syncthreads();

    for (int ts = 0; ts < Sz; ts++){
        int s = dir ? (Sz-1-ts) : ts;
        float prev0=0.f, prev1=0.f, prev2=0.f, prev3=0.f;
        if (t < 32){
            long long base = (long long)s*H4z + slice*32 + t;
            prev0 = __ldg(&pre[base + 0*Hz]);
            prev1 = __ldg(&pre[base + 1*Hz]);
            prev2 = __ldg(&pre[base + 2*Hz]);
            prev3 = __ldg(&pre[base + 3*Hz]);
        }
        const float4* hp = (const float4*)(&hsm[ts & 1][0]) + kw*8;
        float hreg[32];
        #pragma unroll
        for (int k4 = 0; k4 < 8; k4++){
            float4 v = hp[k4];
            hreg[4*k4+0]=v.x; hreg[4*k4+1]=v.y; hreg[4*k4+2]=v.z; hreg[4*k4+3]=v.w;
        }
        float acc0=0.f, acc1=0.f, acc2=0.f, acc3=0.f;
        #pragma unroll
        for (int k = 0; k < 32; k++){
            float hv = hreg[k];
            acc0 = fmaf(wr[0][k], hv, acc0);
            acc1 = fmaf(wr[1][k], hv, acc1);
            acc2 = fmaf(wr[2][k], hv, acc2);
            acc3 = fmaf(wr[3][k], hv, acc3);
        }
        part[kw][4*l+0]=acc0; part[kw][4*l+1]=acc1;
        part[kw][4*l+2]=acc2; part[kw][4*l+3]=acc3;
        __syncthreads();
        if (t < 32){
            float t0=prev0, t1=prev1, t2=prev2, t3=prev3;
            #pragma unroll
            for (int w2 = 0; w2 < 8; w2++){
                t0 += part[w2][t];
                t1 += part[w2][32+t];
                t2 += part[w2][64+t];
                t3 += part[w2][96+t];
            }
            float iv = sigmf_(t0);
            float fv = sigmf_(t1);
            float gv = tanhf(t2);
            float ov = sigmf_(t3);
            c = fv*c + iv*gv;
            float h = ov*tanhf(c);
            hlast = h;
            if (!stage) hs[(long long)s*Hz + slice*32 + t] = h;
            if (ts < Sz-1){
                unsigned off = (unsigned)(((ts+1) & 1)*Hz + slice*32 + t)*4u;
                unsigned hb = __float_as_uint(h);
                #pragma unroll
                for (int rb = 0; rb < 8; rb++){
                    asm volatile("st.shared::cluster.u32 [%0], %1;"
                                 :: "r"(rbase[rb] + off), "r"(hb) : "memory");
                }
            }
        }
        if (ts < Sz-1){
            asm volatile("barrier.cluster.arrive.aligned;" ::: "memory");
            asm volatile("barrier.cluster.wait.aligned;" ::: "memory");
        }
    }
    if (stage && t < 32)
        g_s[OFF_HT + (long long)(grp*2+dir)*Bz*Hz + (long long)b*Hz + slice*32 + t] = hlast;
}

// fused: plain norm + 10 weighted norms per (arr, r)
__global__ void norms_all_kernel(const float* __restrict__ w3, const float* __restrict__ w4){
    int id = blockIdx.x;                 // 4*B*S
    int arr = id / (Bz*Sz), r = id % (Bz*Sz);
    const float* w = (arr & 1) ? w4 : w3;
    __shared__ float red[Lz+1][8];
    int tid = threadIdx.x, wp = tid >> 5, lane = tid & 31;
    float x = g_s[OFF_HS + (long long)arr*BSH + (long long)r*Hz + tid];
    float vv = x*x;
    float s0 = warp_sum(vv);
    if (lane == 0) red[Lz][wp] = s0;
    for (int l = 0; l < Lz; l++){
        float wv = __ldg(&w[l*Hz + tid]);
        float s = warp_sum(wv*wv*vv);
        if (lane == 0) red[l][wp] = s;
    }
    __syncthreads();
    if (tid < Lz){
        float s = 0.f;
        #pragma unroll
        for (int i = 0; i < 8; i++) s += red[tid][i];
        g_s[OFF_NLW + (long long)(arr*Bz*Sz + r)*Lz + tid] = sqrtf(s);
    }
    if (tid == Lz){
        float s = 0.f;
        #pragma unroll
        for (int i = 0; i < 8; i++) s += red[Lz][i];
        g_s[OFF_NRM + (long long)arr*Bz*Sz + r] = sqrtf(s);
    }
}

// cosine attention + fused row max/sum
__global__ void att_kernel(){
    int id = blockIdx.x;                 // 2*B*S
    int dir = id / (Bz*Sz), r = id % (Bz*Sz);
    int b = r / Sz;
    __shared__ float v1s[Hz];
    __shared__ float sbs[8], sbm[8];
    int tid = threadIdx.x, w = tid >> 5, lane = tid & 31;
    v1s[tid] = g_s[OFF_HS + (long long)dir*BSH + (long long)r*Hz + tid];
    __syncthreads();
    const float4* v2 = (const float4*)(g_s + OFF_HS + (long long)(2+dir)*BSH + (long long)(b*Sz + tid)*Hz);
    float acc = 0.f;
    #pragma unroll 8
    for (int h4 = 0; h4 < Hz/4; h4++){
        float4 o = v2[h4];
        acc = fmaf(v1s[4*h4+0], o.x, acc);
        acc = fmaf(v1s[4*h4+1], o.y, acc);
        acc = fmaf(v1s[4*h4+2], o.z, acc);
        acc = fmaf(v1s[4*h4+3], o.w, acc);
    }
    float n1 = g_s[OFF_NRM + (long long)dir*Bz*Sz + r];
    float n2 = g_s[OFF_NRM + (long long)(2+dir)*Bz*Sz + b*Sz + tid];
    float d = n1*n2;
    float a = acc / (d > EPSf ? d : EPSf);
    g_s[OFF_ATT + (long long)dir*BSS + (long long)r*Sz + tid] = a;
    float ssum = warp_sum(a);
    float smax = warp_max(a);
    if (lane == 0){ sbs[w] = ssum; sbm[w] = smax; }
    __syncthreads();
    if (tid == 0){
        float tots = 0.f, totm = -3.4e38f;
        #pragma unroll
        for (int i = 0; i < 8; i++){ tots += sbs[i]; totm = fmaxf(totm, sbm[i]); }
        g_s[OFF_ROWSUM + (long long)dir*Bz*Sz + r] = tots;
        if (dir == 0){
            float* mp = g_s + OFF_MVP + (long long)r*AGGz;
            mp[0] = totm;
            mp[1] = tots / (float)Sz;
        }
    }
}

__global__ void colstats_kernel(){
    int dir = blockIdx.x / Bz, b = blockIdx.x % Bz;   // grid 2*B
    int q = threadIdx.x;
    const float* att = g_s + OFF_ATT + (long long)dir*BSS + (long long)b*Sz*Sz;
    float s = 0.f, m = -3.4e38f;
    for (int p = 0; p < Sz; p++){
        float a = att[(long long)p*Sz + q];
        s += a; m = fmaxf(m, a);
    }
    g_s[OFF_COLSUM + (long long)dir*Bz*Sz + b*Sz + q] = s;
    if (dir == 0){
        float* mh = g_s + OFF_MVH + (long long)(b*Sz + q)*AGGz;
        mh[0] = m;
        mh[1] = s / (float)Sz;
    }
}

// mean_h / max_h, tiled: 8 p-rows per block; grid 2*B*32
__global__ void statsrow_kernel(){
    int id = blockIdx.x;
    int dir = id / (Bz*32); int rem = id % (Bz*32);
    int b = rem / 32, pt = rem % 32;
    __shared__ float arow[8][Sz];
    int tid = threadIdx.x;
    const float* att = g_s + OFF_ATT + (long long)dir*BSS + (long long)(b*Sz + pt*8)*Sz;
    for (int i = tid; i < 8*Sz; i += 256)
        arow[i >> 8][i & 255] = att[(long long)(i >> 8)*Sz + (i & 255)];
    __syncthreads();
    const float* vh = g_s + OFF_HS + (long long)(2+dir)*BSH + (long long)b*Sz*Hz;
    float sm[8], mx[8];
    #pragma unroll
    for (int p = 0; p < 8; p++){ sm[p] = 0.f; mx[p] = -3.4e38f; }
    for (int q = 0; q < Sz; q++){
        float vhv = vh[(long long)q*Hz + tid];
        #pragma unroll
        for (int p = 0; p < 8; p++){
            float pr = arow[p][q]*vhv;
            sm[p] += pr; mx[p] = fmaxf(mx[p], pr);
        }
    }
    #pragma unroll
    for (int p = 0; p < 8; p++){
        int rr = b*Sz + pt*8 + p;
        float rs = g_s[OFF_ROWSUM + (long long)dir*Bz*Sz + rr];
        g_s[OFF_STATS + (long long)(0*2+dir)*BSH + (long long)rr*Hz + tid] = sm[p] / (rs > EPSf ? rs : EPSf);
        g_s[OFF_STATS + (long long)(1*2+dir)*BSH + (long long)rr*Hz + tid] = mx[p];
    }
}

// mean_p / max_p, tiled: 8 q-cols per block; grid 2*B*32
__global__ void statscol_kernel(){
    int id = blockIdx.x;
    int dir = id / (Bz*32); int rem = id % (Bz*32);
    int b = rem / 32, qt = rem % 32;
    __shared__ float acol[8][Sz];       // acol[j][p] = att[p][qt*8+j]
    int tid = threadIdx.x;
    const float* att = g_s + OFF_ATT + (long long)dir*BSS + (long long)b*Sz*Sz;
    for (int i = tid; i < 8*Sz; i += 256){
        int p = i >> 3, j = i & 7;
        acol[j][p] = att[(long long)p*Sz + qt*8 + j];
    }
    __syncthreads();
    const float* vp = g_s + OFF_HS + (long long)dir*BSH + (long long)b*Sz*Hz;
    float sm[8], mx[8];
    #pragma unroll
    for (int j = 0; j < 8; j++){ sm[j] = 0.f; mx[j] = -3.4e38f; }
    for (int p = 0; p < Sz; p++){
        float vpv = vp[(long long)p*Hz + tid];
        #pragma unroll
        for (int j = 0; j < 8; j++){
            float pr = acol[j][p]*vpv;
            sm[j] += pr; mx[j] = fmaxf(mx[j], pr);
        }
    }
    #pragma unroll
    for (int j = 0; j < 8; j++){
        int rr = b*Sz + qt*8 + j;
        float cs = g_s[OFF_COLSUM + (long long)dir*Bz*Sz + rr];
        g_s[OFF_STATS + (long long)(2*2+dir)*BSH + (long long)rr*Hz + tid] = sm[j] / (cs > EPSf ? cs : EPSf);
        g_s[OFF_STATS + (long long)(3*2+dir)*BSH + (long long)rr*Hz + tid] = mx[j];
    }
}

// pairwise matching, single pass: row-max -> mv_p; spill mm -> scratch for colmax
__global__ void __launch_bounds__(256) pairwise_kernel(const float* __restrict__ w3, const float* __restrict__ w4){
    int id = blockIdx.x;                 // 2*B*S
    int dir = id / (Bz*Sz), r = id % (Bz*Sz);
    int b = r / Sz, s = r % Sz;
    const float* w = dir ? w4 : w3;
    __shared__ float w2s[Lz*Hz];
    __shared__ float vrow[Hz];
    __shared__ float red[Lz][8];
    int tid = threadIdx.x, wp = tid >> 5, lane = tid & 31;
    for (int i = tid; i < Lz*Hz; i += 256){ float x = w[i]; w2s[i] = x*x; }
    vrow[tid] = g_s[OFF_HS + (long long)dir*BSH + (long long)r*Hz + tid];
    __syncthreads();
    const float4* other = (const float4*)(g_s + OFF_HS + (long long)(2+dir)*BSH + (long long)(b*Sz + tid)*Hz);
    float acc[Lz];
    #pragma unroll
    for (int l = 0; l < Lz; l++) acc[l] = 0.f;
    for (int h4 = 0; h4 < Hz/4; h4++){
        float4 o = other[h4];
        float p0 = vrow[4*h4+0]*o.x, p1 = vrow[4*h4+1]*o.y;
        float p2 = vrow[4*h4+2]*o.z, p3 = vrow[4*h4+3]*o.w;
        #pragma unroll
        for (int l = 0; l < Lz; l++){
            acc[l] = fmaf(w2s[l*Hz + 4*h4+0], p0, acc[l]);
            acc[l] = fmaf(w2s[l*Hz + 4*h4+1], p1, acc[l]);
            acc[l] = fmaf(w2s[l*Hz + 4*h4+2], p2, acc[l]);
            acc[l] = fmaf(w2s[l*Hz + 4*h4+3], p3, acc[l]);
        }
    }
    const float* nfix = g_s + OFF_NLW + (long long)((0*2+dir)*Bz*Sz + b*Sz + s)*Lz;
    const float* nstr = g_s + OFF_NLW + (long long)((1*2+dir)*Bz*Sz + b*Sz + tid)*Lz;
    float* mmS = g_s + OFF_MMS + (long long)((dir*Bz + b)*Lz)*Sz*Sz;
    #pragma unroll
    for (int l = 0; l < Lz; l++){
        float d = nfix[l]*nstr[l];
        float v = acc[l] / (d > EPSf ? d : EPSf);
        mmS[(long long)l*Sz*Sz + (long long)s*Sz + tid] = v;
        float m = warp_max(v);
        if (lane == 0) red[l][wp] = m;
    }
    __syncthreads();
    if (tid < Lz){
        float m = red[tid][0];
        #pragma unroll
        for (int i = 1; i < 8; i++) m = fmaxf(m, red[tid][i]);
        g_s[OFF_MVP + (long long)(b*Sz + s)*AGGz + 2 + dir*10 + tid] = m;
    }
}

// column max of mm over p -> mv_h.  grid 2*B*L, 256 threads (tid = q)
__global__ void colmax_kernel(){
    int id = blockIdx.x;
    int dir = id / (Bz*Lz); int rem = id % (Bz*Lz);
    int b = rem / Lz, l = rem % Lz;
    int q = threadIdx.x;
    const float* mmS = g_s + OFF_MMS + ((long long)((dir*Bz + b)*Lz) + l)*Sz*Sz;
    float m = -3.4e38f;
    for (int p = 0; p < Sz; p++) m = fmaxf(m, mmS[(long long)p*Sz + q]);
    g_s[OFF_MVH + (long long)(b*Sz + q)*AGGz + 2 + dir*10 + l] = m;
}

// attentive / max-attentive mp_match, 8 combos
__global__ void mpmatch_kernel(const float* __restrict__ w5, const float* __restrict__ w6,
                               const float* __restrict__ w7, const float* __restrict__ w8){
    int id = blockIdx.x;                 // 8*B*S
    int k = id / (Bz*Sz), r = id % (Bz*Sz);
    int b = r / Sz, s = r % Sz;
    int dir = k & 1;
    int side = k >> 2;                   // 0: mv_p, 1: mv_h
    int arr  = side ? (2+dir) : dir;
    int kind = side ? ((k & 2) ? 3 : 2) : ((k & 2) ? 1 : 0);
    int wsel = k & 3;
    const float* w = (wsel==0) ? w5 : (wsel==1) ? w6 : (wsel==2) ? w7 : w8;
    __shared__ float rnum[Lz][8], rn1[Lz][8], rn2[Lz][8];
    int tid = threadIdx.x, wp = tid >> 5, lane = tid & 31;
    float a  = g_s[OFF_HS + (long long)arr*BSH + (long long)(b*Sz+s)*Hz + tid];
    float bb = g_s[OFF_STATS + (long long)(kind*2+dir)*BSH + (long long)(b*Sz+s)*Hz + tid];
    float ab = a*bb, aa = a*a, b2 = bb*bb;
    for (int l = 0; l < Lz; l++){
        float wv = __ldg(&w[l*Hz + tid]);
        float w2 = wv*wv;
        float num = warp_sum(w2*ab);
        float n1  = warp_sum(w2*aa);
        float n2  = warp_sum(w2*b2);
        if (lane == 0){ rnum[l][wp] = num; rn1[l][wp] = n1; rn2[l][wp] = n2; }
    }
    __syncthreads();
    if (tid < Lz){
        float N = 0.f, A = 0.f, B2 = 0.f;
        #pragma unroll
        for (int i = 0; i < 8; i++){ N += rnum[tid][i]; A += rn1[tid][i]; B2 += rn2[tid][i]; }
        g_s[(side ? OFF_MVH : OFF_MVP) + (long long)(b*Sz + s)*AGGz + 22 + wsel*10 + tid]
            = N / fmaxf(sqrtf(A)*sqrtf(B2), EPSf);
    }
}

__global__ void means_kernel(const float* __restrict__ left, const float* __restrict__ right){
    int which = blockIdx.x >> 2, b = blockIdx.x & 3;   // grid 8, 320 threads
    int d = threadIdx.x;
    if (d >= Dz) return;
    const float* x = which ? right : left;
    float s = 0.f;
    for (int t = 0; t < Sz; t++) s += x[((long long)b*Sz + t)*Dz + d];
    g_s[OFF_MEANS + (long long)which*Bz*Dz + (long long)b*Dz + d] = s / (float)Sz;
}

__global__ void fc1_kernel(const float* __restrict__ fc1_b){
    int b = blockIdx.x;                  // grid B, 512 threads
    int tid = threadIdx.x;
    __shared__ float feat[FEATN + 6];
    for (int i = tid; i < FEATN; i += 512){
        float v;
        if (i < 1024)       v = g_s[OFF_HT + (long long)(i >> 8)*Bz*Hz + (long long)b*Hz + (i & 255)];
        else if (i < 1026)  v = 0.5f;
        else if (i < 1326)  v = g_s[OFF_MEANS + (long long)b*Dz + (i - 1026)];
        else                v = g_s[OFF_MEANS + (long long)Bz*Dz + (long long)b*Dz + (i - 1326)];
        feat[i] = v;
    }
    __syncthreads();
    float acc = fc1_b[tid];
    for (int k = 0; k < FEATN; k++)
        acc = fmaf(feat[k], g_s[OFF_FC1WT + (long long)k*512 + tid], acc);
    g_s[OFF_FC1O + (long long)b*512 + tid] = tanhf(acc);
}

__global__ void fc2_kernel(const float* __restrict__ W2, const float* __restrict__ b2,
                           float* __restrict__ out){
    int b = blockIdx.x;                  // grid B, 512 threads
    int tid = threadIdx.x;
    __shared__ float y[512];
    y[tid] = g_s[OFF_FC1O + (long long)b*512 + tid];
    __syncthreads();
    if (tid < NCLSz){
        float acc = b2[tid];
        for (int o = 0; o < 512; o++) acc = fmaf(y[o], W2[(long long)tid*512 + o], acc);
        out[b*NCLSz + tid] = acc;
    }
}

extern "C" void kernel_launch(void* const* d_in, const int* in_sizes, int n_in,
                              void* d_out, int out_size){
    const float* left      = (const float*)d_in[0];
    const float* right     = (const float*)d_in[1];
    const float* ctx_Wih_f = (const float*)d_in[2];
    const float* ctx_Whh_f = (const float*)d_in[3];
    const float* ctx_b_f   = (const float*)d_in[4];
    const float* ctx_Wih_b = (const float*)d_in[5];
    const float* ctx_Whh_b = (const float*)d_in[6];
    const float* ctx_b_b   = (const float*)d_in[7];
    const float* agg_Wih_f = (const float*)d_in[8];
    const float* agg_Whh_f = (const float*)d_in[9];
    const float* agg_b_f   = (const float*)d_in[10];
    const float* agg_Wih_b = (const float*)d_in[11];
    const float* agg_Whh_b = (const float*)d_in[12];
    const float* agg_b_b   = (const float*)d_in[13];
    const float* mp_w3     = (const float*)d_in[14];
    const float* mp_w4     = (const float*)d_in[15];
    const float* mp_w5     = (const float*)d_in[16];
    const float* mp_w6     = (const float*)d_in[17];
    const float* mp_w7     = (const float*)d_in[18];
    const float* mp_w8     = (const float*)d_in[19];
    const float* fc1_W     = (const float*)d_in[20];
    const float* fc1_b     = (const float*)d_in[21];
    const float* fc2_W     = (const float*)d_in[22];
    const float* fc2_b     = (const float*)d_in[23];
    float* out = (float*)d_out;

    // weight transposes: exactly 2 launches (lstm3 becomes launch #4 for ncu)
    transpose2_kernel<<<dim3(128,1,2),256>>>(ctx_Wih_f, ctx_Wih_b, OFF_WIHT_CF, OFF_WIHT_CB, H4z, Dz);
    transpose3_kernel<<<dim3(128,1,3),256>>>(agg_Wih_f, agg_Wih_b, fc1_W,
        OFF_WIHT_AF, OFF_WIHT_AB, OFF_FC1WT, H4z, AGGz, 512, FEATN);

    // ctx pre-activation GEMMs, batched over z (left f/b, right f/b)
    gemm4_kernel<<<dim3(16,16,4),256>>>(left, right, 0, 0,
        OFF_WIHT_CF, (long long)Dz*H4z, ctx_b_f, ctx_b_b,
        OFF_PRE_CTX, Bz*Sz, H4z, Dz);

    lstm3_kernel<<<128,256>>>(0, ctx_Whh_f, ctx_Whh_b);

    norms_all_kernel<<<4*Bz*Sz,256>>>(mp_w3, mp_w4);
    att_kernel<<<2*Bz*Sz,256>>>();
    colstats_kernel<<<2*Bz,256>>>();
    statsrow_kernel<<<2*Bz*32,256>>>();
    statscol_kernel<<<2*Bz*32,256>>>();
    pairwise_kernel<<<2*Bz*Sz,256>>>(mp_w3, mp_w4);
    colmax_kernel<<<2*Bz*Lz,256>>>();
    mpmatch_kernel<<<8*Bz*Sz,256>>>(mp_w5, mp_w6, mp_w7, mp_w8);
    means_kernel<<<8,320>>>(left, right);

    // agg pre-activation GEMMs, batched over z (mv_p f/b, mv_h f/b)
    gemm4_kernel<<<dim3(16,16,4),256>>>(nullptr, nullptr, OFF_MVP, OFF_MVH,
        OFF_WIHT_AF, (long long)AGGz*H4z, agg_b_f, agg_b_b,
        OFF_PRE_AGG, Bz*Sz, H4z, AGGz);

    lstm3_kernel<<<128,256>>>(1, agg_Whh_f, agg_Whh_b);

    fc1_kernel<<<Bz,512>>>(fc1_b);
    fc2_kernel<<<Bz,512>>>(fc2_W, fc2_b, out);
}

// round 11
// speedup vs baseline: 1.0353x; 1.0353x over previous
#include <cuda_runtime.h>
#include <math.h>

// ---------------- problem constants ----------------
#define Bz   4
#define Sz   256
#define Dz   300
#define Hz   256
#define H4z  1024
#define Lz   10
#define AGGz 62
#define NCLSz 22
#define FEATN 1626          // 4*H + 2 + 2*D
#define BSH  (Bz*Sz*Hz)     // 262144
#define BSS  (Bz*Sz*Sz)     // 262144
#define EPSf 1e-8f

// ---------------- scratch layout (floats) ----------------
constexpr long long OFF_WIHT_CF = 0;
constexpr long long OFF_WIHT_CB = OFF_WIHT_CF + (long long)Dz*H4z;
constexpr long long OFF_WIHT_AF = OFF_WIHT_CB + (long long)Dz*H4z;
constexpr long long OFF_WIHT_AB = OFF_WIHT_AF + (long long)AGGz*H4z;
constexpr long long OFF_FC1WT   = OFF_WIHT_AB + (long long)AGGz*H4z;
constexpr long long OFF_PRE_CTX = OFF_FC1WT + (long long)FEATN*512;
constexpr long long OFF_HS      = OFF_PRE_CTX + 4LL*Bz*Sz*H4z;   // p_fw,p_bw,h_fw,h_bw
constexpr long long OFF_NRM     = OFF_HS + 4LL*BSH;              // (4,B,S)
constexpr long long OFF_ATT     = OFF_NRM + 4LL*Bz*Sz;           // (2,B,S,S)
constexpr long long OFF_ROWSUM  = OFF_ATT + 2LL*BSS;             // (2,B,S)
constexpr long long OFF_COLSUM  = OFF_ROWSUM + 2LL*Bz*Sz;        // (2,B,S)
constexpr long long OFF_STATS   = OFF_COLSUM + 2LL*Bz*Sz;        // (4 kinds x 2 dirs, B,S,H)
constexpr long long OFF_NLW     = OFF_STATS + 8LL*BSH;           // (arr, B,S,L)
constexpr long long OFF_MVP     = OFF_NLW + 4LL*Bz*Sz*Lz;        // (B,S,62)
constexpr long long OFF_MVH     = OFF_MVP + (long long)Bz*Sz*AGGz;
constexpr long long OFF_PRE_AGG = OFF_MVH + (long long)Bz*Sz*AGGz;
constexpr long long OFF_HT      = OFF_PRE_AGG + 4LL*Bz*Sz*H4z;   // (4,B,H)
constexpr long long OFF_MEANS   = OFF_HT + 4LL*Bz*Hz;            // (2,B,D)
constexpr long long OFF_FC1O    = OFF_MEANS + 2LL*Bz*Dz;         // (B,512)
constexpr long long OFF_MMS     = OFF_FC1O + (long long)Bz*512;  // (2,B,L,P,Q) mm spill
constexpr long long SCRATCH_N   = OFF_MMS + 2LL*Bz*Lz*Sz*Sz + 64;

__device__ __align__(256) float g_s[SCRATCH_N];

__device__ __forceinline__ float warp_sum(float v){
    #pragma unroll
    for (int o = 16; o > 0; o >>= 1) v += __shfl_down_sync(0xffffffffu, v, o);
    return v;
}
__device__ __forceinline__ float warp_max(float v){
    #pragma unroll
    for (int o = 16; o > 0; o >>= 1) v = fmaxf(v, __shfl_down_sync(0xffffffffu, v, o));
    return v;
}
__device__ __forceinline__ unsigned smem_u32(const void* p){
    unsigned r;
    asm("{ .reg .u64 t; cvta.to.shared.u64 t, %1; cvt.u32.u64 %0, t; }" : "=r"(r) : "l"(p));
    return r;
}
// fast, inf-safe sigmoid / tanh via MUFU-based __expf (~1e-7 rel err)
__device__ __forceinline__ float fsig(float x){ return __fdividef(1.f, 1.f + __expf(-x)); }
__device__ __forceinline__ float ftanh(float x){ return 1.f - __fdividef(2.f, 1.f + __expf(2.f*x)); }

__device__ __forceinline__ unsigned long long pk2(float a, float b){
    unsigned long long r;
    asm("mov.b64 %0, {%1, %2};" : "=l"(r) : "f"(a), "f"(b));
    return r;
}
__device__ __forceinline__ void upk2(float& lo, float& hi, unsigned long long v){
    asm("mov.b64 {%0, %1}, %2;" : "=f"(lo), "=f"(hi) : "l"(v));
}
__device__ __forceinline__ unsigned long long ffma2(unsigned long long a,
        unsigned long long b, unsigned long long c){
    unsigned long long d;
    asm("fma.rn.f32x2 %0, %1, %2, %3;" : "=l"(d) : "l"(a), "l"(b), "l"(c));
    return d;
}

// two transposes in one launch
__global__ void transpose2_kernel(const float* __restrict__ s0, const float* __restrict__ s1,
                                  long long d0, long long d1, int R, int C){
    const float* src = blockIdx.z ? s1 : s0;
    long long dst = blockIdx.z ? d1 : d0;
    long long total = (long long)R*C;
    for (long long i = blockIdx.x*(long long)blockDim.x + threadIdx.x; i < total;
         i += (long long)gridDim.x*blockDim.x){
        int r = (int)(i / C), c = (int)(i % C);
        g_s[dst + (long long)c*R + r] = src[i];
    }
}

// three transposes in one launch (agg_f, agg_b, fc1)
__global__ void transpose3_kernel(const float* __restrict__ s0, const float* __restrict__ s1,
                                  const float* __restrict__ s2,
                                  long long d0, long long d1, long long d2,
                                  int R01, int C01, int R2, int C2){
    int z = blockIdx.z;
    const float* src = (z==0) ? s0 : (z==1) ? s1 : s2;
    long long dst = (z==0) ? d0 : (z==1) ? d1 : d2;
    int R = (z<2) ? R01 : R2, C = (z<2) ? C01 : C2;
    long long total = (long long)R*C;
    for (long long i = blockIdx.x*(long long)blockDim.x + threadIdx.x; i < total;
         i += (long long)gridDim.x*blockDim.x){
        int r = (int)(i / C), c = (int)(i % C);
        g_s[dst + (long long)c*R + r] = src[i];
    }
}

// Batched GEMM over z=0..3 with register double-buffered tile loads.
__global__ void __launch_bounds__(256) gemm4_kernel(
        const float* __restrict__ A0, const float* __restrict__ A1,
        long long a0_off, long long a1_off,
        long long bt_base, long long bt_stride,
        const float* __restrict__ biasF, const float* __restrict__ biasB,
        long long c_off, int M, int N, int K){
    int z = blockIdx.z;
    const float* A  = (z < 2) ? (A0 ? A0 : (g_s + a0_off)) : (A1 ? A1 : (g_s + a1_off));
    const float* Bt = g_s + bt_base + (long long)(z & 1)*bt_stride;
    const float* bias = (z & 1) ? biasB : biasF;
    float* C = g_s + c_off + (long long)z*M*N;
    __shared__ float As[16][68];
    __shared__ float Bs[16][68];
    int bm = blockIdx.y*64, bn = blockIdx.x*64;
    int tid = threadIdx.x;
    int tr = tid >> 4, tc = tid & 15;
    float acc[4][4] = {};
    float ra[4], rb[4];

    #pragma unroll
    for (int ii = 0; ii < 4; ii++){
        int i = tid + ii*256;
        int m = i >> 4, k = i & 15;
        ra[ii] = (k < K) ? A[(long long)(bm+m)*K + k] : 0.f;
    }
    #pragma unroll
    for (int ii = 0; ii < 4; ii++){
        int i = tid + ii*256;
        int k = i >> 6, n = i & 63;
        rb[ii] = (k < K) ? Bt[(long long)k*N + bn + n] : 0.f;
    }

    for (int k0 = 0; k0 < K; k0 += 16){
        #pragma unroll
        for (int ii = 0; ii < 4; ii++){
            int i = tid + ii*256;
            As[i & 15][i >> 4] = ra[ii];
        }
        #pragma unroll
        for (int ii = 0; ii < 4; ii++){
            int i = tid + ii*256;
            Bs[i >> 6][i & 63] = rb[ii];
        }
        __syncthreads();
        int kn = k0 + 16;
        if (kn < K){
            #pragma unroll
            for (int ii = 0; ii < 4; ii++){
                int i = tid + ii*256;
                int m = i >> 4, k = i & 15;
                ra[ii] = (kn+k < K) ? A[(long long)(bm+m)*K + kn + k] : 0.f;
            }
            #pragma unroll
            for (int ii = 0; ii < 4; ii++){
                int i = tid + ii*256;
                int k = i >> 6, n = i & 63;
                rb[ii] = (kn+k < K) ? Bt[(long long)(kn+k)*N + bn + n] : 0.f;
            }
        }
        #pragma unroll
        for (int k = 0; k < 16; k++){
            float4 av = *(const float4*)&As[k][tr*4];
            float4 bv = *(const float4*)&Bs[k][tc*4];
            float a[4] = {av.x, av.y, av.z, av.w};
            float bb[4] = {bv.x, bv.y, bv.z, bv.w};
            #pragma unroll
            for (int i = 0; i < 4; i++)
                #pragma unroll
                for (int j = 0; j < 4; j++) acc[i][j] = fmaf(a[i], bb[j], acc[i][j]);
        }
        __syncthreads();
    }
    #pragma unroll
    for (int i = 0; i < 4; i++){
        int m = bm + tr*4 + i;
        #pragma unroll
        for (int j = 0; j < 4; j++){
            int n = bn + tc*4 + j;
            C[(long long)m*N + n] = acc[i][j] + bias[n];
        }
    }
}

// Cluster LSTM v4: 8-CTA cluster per unit; grid=128, 256 thr.
// Weights packed f32x2 in registers; h double-buffered in SMEM with DSMEM
// broadcast; one-way mbarrier signaling (1 wait/step) replaces barrier.cluster.
__global__ void __cluster_dims__(8,1,1) __launch_bounds__(256,1) lstm4_kernel(int stage,
        const float* __restrict__ Whh_f, const float* __restrict__ Whh_b){
    int slice;
    asm("mov.u32 %0, %%cluster_ctarank;" : "=r"(slice));
    int unit = blockIdx.x >> 3;
    int grp = unit >> 3, dir = (unit >> 2) & 1, b = unit & 3;
    long long chunk = (long long)(grp*2 + dir)*Bz + b;
    const float* pre = g_s + (stage ? OFF_PRE_AGG : OFF_PRE_CTX) + chunk*(long long)Sz*H4z;
    const float* Whh = dir ? Whh_b : Whh_f;
    float* hs = g_s + OFF_HS + chunk*(long long)Sz*Hz;

    int t = threadIdx.x;
    int kw = t >> 5, l = t & 31;

    // weight tile -> packed f32x2 registers: rows rho=4l..4l+3, k in [kw*32,+32)
    unsigned long long wrp[4][16];
    #pragma unroll
    for (int j = 0; j < 4; j++){
        int rho = 4*l + j;
        int G = (rho >> 5)*Hz + slice*32 + (rho & 31);
        const float4* row = (const float4*)(Whh + (long long)G*Hz) + kw*8;
        #pragma unroll
        for (int k4 = 0; k4 < 8; k4++){
            float4 v = row[k4];
            wrp[j][2*k4+0] = pk2(v.x, v.y);
            wrp[j][2*k4+1] = pk2(v.z, v.w);
        }
    }

    __shared__ float hsm[2][Hz];
    __shared__ float part[8][128];
    __shared__ __align__(8) unsigned long long mbarS[2];

    hsm[0][t] = 0.f;
    if (t == 0){
        unsigned mb0 = smem_u32(&mbarS[0]);
        asm volatile("mbarrier.init.shared.b64 [%0], 8;" :: "r"(mb0) : "memory");
        asm volatile("mbarrier.init.shared.b64 [%0], 8;" :: "r"(mb0 + 8) : "memory");
    }
    // remote DSMEM bases for hsm and mbarS across the 8 cluster ranks
    unsigned rbase[8], rmb[8];
    {
        unsigned lbase = smem_u32(&hsm[0][0]);
        unsigned lmb   = smem_u32(&mbarS[0]);
        #pragma unroll
        for (int rb = 0; rb < 8; rb++){
            asm("mapa.shared::cluster.u32 %0, %1, %2;" : "=r"(rbase[rb]) : "r"(lbase), "r"(rb));
            asm("mapa.shared::cluster.u32 %0, %1, %2;" : "=r"(rmb[rb])   : "r"(lmb),   "r"(rb));
        }
    }
    float c = 0.f, hlast = 0.f;
    __syncthreads();
    // all CTAs' mbarriers initialized before any arrive can land
    asm volatile("barrier.cluster.arrive.aligned;" ::: "memory");
    asm volatile("barrier.cluster.wait.aligned;" ::: "memory");

    unsigned lmb0 = smem_u32(&mbarS[0]);

    for (int ts = 0; ts < Sz; ts++){
        int s = dir ? (Sz-1-ts) : ts;
        float prev0=0.f, prev1=0.f, prev2=0.f, prev3=0.f;
        if (t < 32){
            long long base = (long long)s*H4z + slice*32 + t;
            prev0 = __ldg(&pre[base + 0*Hz]);
            prev1 = __ldg(&pre[base + 1*Hz]);
            prev2 = __ldg(&pre[base + 2*Hz]);
            prev3 = __ldg(&pre[base + 3*Hz]);
        }
        if (ts > 0){
            // wait S_{ts-1}: all peers wrote h_ts and finished reading h_{ts-1}
            unsigned mb = lmb0 + ((ts-1) & 1)*8u;
            unsigned par = ((unsigned)(ts-1) >> 1) & 1u;
            unsigned done = 0;
            while (!done){
                asm volatile(
                    "{\n\t.reg .pred p;\n\t"
                    "mbarrier.try_wait.parity.acquire.cluster.shared::cta.b64 p, [%1], %2, 0x989680;\n\t"
                    "selp.b32 %0, 1, 0, p;\n\t}"
                    : "=r"(done) : "r"(mb), "r"(par) : "memory");
            }
        }
        const float4* hp = (const float4*)(&hsm[ts & 1][0]) + kw*8;
        unsigned long long accP0 = 0, accP1 = 0, accP2 = 0, accP3 = 0;
        #pragma unroll
        for (int k4 = 0; k4 < 8; k4++){
            float4 v = hp[k4];
            unsigned long long h0 = pk2(v.x, v.y);
            unsigned long long h1 = pk2(v.z, v.w);
            accP0 = ffma2(wrp[0][2*k4+0], h0, accP0);
            accP1 = ffma2(wrp[1][2*k4+0], h0, accP1);
            accP2 = ffma2(wrp[2][2*k4+0], h0, accP2);
            accP3 = ffma2(wrp[3][2*k4+0], h0, accP3);
            accP0 = ffma2(wrp[0][2*k4+1], h1, accP0);
            accP1 = ffma2(wrp[1][2*k4+1], h1, accP1);
            accP2 = ffma2(wrp[2][2*k4+1], h1, accP2);
            accP3 = ffma2(wrp[3][2*k4+1], h1, accP3);
        }
        float lo, hi;
        upk2(lo, hi, accP0); part[kw][4*l+0] = lo + hi;
        upk2(lo, hi, accP1); part[kw][4*l+1] = lo + hi;
        upk2(lo, hi, accP2); part[kw][4*l+2] = lo + hi;
        upk2(lo, hi, accP3); part[kw][4*l+3] = lo + hi;
        __syncthreads();
        if (t < 32){
            float t0=prev0, t1=prev1, t2=prev2, t3=prev3;
            #pragma unroll
            for (int w2 = 0; w2 < 8; w2++){
                t0 += part[w2][t];
                t1 += part[w2][32+t];
                t2 += part[w2][64+t];
                t3 += part[w2][96+t];
            }
            float iv = fsig(t0);
            float fv = fsig(t1);
            float gv = ftanh(t2);
            float ov = fsig(t3);
            c = fv*c + iv*gv;
            float h = ov*ftanh(c);
            hlast = h;
            if (!stage) hs[(long long)s*Hz + slice*32 + t] = h;
            if (ts < Sz-1){
                unsigned off = (unsigned)(((ts+1) & 1)*Hz + slice*32 + t)*4u;
                unsigned hb = __float_as_uint(h);
                #pragma unroll
                for (int rb = 0; rb < 8; rb++){
                    asm volatile("st.shared::cluster.u32 [%0], %1;"
                                 :: "r"(rbase[rb] + off), "r"(hb) : "memory");
                }
                __syncwarp(0xffffffffu);
                if (t == 0){
                    asm volatile("fence.acq_rel.cluster;" ::: "memory");
                    unsigned slotoff = (unsigned)(ts & 1)*8u;
                    #pragma unroll
                    for (int rb = 0; rb < 8; rb++){
                        asm volatile("mbarrier.arrive.shared::cluster.b64 _, [%0];"
                                     :: "r"(rmb[rb] + slotoff) : "memory");
                    }
                }
            }
        }
    }
    if (stage && t < 32)
        g_s[OFF_HT + (long long)(grp*2+dir)*Bz*Hz + (long long)b*Hz + slice*32 + t] = hlast;
}

// fused: plain norm + 10 weighted norms per (arr, r)
__global__ void norms_all_kernel(const float* __restrict__ w3, const float* __restrict__ w4){
    int id = blockIdx.x;                 // 4*B*S
    int arr = id / (Bz*Sz), r = id % (Bz*Sz);
    const float* w = (arr & 1) ? w4 : w3;
    __shared__ float red[Lz+1][8];
    int tid = threadIdx.x, wp = tid >> 5, lane = tid & 31;
    float x = g_s[OFF_HS + (long long)arr*BSH + (long long)r*Hz + tid];
    float vv = x*x;
    float s0 = warp_sum(vv);
    if (lane == 0) red[Lz][wp] = s0;
    for (int l = 0; l < Lz; l++){
        float wv = __ldg(&w[l*Hz + tid]);
        float s = warp_sum(wv*wv*vv);
        if (lane == 0) red[l][wp] = s;
    }
    __syncthreads();
    if (tid < Lz){
        float s = 0.f;
        #pragma unroll
        for (int i = 0; i < 8; i++) s += red[tid][i];
        g_s[OFF_NLW + (long long)(arr*Bz*Sz + r)*Lz + tid] = sqrtf(s);
    }
    if (tid == Lz){
        float s = 0.f;
        #pragma unroll
        for (int i = 0; i < 8; i++) s += red[Lz][i];
        g_s[OFF_NRM + (long long)arr*Bz*Sz + r] = sqrtf(s);
    }
}

// cosine attention + fused row max/sum
__global__ void att_kernel(){
    int id = blockIdx.x;                 // 2*B*S
    int dir = id / (Bz*Sz), r = id % (Bz*Sz);
    int b = r / Sz;
    __shared__ float v1s[Hz];
    __shared__ float sbs[8], sbm[8];
    int tid = threadIdx.x, w = tid >> 5, lane = tid & 31;
    v1s[tid] = g_s[OFF_HS + (long long)dir*BSH + (long long)r*Hz + tid];
    __syncthreads();
    const float4* v2 = (const float4*)(g_s + OFF_HS + (long long)(2+dir)*BSH + (long long)(b*Sz + tid)*Hz);
    float acc = 0.f;
    #pragma unroll 8
    for (int h4 = 0; h4 < Hz/4; h4++){
        float4 o = v2[h4];
        acc = fmaf(v1s[4*h4+0], o.x, acc);
        acc = fmaf(v1s[4*h4+1], o.y, acc);
        acc = fmaf(v1s[4*h4+2], o.z, acc);
        acc = fmaf(v1s[4*h4+3], o.w, acc);
    }
    float n1 = g_s[OFF_NRM + (long long)dir*Bz*Sz + r];
    float n2 = g_s[OFF_NRM + (long long)(2+dir)*Bz*Sz + b*Sz + tid];
    float d = n1*n2;
    float a = acc / (d > EPSf ? d : EPSf);
    g_s[OFF_ATT + (long long)dir*BSS + (long long)r*Sz + tid] = a;
    float ssum = warp_sum(a);
    float smax = warp_max(a);
    if (lane == 0){ sbs[w] = ssum; sbm[w] = smax; }
    __syncthreads();
    if (tid == 0){
        float tots = 0.f, totm = -3.4e38f;
        #pragma unroll
        for (int i = 0; i < 8; i++){ tots += sbs[i]; totm = fmaxf(totm, sbm[i]); }
        g_s[OFF_ROWSUM + (long long)dir*Bz*Sz + r] = tots;
        if (dir == 0){
            float* mp = g_s + OFF_MVP + (long long)r*AGGz;
            mp[0] = totm;
            mp[1] = tots / (float)Sz;
        }
    }
}

__global__ void colstats_kernel(){
    int dir = blockIdx.x / Bz, b = blockIdx.x % Bz;   // grid 2*B
    int q = threadIdx.x;
    const float* att = g_s + OFF_ATT + (long long)dir*BSS + (long long)b*Sz*Sz;
    float s = 0.f, m = -3.4e38f;
    for (int p = 0; p < Sz; p++){
        float a = att[(long long)p*Sz + q];
        s += a; m = fmaxf(m, a);
    }
    g_s[OFF_COLSUM + (long long)dir*Bz*Sz + b*Sz + q] = s;
    if (dir == 0){
        float* mh = g_s + OFF_MVH + (long long)(b*Sz + q)*AGGz;
        mh[0] = m;
        mh[1] = s / (float)Sz;
    }
}

// mean_h / max_h, tiled: 8 p-rows per block; grid 2*B*32
__global__ void statsrow_kernel(){
    int id = blockIdx.x;
    int dir = id / (Bz*32); int rem = id % (Bz*32);
    int b = rem / 32, pt = rem % 32;
    __shared__ float arow[8][Sz];
    int tid = threadIdx.x;
    const float* att = g_s + OFF_ATT + (long long)dir*BSS + (long long)(b*Sz + pt*8)*Sz;
    for (int i = tid; i < 8*Sz; i += 256)
        arow[i >> 8][i & 255] = att[(long long)(i >> 8)*Sz + (i & 255)];
    __syncthreads();
    const float* vh = g_s + OFF_HS + (long long)(2+dir)*BSH + (long long)b*Sz*Hz;
    float sm[8], mx[8];
    #pragma unroll
    for (int p = 0; p < 8; p++){ sm[p] = 0.f; mx[p] = -3.4e38f; }
    for (int q = 0; q < Sz; q++){
        float vhv = vh[(long long)q*Hz + tid];
        #pragma unroll
        for (int p = 0; p < 8; p++){
            float pr = arow[p][q]*vhv;
            sm[p] += pr; mx[p] = fmaxf(mx[p], pr);
        }
    }
    #pragma unroll
    for (int p = 0; p < 8; p++){
        int rr = b*Sz + pt*8 + p;
        float rs = g_s[OFF_ROWSUM + (long long)dir*Bz*Sz + rr];
        g_s[OFF_STATS + (long long)(0*2+dir)*BSH + (long long)rr*Hz + tid] = sm[p] / (rs > EPSf ? rs : EPSf);
        g_s[OFF_STATS + (long long)(1*2+dir)*BSH + (long long)rr*Hz + tid] = mx[p];
    }
}

// mean_p / max_p, tiled: 8 q-cols per block; grid 2*B*32
__global__ void statscol_kernel(){
    int id = blockIdx.x;
    int dir = id / (Bz*32); int rem = id % (Bz*32);
    int b = rem / 32, qt = rem % 32;
    __shared__ float acol[8][Sz];
    int tid = threadIdx.x;
    const float* att = g_s + OFF_ATT + (long long)dir*BSS + (long long)b*Sz*Sz;
    for (int i = tid; i < 8*Sz; i += 256){
        int p = i >> 3, j = i & 7;
        acol[j][p] = att[(long long)p*Sz + qt*8 + j];
    }
    __syncthreads();
    const float* vp = g_s + OFF_HS + (long long)dir*BSH + (long long)b*Sz*Hz;
    float sm[8], mx[8];
    #pragma unroll
    for (int j = 0; j < 8; j++){ sm[j] = 0.f; mx[j] = -3.4e38f; }
    for (int p = 0; p < Sz; p++){
        float vpv = vp[(long long)p*Hz + tid];
        #pragma unroll
        for (int j = 0; j < 8; j++){
            float pr = acol[j][p]*vpv;
            sm[j] += pr; mx[j] = fmaxf(mx[j], pr);
        }
    }
    #pragma unroll
    for (int j = 0; j < 8; j++){
        int rr = b*Sz + qt*8 + j;
        float cs = g_s[OFF_COLSUM + (long long)dir*Bz*Sz + rr];
        g_s[OFF_STATS + (long long)(2*2+dir)*BSH + (long long)rr*Hz + tid] = sm[j] / (cs > EPSf ? cs : EPSf);
        g_s[OFF_STATS + (long long)(3*2+dir)*BSH + (long long)rr*Hz + tid] = mx[j];
    }
}

// pairwise matching, single pass: row-max -> mv_p; spill mm -> scratch for colmax
__global__ void __launch_bounds__(256) pairwise_kernel(const float* __restrict__ w3, const float* __restrict__ w4){
    int id = blockIdx.x;                 // 2*B*S
    int dir = id / (Bz*Sz), r = id % (Bz*Sz);
    int b = r / Sz, s = r % Sz;
    const float* w = dir ? w4 : w3;
    __shared__ float w2s[Lz*Hz];
    __shared__ float vrow[Hz];
    __shared__ float red[Lz][8];
    int tid = threadIdx.x, wp = tid >> 5, lane = tid & 31;
    for (int i = tid; i < Lz*Hz; i += 256){ float x = w[i]; w2s[i] = x*x; }
    vrow[tid] = g_s[OFF_HS + (long long)dir*BSH + (long long)r*Hz + tid];
    __syncthreads();
    const float4* other = (const float4*)(g_s + OFF_HS + (long long)(2+dir)*BSH + (long long)(b*Sz + tid)*Hz);
    float acc[Lz];
    #pragma unroll
    for (int l = 0; l < Lz; l++) acc[l] = 0.f;
    for (int h4 = 0; h4 < Hz/4; h4++){
        float4 o = other[h4];
        float p0 = vrow[4*h4+0]*o.x, p1 = vrow[4*h4+1]*o.y;
        float p2 = vrow[4*h4+2]*o.z, p3 = vrow[4*h4+3]*o.w;
        #pragma unroll
        for (int l = 0; l < Lz; l++){
            acc[l] = fmaf(w2s[l*Hz + 4*h4+0], p0, acc[l]);
            acc[l] = fmaf(w2s[l*Hz + 4*h4+1], p1, acc[l]);
            acc[l] = fmaf(w2s[l*Hz + 4*h4+2], p2, acc[l]);
            acc[l] = fmaf(w2s[l*Hz + 4*h4+3], p3, acc[l]);
        }
    }
    const float* nfix = g_s + OFF_NLW + (long long)((0*2+dir)*Bz*Sz + b*Sz + s)*Lz;
    const float* nstr = g_s + OFF_NLW + (long long)((1*2+dir)*Bz*Sz + b*Sz + tid)*Lz;
    float* mmS = g_s + OFF_MMS + (long long)((dir*Bz + b)*Lz)*Sz*Sz;
    #pragma unroll
    for (int l = 0; l < Lz; l++){
        float d = nfix[l]*nstr[l];
        float v = acc[l] / (d > EPSf ? d : EPSf);
        mmS[(long long)l*Sz*Sz + (long long)s*Sz + tid] = v;
        float m = warp_max(v);
        if (lane == 0) red[l][wp] = m;
    }
    __syncthreads();
    if (tid < Lz){
        float m = red[tid][0];
        #pragma unroll
        for (int i = 1; i < 8; i++) m = fmaxf(m, red[tid][i]);
        g_s[OFF_MVP + (long long)(b*Sz + s)*AGGz + 2 + dir*10 + tid] = m;
    }
}

// column max of mm over p -> mv_h.  grid 2*B*L, 256 threads (tid = q)
__global__ void colmax_kernel(){
    int id = blockIdx.x;
    int dir = id / (Bz*Lz); int rem = id % (Bz*Lz);
    int b = rem / Lz, l = rem % Lz;
    int q = threadIdx.x;
    const float* mmS = g_s + OFF_MMS + ((long long)((dir*Bz + b)*Lz) + l)*Sz*Sz;
    float m = -3.4e38f;
    for (int p = 0; p < Sz; p++) m = fmaxf(m, mmS[(long long)p*Sz + q]);
    g_s[OFF_MVH + (long long)(b*Sz + q)*AGGz + 2 + dir*10 + l] = m;
}

// attentive / max-attentive mp_match, 8 combos
__global__ void mpmatch_kernel(const float* __restrict__ w5, const float* __restrict__ w6,
                               const float* __restrict__ w7, const float* __restrict__ w8){
    int id = blockIdx.x;                 // 8*B*S
    int k = id / (Bz*Sz), r = id % (Bz*Sz);
    int b = r / Sz, s = r % Sz;
    int dir = k & 1;
    int side = k >> 2;
    int arr  = side ? (2+dir) : dir;
    int kind = side ? ((k & 2) ? 3 : 2) : ((k & 2) ? 1 : 0);
    int wsel = k & 3;
    const float* w = (wsel==0) ? w5 : (wsel==1) ? w6 : (wsel==2) ? w7 : w8;
    __shared__ float rnum[Lz][8], rn1[Lz][8], rn2[Lz][8];
    int tid = threadIdx.x, wp = tid >> 5, lane = tid & 31;
    float a  = g_s[OFF_HS + (long long)arr*BSH + (long long)(b*Sz+s)*Hz + tid];
    float bb = g_s[OFF_STATS + (long long)(kind*2+dir)*BSH + (long long)(b*Sz+s)*Hz + tid];
    float ab = a*bb, aa = a*a, b2 = bb*bb;
    for (int l = 0; l < Lz; l++){
        float wv = __ldg(&w[l*Hz + tid]);
        float w2 = wv*wv;
        float num = warp_sum(w2*ab);
        float n1  = warp_sum(w2*aa);
        float n2  = warp_sum(w2*b2);
        if (lane == 0){ rnum[l][wp] = num; rn1[l][wp] = n1; rn2[l][wp] = n2; }
    }
    __syncthreads();
    if (tid < Lz){
        float N = 0.f, A = 0.f, B2 = 0.f;
        #pragma unroll
        for (int i = 0; i < 8; i++){ N += rnum[tid][i]; A += rn1[tid][i]; B2 += rn2[tid][i]; }
        g_s[(side ? OFF_MVH : OFF_MVP) + (long long)(b*Sz + s)*AGGz + 22 + wsel*10 + tid]
            = N / fmaxf(sqrtf(A)*sqrtf(B2), EPSf);
    }
}

__global__ void means_kernel(const float* __restrict__ left, const float* __restrict__ right){
    int which = blockIdx.x >> 2, b = blockIdx.x & 3;   // grid 8, 320 threads
    int d = threadIdx.x;
    if (d >= Dz) return;
    const float* x = which ? right : left;
    float s = 0.f;
    for (int t = 0; t < Sz; t++) s += x[((long long)b*Sz + t)*Dz + d];
    g_s[OFF_MEANS + (long long)which*Bz*Dz + (long long)b*Dz + d] = s / (float)Sz;
}

__global__ void fc1_kernel(const float* __restrict__ fc1_b){
    int b = blockIdx.x;                  // grid B, 512 threads
    int tid = threadIdx.x;
    __shared__ float feat[FEATN + 6];
    for (int i = tid; i < FEATN; i += 512){
        float v;
        if (i < 1024)       v = g_s[OFF_HT + (long long)(i >> 8)*Bz*Hz + (long long)b*Hz + (i & 255)];
        else if (i < 1026)  v = 0.5f;
        else if (i < 1326)  v = g_s[OFF_MEANS + (long long)b*Dz + (i - 1026)];
        else                v = g_s[OFF_MEANS + (long long)Bz*Dz + (long long)b*Dz + (i - 1326)];
        feat[i] = v;
    }
    __syncthreads();
    float acc = fc1_b[tid];
    for (int k = 0; k < FEATN; k++)
        acc = fmaf(feat[k], g_s[OFF_FC1WT + (long long)k*512 + tid], acc);
    g_s[OFF_FC1O + (long long)b*512 + tid] = tanhf(acc);
}

__global__ void fc2_kernel(const float* __restrict__ W2, const float* __restrict__ b2,
                           float* __restrict__ out){
    int b = blockIdx.x;                  // grid B, 512 threads
    int tid = threadIdx.x;
    __shared__ float y[512];
    y[tid] = g_s[OFF_FC1O + (long long)b*512 + tid];
    __syncthreads();
    if (tid < NCLSz){
        float acc = b2[tid];
        for (int o = 0; o < 512; o++) acc = fmaf(y[o], W2[(long long)tid*512 + o], acc);
        out[b*NCLSz + tid] = acc;
    }
}

extern "C" void kernel_launch(void* const* d_in, const int* in_sizes, int n_in,
                              void* d_out, int out_size){
    const float* left      = (const float*)d_in[0];
    const float* right     = (const float*)d_in[1];
    const float* ctx_Wih_f = (const float*)d_in[2];
    const float* ctx_Whh_f = (const float*)d_in[3];
    const float* ctx_b_f   = (const float*)d_in[4];
    const float* ctx_Wih_b = (const float*)d_in[5];
    const float* ctx_Whh_b = (const float*)d_in[6];
    const float* ctx_b_b   = (const float*)d_in[7];
    const float* agg_Wih_f = (const float*)d_in[8];
    const float* agg_Whh_f = (const float*)d_in[9];
    const float* agg_b_f   = (const float*)d_in[10];
    const float* agg_Wih_b = (const float*)d_in[11];
    const float* agg_Whh_b = (const float*)d_in[12];
    const float* agg_b_b   = (const float*)d_in[13];
    const float* mp_w3     = (const float*)d_in[14];
    const float* mp_w4     = (const float*)d_in[15];
    const float* mp_w5     = (const float*)d_in[16];
    const float* mp_w6     = (const float*)d_in[17];
    const float* mp_w7     = (const float*)d_in[18];
    const float* mp_w8     = (const float*)d_in[19];
    const float* fc1_W     = (const float*)d_in[20];
    const float* fc1_b     = (const float*)d_in[21];
    const float* fc2_W     = (const float*)d_in[22];
    const float* fc2_b     = (const float*)d_in[23];
    float* out = (float*)d_out;

    // weight transposes: 2 launches (lstm4 stays launch #4 for ncu)
    transpose2_kernel<<<dim3(128,1,2),256>>>(ctx_Wih_f, ctx_Wih_b, OFF_WIHT_CF, OFF_WIHT_CB, H4z, Dz);
    transpose3_kernel<<<dim3(128,1,3),256>>>(agg_Wih_f, agg_Wih_b, fc1_W,
        OFF_WIHT_AF, OFF_WIHT_AB, OFF_FC1WT, H4z, AGGz, 512, FEATN);

    // ctx pre-activation GEMMs, batched over z (left f/b, right f/b)
    gemm4_kernel<<<dim3(16,16,4),256>>>(left, right, 0, 0,
        OFF_WIHT_CF, (long long)Dz*H4z, ctx_b_f, ctx_b_b,
        OFF_PRE_CTX, Bz*Sz, H4z, Dz);

    lstm4_kernel<<<128,256>>>(0, ctx_Whh_f, ctx_Whh_b);

    norms_all_kernel<<<4*Bz*Sz,256>>>(mp_w3, mp_w4);
    att_kernel<<<2*Bz*Sz,256>>>();
    colstats_kernel<<<2*Bz,256>>>();
    statsrow_kernel<<<2*Bz*32,256>>>();
    statscol_kernel<<<2*Bz*32,256>>>();
    pairwise_kernel<<<2*Bz*Sz,256>>>(mp_w3, mp_w4);
    colmax_kernel<<<2*Bz*Lz,256>>>();
    mpmatch_kernel<<<8*Bz*Sz,256>>>(mp_w5, mp_w6, mp_w7, mp_w8);
    means_kernel<<<8,320>>>(left, right);

    // agg pre-activation GEMMs, batched over z (mv_p f/b, mv_h f/b)
    gemm4_kernel<<<dim3(16,16,4),256>>>(nullptr, nullptr, OFF_MVP, OFF_MVH,
        OFF_WIHT_AF, (long long)AGGz*H4z, agg_b_f, agg_b_b,
        OFF_PRE_AGG, Bz*Sz, H4z, AGGz);

    lstm4_kernel<<<128,256>>>(1, agg_Whh_f, agg_Whh_b);

    fc1_kernel<<<Bz,512>>>(fc1_b);
    fc2_kernel<<<Bz,512>>>(fc2_W, fc2_b, out);
}

// round 12
// speedup vs baseline: 1.3649x; 1.3184x over previous
#include <cuda_runtime.h>
#include <math.h>

// ---------------- problem constants ----------------
#define Bz   4
#define Sz   256
#define Dz   300
#define Hz   256
#define H4z  1024
#define Lz   10
#define AGGz 62
#define NCLSz 22
#define FEATN 1626          // 4*H + 2 + 2*D
#define BSH  (Bz*Sz*Hz)     // 262144
#define BSS  (Bz*Sz*Sz)     // 262144
#define EPSf 1e-8f

// ---------------- scratch layout (floats) ----------------
constexpr long long OFF_WIHT_CF = 0;
constexpr long long OFF_WIHT_CB = OFF_WIHT_CF + (long long)Dz*H4z;
constexpr long long OFF_WIHT_AF = OFF_WIHT_CB + (long long)Dz*H4z;
constexpr long long OFF_WIHT_AB = OFF_WIHT_AF + (long long)AGGz*H4z;
constexpr long long OFF_FC1WT   = OFF_WIHT_AB + (long long)AGGz*H4z;
constexpr long long OFF_PRE_CTX = OFF_FC1WT + (long long)FEATN*512;
constexpr long long OFF_HS      = OFF_PRE_CTX + 4LL*Bz*Sz*H4z;   // p_fw,p_bw,h_fw,h_bw
constexpr long long OFF_NRM     = OFF_HS + 4LL*BSH;              // (4,B,S)
constexpr long long OFF_ATT     = OFF_NRM + 4LL*Bz*Sz;           // (2,B,S,S)
constexpr long long OFF_ROWSUM  = OFF_ATT + 2LL*BSS;             // (2,B,S)
constexpr long long OFF_COLSUM  = OFF_ROWSUM + 2LL*Bz*Sz;        // (2,B,S)
constexpr long long OFF_STATS   = OFF_COLSUM + 2LL*Bz*Sz;        // (4 kinds x 2 dirs, B,S,H)
constexpr long long OFF_NLW     = OFF_STATS + 8LL*BSH;           // (arr, B,S,L)
constexpr long long OFF_MVP     = OFF_NLW + 4LL*Bz*Sz*Lz;        // (B,S,62)
constexpr long long OFF_MVH     = OFF_MVP + (long long)Bz*Sz*AGGz;
constexpr long long OFF_PRE_AGG = OFF_MVH + (long long)Bz*Sz*AGGz;
constexpr long long OFF_HT      = OFF_PRE_AGG + 4LL*Bz*Sz*H4z;   // (4,B,H)
constexpr long long OFF_MEANS   = OFF_HT + 4LL*Bz*Hz;            // (2,B,D)
constexpr long long OFF_FC1O    = OFF_MEANS + 2LL*Bz*Dz;         // (B,512)
constexpr long long OFF_MMS     = OFF_FC1O + (long long)Bz*512;  // (2,B,L,P,Q) mm spill
constexpr long long SCRATCH_N   = OFF_MMS + 2LL*Bz*Lz*Sz*Sz + 64;

__device__ __align__(256) float g_s[SCRATCH_N];

__device__ __forceinline__ float warp_sum(float v){
    #pragma unroll
    for (int o = 16; o > 0; o >>= 1) v += __shfl_down_sync(0xffffffffu, v, o);
    return v;
}
__device__ __forceinline__ float warp_max(float v){
    #pragma unroll
    for (int o = 16; o > 0; o >>= 1) v = fmaxf(v, __shfl_down_sync(0xffffffffu, v, o));
    return v;
}
__device__ __forceinline__ unsigned smem_u32(const void* p){
    unsigned r;
    asm("{ .reg .u64 t; cvta.to.shared.u64 t, %1; cvt.u32.u64 %0, t; }" : "=r"(r) : "l"(p));
    return r;
}
// fast, inf-safe sigmoid / tanh via MUFU-based __expf (~1e-7 rel err)
__device__ __forceinline__ float fsig(float x){ return __fdividef(1.f, 1.f + __expf(-x)); }
__device__ __forceinline__ float ftanh(float x){ return 1.f - __fdividef(2.f, 1.f + __expf(2.f*x)); }

__device__ __forceinline__ unsigned long long pk2(float a, float b){
    unsigned long long r;
    asm("mov.b64 %0, {%1, %2};" : "=l"(r) : "f"(a), "f"(b));
    return r;
}
__device__ __forceinline__ void upk2(float& lo, float& hi, unsigned long long v){
    asm("mov.b64 {%0, %1}, %2;" : "=f"(lo), "=f"(hi) : "l"(v));
}
__device__ __forceinline__ unsigned long long ffma2(unsigned long long a,
        unsigned long long b, unsigned long long c){
    unsigned long long d;
    asm("fma.rn.f32x2 %0, %1, %2, %3;" : "=l"(d) : "l"(a), "l"(b), "l"(c));
    return d;
}

// two transposes in one launch
__global__ void transpose2_kernel(const float* __restrict__ s0, const float* __restrict__ s1,
                                  long long d0, long long d1, int R, int C){
    const float* src = blockIdx.z ? s1 : s0;
    long long dst = blockIdx.z ? d1 : d0;
    long long total = (long long)R*C;
    for (long long i = blockIdx.x*(long long)blockDim.x + threadIdx.x; i < total;
         i += (long long)gridDim.x*blockDim.x){
        int r = (int)(i / C), c = (int)(i % C);
        g_s[dst + (long long)c*R + r] = src[i];
    }
}

// three transposes in one launch (agg_f, agg_b, fc1)
__global__ void transpose3_kernel(const float* __restrict__ s0, const float* __restrict__ s1,
                                  const float* __restrict__ s2,
                                  long long d0, long long d1, long long d2,
                                  int R01, int C01, int R2, int C2){
    int z = blockIdx.z;
    const float* src = (z==0) ? s0 : (z==1) ? s1 : s2;
    long long dst = (z==0) ? d0 : (z==1) ? d1 : d2;
    int R = (z<2) ? R01 : R2, C = (z<2) ? C01 : C2;
    long long total = (long long)R*C;
    for (long long i = blockIdx.x*(long long)blockDim.x + threadIdx.x; i < total;
         i += (long long)gridDim.x*blockDim.x){
        int r = (int)(i / C), c = (int)(i % C);
        g_s[dst + (long long)c*R + r] = src[i];
    }
}

// Batched GEMM over z=0..3 with register double-buffered tile loads.
__global__ void __launch_bounds__(256) gemm4_kernel(
        const float* __restrict__ A0, const float* __restrict__ A1,
        long long a0_off, long long a1_off,
        long long bt_base, long long bt_stride,
        const float* __restrict__ biasF, const float* __restrict__ biasB,
        long long c_off, int M, int N, int K){
    int z = blockIdx.z;
    const float* A  = (z < 2) ? (A0 ? A0 : (g_s + a0_off)) : (A1 ? A1 : (g_s + a1_off));
    const float* Bt = g_s + bt_base + (long long)(z & 1)*bt_stride;
    const float* bias = (z & 1) ? biasB : biasF;
    float* C = g_s + c_off + (long long)z*M*N;
    __shared__ float As[16][68];
    __shared__ float Bs[16][68];
    int bm = blockIdx.y*64, bn = blockIdx.x*64;
    int tid = threadIdx.x;
    int tr = tid >> 4, tc = tid & 15;
    float acc[4][4] = {};
    float ra[4], rb[4];

    #pragma unroll
    for (int ii = 0; ii < 4; ii++){
        int i = tid + ii*256;
        int m = i >> 4, k = i & 15;
        ra[ii] = (k < K) ? A[(long long)(bm+m)*K + k] : 0.f;
    }
    #pragma unroll
    for (int ii = 0; ii < 4; ii++){
        int i = tid + ii*256;
        int k = i >> 6, n = i & 63;
        rb[ii] = (k < K) ? Bt[(long long)k*N + bn + n] : 0.f;
    }

    for (int k0 = 0; k0 < K; k0 += 16){
        #pragma unroll
        for (int ii = 0; ii < 4; ii++){
            int i = tid + ii*256;
            As[i & 15][i >> 4] = ra[ii];
        }
        #pragma unroll
        for (int ii = 0; ii < 4; ii++){
            int i = tid + ii*256;
            Bs[i >> 6][i & 63] = rb[ii];
        }
        __syncthreads();
        int kn = k0 + 16;
        if (kn < K){
            #pragma unroll
            for (int ii = 0; ii < 4; ii++){
                int i = tid + ii*256;
                int m = i >> 4, k = i & 15;
                ra[ii] = (kn+k < K) ? A[(long long)(bm+m)*K + kn + k] : 0.f;
            }
            #pragma unroll
            for (int ii = 0; ii < 4; ii++){
                int i = tid + ii*256;
                int k = i >> 6, n = i & 63;
                rb[ii] = (kn+k < K) ? Bt[(long long)(kn+k)*N + bn + n] : 0.f;
            }
        }
        #pragma unroll
        for (int k = 0; k < 16; k++){
            float4 av = *(const float4*)&As[k][tr*4];
            float4 bv = *(const float4*)&Bs[k][tc*4];
            float a[4] = {av.x, av.y, av.z, av.w};
            float bb[4] = {bv.x, bv.y, bv.z, bv.w};
            #pragma unroll
            for (int i = 0; i < 4; i++)
                #pragma unroll
                for (int j = 0; j < 4; j++) acc[i][j] = fmaf(a[i], bb[j], acc[i][j]);
        }
        __syncthreads();
    }
    #pragma unroll
    for (int i = 0; i < 4; i++){
        int m = bm + tr*4 + i;
        #pragma unroll
        for (int j = 0; j < 4; j++){
            int n = bn + tc*4 + j;
            C[(long long)m*N + n] = acc[i][j] + bias[n];
        }
    }
}

// Cluster LSTM v5: 8 clusters x 8 CTAs (64 CTAs total -> single wave),
// TWO batches per cluster sharing the same weight registers.
// grid=64, 256 thr. h double-buffered per batch; one-way mbarrier signaling.
__global__ void __cluster_dims__(8,1,1) __launch_bounds__(256,1) lstm5_kernel(int stage,
        const float* __restrict__ Whh_f, const float* __restrict__ Whh_b){
    int slice;
    asm("mov.u32 %0, %%cluster_ctarank;" : "=r"(slice));
    int cid = blockIdx.x >> 3;           // 0..7
    int grpdir = cid >> 1;               // 0..3
    int bpair  = cid & 1;                // batches {2*bpair, 2*bpair+1}
    int grp = grpdir >> 1, dir = grpdir & 1;
    long long chunk0 = (long long)(grp*2 + dir)*Bz + (bpair*2 + 0);
    long long chunk1 = (long long)(grp*2 + dir)*Bz + (bpair*2 + 1);
    long long preBase = stage ? OFF_PRE_AGG : OFF_PRE_CTX;
    const float* pre0 = g_s + preBase + chunk0*(long long)Sz*H4z;
    const float* pre1 = g_s + preBase + chunk1*(long long)Sz*H4z;
    const float* Whh = dir ? Whh_b : Whh_f;
    float* hs0 = g_s + OFF_HS + chunk0*(long long)Sz*Hz;
    float* hs1 = g_s + OFF_HS + chunk1*(long long)Sz*Hz;

    int t = threadIdx.x;
    int kw = t >> 5, l = t & 31;

    // weight tile -> packed f32x2 registers: rows rho=4l..4l+3, k in [kw*32,+32)
    unsigned long long wrp[4][16];
    #pragma unroll
    for (int j = 0; j < 4; j++){
        int rho = 4*l + j;
        int G = (rho >> 5)*Hz + slice*32 + (rho & 31);
        const float4* row = (const float4*)(Whh + (long long)G*Hz) + kw*8;
        #pragma unroll
        for (int k4 = 0; k4 < 8; k4++){
            float4 v = row[k4];
            wrp[j][2*k4+0] = pk2(v.x, v.y);
            wrp[j][2*k4+1] = pk2(v.z, v.w);
        }
    }

    __shared__ float hsm[2][2][Hz];      // [buf][batch][h]
    __shared__ float part[2][8][128];    // [batch][kw][gate-row]
    __shared__ __align__(8) unsigned long long mbarS[2];

    hsm[0][0][t] = 0.f;
    hsm[0][1][t] = 0.f;
    if (t == 0){
        unsigned mb0 = smem_u32(&mbarS[0]);
        asm volatile("mbarrier.init.shared.b64 [%0], 16;" :: "r"(mb0) : "memory");
        asm volatile("mbarrier.init.shared.b64 [%0], 16;" :: "r"(mb0 + 8) : "memory");
    }
    unsigned rbase[8], rmb[8];
    {
        unsigned lbase = smem_u32(&hsm[0][0][0]);
        unsigned lmb   = smem_u32(&mbarS[0]);
        #pragma unroll
        for (int rb = 0; rb < 8; rb++){
            asm("mapa.shared::cluster.u32 %0, %1, %2;" : "=r"(rbase[rb]) : "r"(lbase), "r"(rb));
            asm("mapa.shared::cluster.u32 %0, %1, %2;" : "=r"(rmb[rb])   : "r"(lmb),   "r"(rb));
        }
    }
    float c = 0.f, hlast = 0.f;
    __syncthreads();
    asm volatile("barrier.cluster.arrive.aligned;" ::: "memory");
    asm volatile("barrier.cluster.wait.aligned;" ::: "memory");

    unsigned lmb0 = smem_u32(&mbarS[0]);

    for (int ts = 0; ts < Sz; ts++){
        int s = dir ? (Sz-1-ts) : ts;
        float prev0=0.f, prev1=0.f, prev2=0.f, prev3=0.f;
        if (t < 64){
            const float* prew = (t & 32) ? pre1 : pre0;
            long long base = (long long)s*H4z + slice*32 + (t & 31);
            prev0 = __ldg(&prew[base + 0*Hz]);
            prev1 = __ldg(&prew[base + 1*Hz]);
            prev2 = __ldg(&prew[base + 2*Hz]);
            prev3 = __ldg(&prew[base + 3*Hz]);
        }
        if (ts > 0){
            unsigned mb = lmb0 + ((ts-1) & 1)*8u;
            unsigned par = ((unsigned)(ts-1) >> 1) & 1u;
            unsigned done = 0;
            while (!done){
                asm volatile(
                    "{\n\t.reg .pred p;\n\t"
                    "mbarrier.try_wait.parity.acquire.cluster.shared::cta.b64 p, [%1], %2, 0x989680;\n\t"
                    "selp.b32 %0, 1, 0, p;\n\t}"
                    : "=r"(done) : "r"(mb), "r"(par) : "memory");
            }
        }
        int buf = ts & 1;
        const float4* hp0 = (const float4*)(&hsm[buf][0][0]) + kw*8;
        const float4* hp1 = (const float4*)(&hsm[buf][1][0]) + kw*8;
        unsigned long long a00=0, a01=0, a02=0, a03=0;
        unsigned long long a10=0, a11=0, a12=0, a13=0;
        #pragma unroll
        for (int k4 = 0; k4 < 8; k4++){
            float4 v0 = hp0[k4];
            float4 v1 = hp1[k4];
            unsigned long long h0a = pk2(v0.x, v0.y), h0b = pk2(v0.z, v0.w);
            unsigned long long h1a = pk2(v1.x, v1.y), h1b = pk2(v1.z, v1.w);
            a00 = ffma2(wrp[0][2*k4+0], h0a, a00);
            a01 = ffma2(wrp[1][2*k4+0], h0a, a01);
            a02 = ffma2(wrp[2][2*k4+0], h0a, a02);
            a03 = ffma2(wrp[3][2*k4+0], h0a, a03);
            a10 = ffma2(wrp[0][2*k4+0], h1a, a10);
            a11 = ffma2(wrp[1][2*k4+0], h1a, a11);
            a12 = ffma2(wrp[2][2*k4+0], h1a, a12);
            a13 = ffma2(wrp[3][2*k4+0], h1a, a13);
            a00 = ffma2(wrp[0][2*k4+1], h0b, a00);
            a01 = ffma2(wrp[1][2*k4+1], h0b, a01);
            a02 = ffma2(wrp[2][2*k4+1], h0b, a02);
            a03 = ffma2(wrp[3][2*k4+1], h0b, a03);
            a10 = ffma2(wrp[0][2*k4+1], h1b, a10);
            a11 = ffma2(wrp[1][2*k4+1], h1b, a11);
            a12 = ffma2(wrp[2][2*k4+1], h1b, a12);
            a13 = ffma2(wrp[3][2*k4+1], h1b, a13);
        }
        float lo, hi;
        upk2(lo, hi, a00); part[0][kw][4*l+0] = lo + hi;
        upk2(lo, hi, a01); part[0][kw][4*l+1] = lo + hi;
        upk2(lo, hi, a02); part[0][kw][4*l+2] = lo + hi;
        upk2(lo, hi, a03); part[0][kw][4*l+3] = lo + hi;
        upk2(lo, hi, a10); part[1][kw][4*l+0] = lo + hi;
        upk2(lo, hi, a11); part[1][kw][4*l+1] = lo + hi;
        upk2(lo, hi, a12); part[1][kw][4*l+2] = lo + hi;
        upk2(lo, hi, a13); part[1][kw][4*l+3] = lo + hi;
        __syncthreads();
        if (t < 64){
            int w = t >> 5, u = t & 31;
            float t0=prev0, t1=prev1, t2=prev2, t3=prev3;
            #pragma unroll
            for (int w2 = 0; w2 < 8; w2++){
                t0 += part[w][w2][u];
                t1 += part[w][w2][32+u];
                t2 += part[w][w2][64+u];
                t3 += part[w][w2][96+u];
            }
            float iv = fsig(t0);
            float fv = fsig(t1);
            float gv = ftanh(t2);
            float ov = fsig(t3);
            c = fv*c + iv*gv;
            float h = ov*ftanh(c);
            hlast = h;
            if (!stage){
                float* hsw = w ? hs1 : hs0;
                hsw[(long long)s*Hz + slice*32 + u] = h;
            }
            if (ts < Sz-1){
                unsigned off = (unsigned)(((((ts+1) & 1)*2 + w)*Hz) + slice*32 + u)*4u;
                unsigned hb = __float_as_uint(h);
                #pragma unroll
                for (int rb = 0; rb < 8; rb++){
                    asm volatile("st.shared::cluster.u32 [%0], %1;"
                                 :: "r"(rbase[rb] + off), "r"(hb) : "memory");
                }
                __syncwarp(0xffffffffu);
                if (u == 0){
                    asm volatile("fence.acq_rel.cluster;" ::: "memory");
                    unsigned slotoff = (unsigned)(ts & 1)*8u;
                    #pragma unroll
                    for (int rb = 0; rb < 8; rb++){
                        asm volatile("mbarrier.arrive.shared::cluster.b64 _, [%0];"
                                     :: "r"(rmb[rb] + slotoff) : "memory");
                    }
                }
            }
        }
    }
    if (stage && t < 64){
        int w = t >> 5, u = t & 31;
        int b = bpair*2 + w;
        g_s[OFF_HT + (long long)(grp*2+dir)*Bz*Hz + (long long)b*Hz + slice*32 + u] = hlast;
    }
}

// fused: plain norm + 10 weighted norms per (arr, r)
__global__ void norms_all_kernel(const float* __restrict__ w3, const float* __restrict__ w4){
    int id = blockIdx.x;                 // 4*B*S
    int arr = id / (Bz*Sz), r = id % (Bz*Sz);
    const float* w = (arr & 1) ? w4 : w3;
    __shared__ float red[Lz+1][8];
    int tid = threadIdx.x, wp = tid >> 5, lane = tid & 31;
    float x = g_s[OFF_HS + (long long)arr*BSH + (long long)r*Hz + tid];
    float vv = x*x;
    float s0 = warp_sum(vv);
    if (lane == 0) red[Lz][wp] = s0;
    for (int l = 0; l < Lz; l++){
        float wv = __ldg(&w[l*Hz + tid]);
        float s = warp_sum(wv*wv*vv);
        if (lane == 0) red[l][wp] = s;
    }
    __syncthreads();
    if (tid < Lz){
        float s = 0.f;
        #pragma unroll
        for (int i = 0; i < 8; i++) s += red[tid][i];
        g_s[OFF_NLW + (long long)(arr*Bz*Sz + r)*Lz + tid] = sqrtf(s);
    }
    if (tid == Lz){
        float s = 0.f;
        #pragma unroll
        for (int i = 0; i < 8; i++) s += red[Lz][i];
        g_s[OFF_NRM + (long long)arr*Bz*Sz + r] = sqrtf(s);
    }
}

// cosine attention + fused row max/sum
__global__ void att_kernel(){
    int id = blockIdx.x;                 // 2*B*S
    int dir = id / (Bz*Sz), r = id % (Bz*Sz);
    int b = r / Sz;
    __shared__ float v1s[Hz];
    __shared__ float sbs[8], sbm[8];
    int tid = threadIdx.x, w = tid >> 5, lane = tid & 31;
    v1s[tid] = g_s[OFF_HS + (long long)dir*BSH + (long long)r*Hz + tid];
    __syncthreads();
    const float4* v2 = (const float4*)(g_s + OFF_HS + (long long)(2+dir)*BSH + (long long)(b*Sz + tid)*Hz);
    float acc = 0.f;
    #pragma unroll 8
    for (int h4 = 0; h4 < Hz/4; h4++){
        float4 o = v2[h4];
        acc = fmaf(v1s[4*h4+0], o.x, acc);
        acc = fmaf(v1s[4*h4+1], o.y, acc);
        acc = fmaf(v1s[4*h4+2], o.z, acc);
        acc = fmaf(v1s[4*h4+3], o.w, acc);
    }
    float n1 = g_s[OFF_NRM + (long long)dir*Bz*Sz + r];
    float n2 = g_s[OFF_NRM + (long long)(2+dir)*Bz*Sz + b*Sz + tid];
    float d = n1*n2;
    float a = acc / (d > EPSf ? d : EPSf);
    g_s[OFF_ATT + (long long)dir*BSS + (long long)r*Sz + tid] = a;
    float ssum = warp_sum(a);
    float smax = warp_max(a);
    if (lane == 0){ sbs[w] = ssum; sbm[w] = smax; }
    __syncthreads();
    if (tid == 0){
        float tots = 0.f, totm = -3.4e38f;
        #pragma unroll
        for (int i = 0; i < 8; i++){ tots += sbs[i]; totm = fmaxf(totm, sbm[i]); }
        g_s[OFF_ROWSUM + (long long)dir*Bz*Sz + r] = tots;
        if (dir == 0){
            float* mp = g_s + OFF_MVP + (long long)r*AGGz;
            mp[0] = totm;
            mp[1] = tots / (float)Sz;
        }
    }
}

__global__ void colstats_kernel(){
    int dir = blockIdx.x / Bz, b = blockIdx.x % Bz;   // grid 2*B
    int q = threadIdx.x;
    const float* att = g_s + OFF_ATT + (long long)dir*BSS + (long long)b*Sz*Sz;
    float s = 0.f, m = -3.4e38f;
    for (int p = 0; p < Sz; p++){
        float a = att[(long long)p*Sz + q];
        s += a; m = fmaxf(m, a);
    }
    g_s[OFF_COLSUM + (long long)dir*Bz*Sz + b*Sz + q] = s;
    if (dir == 0){
        float* mh = g_s + OFF_MVH + (long long)(b*Sz + q)*AGGz;
        mh[0] = m;
        mh[1] = s / (float)Sz;
    }
}

// mean_h / max_h, tiled: 8 p-rows per block; grid 2*B*32
__global__ void statsrow_kernel(){
    int id = blockIdx.x;
    int dir = id / (Bz*32); int rem = id % (Bz*32);
    int b = rem / 32, pt = rem % 32;
    __shared__ float arow[8][Sz];
    int tid = threadIdx.x;
    const float* att = g_s + OFF_ATT + (long long)dir*BSS + (long long)(b*Sz + pt*8)*Sz;
    for (int i = tid; i < 8*Sz; i += 256)
        arow[i >> 8][i & 255] = att[(long long)(i >> 8)*Sz + (i & 255)];
    __syncthreads();
    const float* vh = g_s + OFF_HS + (long long)(2+dir)*BSH + (long long)b*Sz*Hz;
    float sm[8], mx[8];
    #pragma unroll
    for (int p = 0; p < 8; p++){ sm[p] = 0.f; mx[p] = -3.4e38f; }
    for (int q = 0; q < Sz; q++){
        float vhv = vh[(long long)q*Hz + tid];
        #pragma unroll
        for (int p = 0; p < 8; p++){
            float pr = arow[p][q]*vhv;
            sm[p] += pr; mx[p] = fmaxf(mx[p], pr);
        }
    }
    #pragma unroll
    for (int p = 0; p < 8; p++){
        int rr = b*Sz + pt*8 + p;
        float rs = g_s[OFF_ROWSUM + (long long)dir*Bz*Sz + rr];
        g_s[OFF_STATS + (long long)(0*2+dir)*BSH + (long long)rr*Hz + tid] = sm[p] / (rs > EPSf ? rs : EPSf);
        g_s[OFF_STATS + (long long)(1*2+dir)*BSH + (long long)rr*Hz + tid] = mx[p];
    }
}

// mean_p / max_p, tiled: 8 q-cols per block; grid 2*B*32
__global__ void statscol_kernel(){
    int id = blockIdx.x;
    int dir = id / (Bz*32); int rem = id % (Bz*32);
    int b = rem / 32, qt = rem % 32;
    __shared__ float acol[8][Sz];
    int tid = threadIdx.x;
    const float* att = g_s + OFF_ATT + (long long)dir*BSS + (long long)b*Sz*Sz;
    for (int i = tid; i < 8*Sz; i += 256){
        int p = i >> 3, j = i & 7;
        acol[j][p] = att[(long long)p*Sz + qt*8 + j];
    }
    __syncthreads();
    const float* vp = g_s + OFF_HS + (long long)dir*BSH + (long long)b*Sz*Hz;
    float sm[8], mx[8];
    #pragma unroll
    for (int j = 0; j < 8; j++){ sm[j] = 0.f; mx[j] = -3.4e38f; }
    for (int p = 0; p < Sz; p++){
        float vpv = vp[(long long)p*Hz + tid];
        #pragma unroll
        for (int j = 0; j < 8; j++){
            float pr = acol[j][p]*vpv;
            sm[j] += pr; mx[j] = fmaxf(mx[j], pr);
        }
    }
    #pragma unroll
    for (int j = 0; j < 8; j++){
        int rr = b*Sz + qt*8 + j;
        float cs = g_s[OFF_COLSUM + (long long)dir*Bz*Sz + rr];
        g_s[OFF_STATS + (long long)(2*2+dir)*BSH + (long long)rr*Hz + tid] = sm[j] / (cs > EPSf ? cs : EPSf);
        g_s[OFF_STATS + (long long)(3*2+dir)*BSH + (long long)rr*Hz + tid] = mx[j];
    }
}

// pairwise matching, single pass: row-max -> mv_p; spill mm -> scratch for colmax
__global__ void __launch_bounds__(256) pairwise_kernel(const float* __restrict__ w3, const float* __restrict__ w4){
    int id = blockIdx.x;                 // 2*B*S
    int dir = id / (Bz*Sz), r = id % (Bz*Sz);
    int b = r / Sz, s = r % Sz;
    const float* w = dir ? w4 : w3;
    __shared__ float w2s[Lz*Hz];
    __shared__ float vrow[Hz];
    __shared__ float red[Lz][8];
    int tid = threadIdx.x, wp = tid >> 5, lane = tid & 31;
    for (int i = tid; i < Lz*Hz; i += 256){ float x = w[i]; w2s[i] = x*x; }
    vrow[tid] = g_s[OFF_HS + (long long)dir*BSH + (long long)r*Hz + tid];
    __syncthreads();
    const float4* other = (const float4*)(g_s + OFF_HS + (long long)(2+dir)*BSH + (long long)(b*Sz + tid)*Hz);
    float acc[Lz];
    #pragma unroll
    for (int l = 0; l < Lz; l++) acc[l] = 0.f;
    for (int h4 = 0; h4 < Hz/4; h4++){
        float4 o = other[h4];
        float p0 = vrow[4*h4+0]*o.x, p1 = vrow[4*h4+1]*o.y;
        float p2 = vrow[4*h4+2]*o.z, p3 = vrow[4*h4+3]*o.w;
        #pragma unroll
        for (int l = 0; l < Lz; l++){
            acc[l] = fmaf(w2s[l*Hz + 4*h4+0], p0, acc[l]);
            acc[l] = fmaf(w2s[l*Hz + 4*h4+1], p1, acc[l]);
            acc[l] = fmaf(w2s[l*Hz + 4*h4+2], p2, acc[l]);
            acc[l] = fmaf(w2s[l*Hz + 4*h4+3], p3, acc[l]);
        }
    }
    const float* nfix = g_s + OFF_NLW + (long long)((0*2+dir)*Bz*Sz + b*Sz + s)*Lz;
    const float* nstr = g_s + OFF_NLW + (long long)((1*2+dir)*Bz*Sz + b*Sz + tid)*Lz;
    float* mmS = g_s + OFF_MMS + (long long)((dir*Bz + b)*Lz)*Sz*Sz;
    #pragma unroll
    for (int l = 0; l < Lz; l++){
        float d = nfix[l]*nstr[l];
        float v = acc[l] / (d > EPSf ? d : EPSf);
        mmS[(long long)l*Sz*Sz + (long long)s*Sz + tid] = v;
        float m = warp_max(v);
        if (lane == 0) red[l][wp] = m;
    }
    __syncthreads();
    if (tid < Lz){
        float m = red[tid][0];
        #pragma unroll
        for (int i = 1; i < 8; i++) m = fmaxf(m, red[tid][i]);
        g_s[OFF_MVP + (long long)(b*Sz + s)*AGGz + 2 + dir*10 + tid] = m;
    }
}

// column max of mm over p -> mv_h.  grid 2*B*L, 256 threads (tid = q)
__global__ void colmax_kernel(){
    int id = blockIdx.x;
    int dir = id / (Bz*Lz); int rem = id % (Bz*Lz);
    int b = rem / Lz, l = rem % Lz;
    int q = threadIdx.x;
    const float* mmS = g_s + OFF_MMS + ((long long)((dir*Bz + b)*Lz) + l)*Sz*Sz;
    float m = -3.4e38f;
    for (int p = 0; p < Sz; p++) m = fmaxf(m, mmS[(long long)p*Sz + q]);
    g_s[OFF_MVH + (long long)(b*Sz + q)*AGGz + 2 + dir*10 + l] = m;
}

// attentive / max-attentive mp_match, 8 combos
__global__ void mpmatch_kernel(const float* __restrict__ w5, const float* __restrict__ w6,
                               const float* __restrict__ w7, const float* __restrict__ w8){
    int id = blockIdx.x;                 // 8*B*S
    int k = id / (Bz*Sz), r = id % (Bz*Sz);
    int b = r / Sz, s = r % Sz;
    int dir = k & 1;
    int side = k >> 2;
    int arr  = side ? (2+dir) : dir;
    int kind = side ? ((k & 2) ? 3 : 2) : ((k & 2) ? 1 : 0);
    int wsel = k & 3;
    const float* w = (wsel==0) ? w5 : (wsel==1) ? w6 : (wsel==2) ? w7 : w8;
    __shared__ float rnum[Lz][8], rn1[Lz][8], rn2[Lz][8];
    int tid = threadIdx.x, wp = tid >> 5, lane = tid & 31;
    float a  = g_s[OFF_HS + (long long)arr*BSH + (long long)(b*Sz+s)*Hz + tid];
    float bb = g_s[OFF_STATS + (long long)(kind*2+dir)*BSH + (long long)(b*Sz+s)*Hz + tid];
    float ab = a*bb, aa = a*a, b2 = bb*bb;
    for (int l = 0; l < Lz; l++){
        float wv = __ldg(&w[l*Hz + tid]);
        float w2 = wv*wv;
        float num = warp_sum(w2*ab);
        float n1  = warp_sum(w2*aa);
        float n2  = warp_sum(w2*b2);
        if (lane == 0){ rnum[l][wp] = num; rn1[l][wp] = n1; rn2[l][wp] = n2; }
    }
    __syncthreads();
    if (tid < Lz){
        float N = 0.f, A = 0.f, B2 = 0.f;
        #pragma unroll
        for (int i = 0; i < 8; i++){ N += rnum[tid][i]; A += rn1[tid][i]; B2 += rn2[tid][i]; }
        g_s[(side ? OFF_MVH : OFF_MVP) + (long long)(b*Sz + s)*AGGz + 22 + wsel*10 + tid]
            = N / fmaxf(sqrtf(A)*sqrtf(B2), EPSf);
    }
}

__global__ void means_kernel(const float* __restrict__ left, const float* __restrict__ right){
    int which = blockIdx.x >> 2, b = blockIdx.x & 3;   // grid 8, 320 threads
    int d = threadIdx.x;
    if (d >= Dz) return;
    const float* x = which ? right : left;
    float s = 0.f;
    for (int t = 0; t < Sz; t++) s += x[((long long)b*Sz + t)*Dz + d];
    g_s[OFF_MEANS + (long long)which*Bz*Dz + (long long)b*Dz + d] = s / (float)Sz;
}

__global__ void fc1_kernel(const float* __restrict__ fc1_b){
    int b = blockIdx.x;                  // grid B, 512 threads
    int tid = threadIdx.x;
    __shared__ float feat[FEATN + 6];
    for (int i = tid; i < FEATN; i += 512){
        float v;
        if (i < 1024)       v = g_s[OFF_HT + (long long)(i >> 8)*Bz*Hz + (long long)b*Hz + (i & 255)];
        else if (i < 1026)  v = 0.5f;
        else if (i < 1326)  v = g_s[OFF_MEANS + (long long)b*Dz + (i - 1026)];
        else                v = g_s[OFF_MEANS + (long long)Bz*Dz + (long long)b*Dz + (i - 1326)];
        feat[i] = v;
    }
    __syncthreads();
    float acc = fc1_b[tid];
    for (int k = 0; k < FEATN; k++)
        acc = fmaf(feat[k], g_s[OFF_FC1WT + (long long)k*512 + tid], acc);
    g_s[OFF_FC1O + (long long)b*512 + tid] = tanhf(acc);
}

__global__ void fc2_kernel(const float* __restrict__ W2, const float* __restrict__ b2,
                           float* __restrict__ out){
    int b = blockIdx.x;                  // grid B, 512 threads
    int tid = threadIdx.x;
    __shared__ float y[512];
    y[tid] = g_s[OFF_FC1O + (long long)b*512 + tid];
    __syncthreads();
    if (tid < NCLSz){
        float acc = b2[tid];
        for (int o = 0; o < 512; o++) acc = fmaf(y[o], W2[(long long)tid*512 + o], acc);
        out[b*NCLSz + tid] = acc;
    }
}

extern "C" void kernel_launch(void* const* d_in, const int* in_sizes, int n_in,
                              void* d_out, int out_size){
    const float* left      = (const float*)d_in[0];
    const float* right     = (const float*)d_in[1];
    const float* ctx_Wih_f = (const float*)d_in[2];
    const float* ctx_Whh_f = (const float*)d_in[3];
    const float* ctx_b_f   = (const float*)d_in[4];
    const float* ctx_Wih_b = (const float*)d_in[5];
    const float* ctx_Whh_b = (const float*)d_in[6];
    const float* ctx_b_b   = (const float*)d_in[7];
    const float* agg_Wih_f = (const float*)d_in[8];
    const float* agg_Whh_f = (const float*)d_in[9];
    const float* agg_b_f   = (const float*)d_in[10];
    const float* agg_Wih_b = (const float*)d_in[11];
    const float* agg_Whh_b = (const float*)d_in[12];
    const float* agg_b_b   = (const float*)d_in[13];
    const float* mp_w3     = (const float*)d_in[14];
    const float* mp_w4     = (const float*)d_in[15];
    const float* mp_w5     = (const float*)d_in[16];
    const float* mp_w6     = (const float*)d_in[17];
    const float* mp_w7     = (const float*)d_in[18];
    const float* mp_w8     = (const float*)d_in[19];
    const float* fc1_W     = (const float*)d_in[20];
    const float* fc1_b     = (const float*)d_in[21];
    const float* fc2_W     = (const float*)d_in[22];
    const float* fc2_b     = (const float*)d_in[23];
    float* out = (float*)d_out;

    // weight transposes: 2 launches (lstm5 stays launch #4 for ncu)
    transpose2_kernel<<<dim3(128,1,2),256>>>(ctx_Wih_f, ctx_Wih_b, OFF_WIHT_CF, OFF_WIHT_CB, H4z, Dz);
    transpose3_kernel<<<dim3(128,1,3),256>>>(agg_Wih_f, agg_Wih_b, fc1_W,
        OFF_WIHT_AF, OFF_WIHT_AB, OFF_FC1WT, H4z, AGGz, 512, FEATN);

    // ctx pre-activation GEMMs, batched over z (left f/b, right f/b)
    gemm4_kernel<<<dim3(16,16,4),256>>>(left, right, 0, 0,
        OFF_WIHT_CF, (long long)Dz*H4z, ctx_b_f, ctx_b_b,
        OFF_PRE_CTX, Bz*Sz, H4z, Dz);

    lstm5_kernel<<<64,256>>>(0, ctx_Whh_f, ctx_Whh_b);

    norms_all_kernel<<<4*Bz*Sz,256>>>(mp_w3, mp_w4);
    att_kernel<<<2*Bz*Sz,256>>>();
    colstats_kernel<<<2*Bz,256>>>();
    statsrow_kernel<<<2*Bz*32,256>>>();
    statscol_kernel<<<2*Bz*32,256>>>();
    pairwise_kernel<<<2*Bz*Sz,256>>>(mp_w3, mp_w4);
    colmax_kernel<<<2*Bz*Lz,256>>>();
    mpmatch_kernel<<<8*Bz*Sz,256>>>(mp_w5, mp_w6, mp_w7, mp_w8);
    means_kernel<<<8,320>>>(left, right);

    // agg pre-activation GEMMs, batched over z (mv_p f/b, mv_h f/b)
    gemm4_kernel<<<dim3(16,16,4),256>>>(nullptr, nullptr, OFF_MVP, OFF_MVH,
        OFF_WIHT_AF, (long long)AGGz*H4z, agg_b_f, agg_b_b,
        OFF_PRE_AGG, Bz*Sz, H4z, AGGz);

    lstm5_kernel<<<64,256>>>(1, agg_Whh_f, agg_Whh_b);

    fc1_kernel<<<Bz,512>>>(fc1_b);
    fc2_kernel<<<Bz,512>>>(fc2_W, fc2_b, out);
}

// round 14
// speedup vs baseline: 1.4414x; 1.0560x over previous
#include <cuda_runtime.h>
#include <math.h>

// ---------------- problem constants ----------------
#define Bz   4
#define Sz   256
#define Dz   300
#define Hz   256
#define H4z  1024
#define Lz   10
#define AGGz 62
#define NCLSz 22
#define FEATN 1626          // 4*H + 2 + 2*D
#define BSH  (Bz*Sz*Hz)     // 262144
#define BSS  (Bz*Sz*Sz)     // 262144
#define EPSf 1e-8f

// ---------------- scratch layout (floats) ----------------
constexpr long long OFF_WIHT_CF = 0;
constexpr long long OFF_WIHT_CB = OFF_WIHT_CF + (long long)Dz*H4z;
constexpr long long OFF_WIHT_AF = OFF_WIHT_CB + (long long)Dz*H4z;
constexpr long long OFF_WIHT_AB = OFF_WIHT_AF + (long long)AGGz*H4z;
constexpr long long OFF_FC1WT   = OFF_WIHT_AB + (long long)AGGz*H4z;
constexpr long long OFF_PRE_CTX = OFF_FC1WT + (long long)FEATN*512;
constexpr long long OFF_HS      = OFF_PRE_CTX + 4LL*Bz*Sz*H4z;   // p_fw,p_bw,h_fw,h_bw
constexpr long long OFF_NRM     = OFF_HS + 4LL*BSH;              // (4,B,S)
constexpr long long OFF_ATT     = OFF_NRM + 4LL*Bz*Sz;           // (2,B,S,S)
constexpr long long OFF_ROWSUM  = OFF_ATT + 2LL*BSS;             // (2,B,S)
constexpr long long OFF_COLSUM  = OFF_ROWSUM + 2LL*Bz*Sz;        // (2,B,S) [unused]
constexpr long long OFF_STATS   = OFF_COLSUM + 2LL*Bz*Sz;        // (4 kinds x 2 dirs, B,S,H)
constexpr long long OFF_NLW     = OFF_STATS + 8LL*BSH;           // (arr, B,S,L)
constexpr long long OFF_MVP     = OFF_NLW + 4LL*Bz*Sz*Lz;        // (B,S,62)
constexpr long long OFF_MVH     = OFF_MVP + (long long)Bz*Sz*AGGz;
constexpr long long OFF_PRE_AGG = OFF_MVH + (long long)Bz*Sz*AGGz;
constexpr long long OFF_HT      = OFF_PRE_AGG + 4LL*Bz*Sz*H4z;   // (4,B,H)
constexpr long long OFF_MEANS   = OFF_HT + 4LL*Bz*Hz;            // (2,B,D)
constexpr long long OFF_FC1O    = OFF_MEANS + 2LL*Bz*Dz;         // (B,512)
constexpr long long OFF_MMS     = OFF_FC1O + (long long)Bz*512;  // (2,B,L,P,Q) mm spill
constexpr long long SCRATCH_N   = OFF_MMS + 2LL*Bz*Lz*Sz*Sz + 64;

__device__ __align__(256) float g_s[SCRATCH_N];

__device__ __forceinline__ float warp_sum(float v){
    #pragma unroll
    for (int o = 16; o > 0; o >>= 1) v += __shfl_down_sync(0xffffffffu, v, o);
    return v;
}
__device__ __forceinline__ float warp_max(float v){
    #pragma unroll
    for (int o = 16; o > 0; o >>= 1) v = fmaxf(v, __shfl_down_sync(0xffffffffu, v, o));
    return v;
}
__device__ __forceinline__ unsigned smem_u32(const void* p){
    unsigned r;
    asm("{ .reg .u64 t; cvta.to.shared.u64 t, %1; cvt.u32.u64 %0, t; }" : "=r"(r) : "l"(p));
    return r;
}
// fast, inf-safe sigmoid / tanh via MUFU-based __expf (~1e-7 rel err)
__device__ __forceinline__ float fsig(float x){ return __fdividef(1.f, 1.f + __expf(-x)); }
__device__ __forceinline__ float ftanh(float x){ return 1.f - __fdividef(2.f, 1.f + __expf(2.f*x)); }

__device__ __forceinline__ unsigned long long pk2(float a, float b){
    unsigned long long r;
    asm("mov.b64 %0, {%1, %2};" : "=l"(r) : "f"(a), "f"(b));
    return r;
}
__device__ __forceinline__ void upk2(float& lo, float& hi, unsigned long long v){
    asm("mov.b64 {%0, %1}, %2;" : "=f"(lo), "=f"(hi) : "l"(v));
}
__device__ __forceinline__ unsigned long long ffma2(unsigned long long a,
        unsigned long long b, unsigned long long c){
    unsigned long long d;
    asm("fma.rn.f32x2 %0, %1, %2, %3;" : "=l"(d) : "l"(a), "l"(b), "l"(c));
    return d;
}
__device__ __forceinline__ float4 ldsm_cluster4(unsigned addr){
    float4 v;
    asm volatile("ld.shared::cluster.v4.f32 {%0,%1,%2,%3}, [%4];"
        : "=f"(v.x), "=f"(v.y), "=f"(v.z), "=f"(v.w) : "r"(addr) : "memory");
    return v;
}

// two transposes in one launch
__global__ void transpose2_kernel(const float* __restrict__ s0, const float* __restrict__ s1,
                                  long long d0, long long d1, int R, int C){
    const float* src = blockIdx.z ? s1 : s0;
    long long dst = blockIdx.z ? d1 : d0;
    long long total = (long long)R*C;
    for (long long i = blockIdx.x*(long long)blockDim.x + threadIdx.x; i < total;
         i += (long long)gridDim.x*blockDim.x){
        int r = (int)(i / C), c = (int)(i % C);
        g_s[dst + (long long)c*R + r] = src[i];
    }
}

// three transposes in one launch (agg_f, agg_b, fc1)
__global__ void transpose3_kernel(const float* __restrict__ s0, const float* __restrict__ s1,
                                  const float* __restrict__ s2,
                                  long long d0, long long d1, long long d2,
                                  int R01, int C01, int R2, int C2){
    int z = blockIdx.z;
    const float* src = (z==0) ? s0 : (z==1) ? s1 : s2;
    long long dst = (z==0) ? d0 : (z==1) ? d1 : d2;
    int R = (z<2) ? R01 : R2, C = (z<2) ? C01 : C2;
    long long total = (long long)R*C;
    for (long long i = blockIdx.x*(long long)blockDim.x + threadIdx.x; i < total;
         i += (long long)gridDim.x*blockDim.x){
        int r = (int)(i / C), c = (int)(i % C);
        g_s[dst + (long long)c*R + r] = src[i];
    }
}

// Batched GEMM over z=0..3 with register double-buffered tile loads.
__global__ void __launch_bounds__(256) gemm4_kernel(
        const float* __restrict__ A0, const float* __restrict__ A1,
        long long a0_off, long long a1_off,
        long long bt_base, long long bt_stride,
        const float* __restrict__ biasF, const float* __restrict__ biasB,
        long long c_off, int M, int N, int K){
    int z = blockIdx.z;
    const float* A  = (z < 2) ? (A0 ? A0 : (g_s + a0_off)) : (A1 ? A1 : (g_s + a1_off));
    const float* Bt = g_s + bt_base + (long long)(z & 1)*bt_stride;
    const float* bias = (z & 1) ? biasB : biasF;
    float* C = g_s + c_off + (long long)z*M*N;
    __shared__ float As[16][68];
    __shared__ float Bs[16][68];
    int bm = blockIdx.y*64, bn = blockIdx.x*64;
    int tid = threadIdx.x;
    int tr = tid >> 4, tc = tid & 15;
    float acc[4][4] = {};
    float ra[4], rb[4];

    #pragma unroll
    for (int ii = 0; ii < 4; ii++){
        int i = tid + ii*256;
        int m = i >> 4, k = i & 15;
        ra[ii] = (k < K) ? A[(long long)(bm+m)*K + k] : 0.f;
    }
    #pragma unroll
    for (int ii = 0; ii < 4; ii++){
        int i = tid + ii*256;
        int k = i >> 6, n = i & 63;
        rb[ii] = (k < K) ? Bt[(long long)k*N + bn + n] : 0.f;
    }

    for (int k0 = 0; k0 < K; k0 += 16){
        #pragma unroll
        for (int ii = 0; ii < 4; ii++){
            int i = tid + ii*256;
            As[i & 15][i >> 4] = ra[ii];
        }
        #pragma unroll
        for (int ii = 0; ii < 4; ii++){
            int i = tid + ii*256;
            Bs[i >> 6][i & 63] = rb[ii];
        }
        __syncthreads();
        int kn = k0 + 16;
        if (kn < K){
            #pragma unroll
            for (int ii = 0; ii < 4; ii++){
                int i = tid + ii*256;
                int m = i >> 4, k = i & 15;
                ra[ii] = (kn+k < K) ? A[(long long)(bm+m)*K + kn + k] : 0.f;
            }
            #pragma unroll
            for (int ii = 0; ii < 4; ii++){
                int i = tid + ii*256;
                int k = i >> 6, n = i & 63;
                rb[ii] = (kn+k < K) ? Bt[(long long)(kn+k)*N + bn + n] : 0.f;
            }
        }
        #pragma unroll
        for (int k = 0; k < 16; k++){
            float4 av = *(const float4*)&As[k][tr*4];
            float4 bv = *(const float4*)&Bs[k][tc*4];
            float a[4] = {av.x, av.y, av.z, av.w};
            float bb[4] = {bv.x, bv.y, bv.z, bv.w};
            #pragma unroll
            for (int i = 0; i < 4; i++)
                #pragma unroll
                for (int j = 0; j < 4; j++) acc[i][j] = fmaf(a[i], bb[j], acc[i][j]);
        }
        __syncthreads();
    }
    #pragma unroll
    for (int i = 0; i < 4; i++){
        int m = bm + tr*4 + i;
        #pragma unroll
        for (int j = 0; j < 4; j++){
            int n = bn + tc*4 + j;
            C[(long long)m*N + n] = acc[i][j] + bias[n];
        }
    }
}

// Cluster LSTM v6: 8 clusters x 8 CTAs, 2 batches per cluster (one wave).
// PULL protocol: h stays LOCAL (STS); peers read via ld.shared::cluster.
// Ordering: stores -> __syncthreads -> release-arrive -> peer acquire-wait
// (transitive happens-before; no cluster fence needed).
__global__ void __cluster_dims__(8,1,1) __launch_bounds__(256,1) lstm6_kernel(int stage,
        const float* __restrict__ Whh_f, const float* __restrict__ Whh_b){
    int slice;
    asm("mov.u32 %0, %%cluster_ctarank;" : "=r"(slice));
    int cid = blockIdx.x >> 3;           // 0..7
    int grpdir = cid >> 1;               // 0..3
    int bpair  = cid & 1;                // batches {2*bpair, 2*bpair+1}
    int grp = grpdir >> 1, dir = grpdir & 1;
    long long chunk0 = (long long)(grp*2 + dir)*Bz + (bpair*2 + 0);
    long long chunk1 = (long long)(grp*2 + dir)*Bz + (bpair*2 + 1);
    long long preBase = stage ? OFF_PRE_AGG : OFF_PRE_CTX;
    const float* pre0 = g_s + preBase + chunk0*(long long)Sz*H4z;
    const float* pre1 = g_s + preBase + chunk1*(long long)Sz*H4z;
    const float* Whh = dir ? Whh_b : Whh_f;
    float* hs0 = g_s + OFF_HS + chunk0*(long long)Sz*Hz;
    float* hs1 = g_s + OFF_HS + chunk1*(long long)Sz*Hz;

    int t = threadIdx.x;
    int kw = t >> 5, l = t & 31;

    // weight tile -> packed f32x2 registers: rows rho=4l..4l+3, k in [kw*32,+32)
    unsigned long long wrp[4][16];
    #pragma unroll
    for (int j = 0; j < 4; j++){
        int rho = 4*l + j;
        int G = (rho >> 5)*Hz + slice*32 + (rho & 31);
        const float4* row = (const float4*)(Whh + (long long)G*Hz) + kw*8;
        #pragma unroll
        for (int k4 = 0; k4 < 8; k4++){
            float4 v = row[k4];
            wrp[j][2*k4+0] = pk2(v.x, v.y);
            wrp[j][2*k4+1] = pk2(v.z, v.w);
        }
    }

    __shared__ float hsm[2][2][Hz];      // [buf][batch][h] — only own slice written
    __shared__ float part[2][8][128];
    __shared__ __align__(8) unsigned long long mbarS[2];

    hsm[0][0][t] = 0.f;
    hsm[0][1][t] = 0.f;
    if (t == 0){
        unsigned mb0 = smem_u32(&mbarS[0]);
        asm volatile("mbarrier.init.shared.b64 [%0], 16;" :: "r"(mb0) : "memory");
        asm volatile("mbarrier.init.shared.b64 [%0], 16;" :: "r"(mb0 + 8) : "memory");
    }
    unsigned rbase[8], rmb[8];
    {
        unsigned lbase = smem_u32(&hsm[0][0][0]);
        unsigned lmb   = smem_u32(&mbarS[0]);
        #pragma unroll
        for (int rb = 0; rb < 8; rb++){
            asm("mapa.shared::cluster.u32 %0, %1, %2;" : "=r"(rbase[rb]) : "r"(lbase), "r"(rb));
            asm("mapa.shared::cluster.u32 %0, %1, %2;" : "=r"(rmb[rb])   : "r"(lmb),   "r"(rb));
        }
    }
    // this warp's k-range [kw*32, kw*32+32) lives in rank kw's smem
    unsigned rh0base = rbase[kw] + (unsigned)(kw*32)*4u;
    float c = 0.f, hlast = 0.f;
    __syncthreads();
    asm volatile("barrier.cluster.arrive.aligned;" ::: "memory");
    asm volatile("barrier.cluster.wait.aligned;" ::: "memory");

    unsigned lmb0 = smem_u32(&mbarS[0]);

    for (int ts = 0; ts < Sz; ts++){
        int s = dir ? (Sz-1-ts) : ts;
        float prev0=0.f, prev1=0.f, prev2=0.f, prev3=0.f;
        if (t < 64){
            const float* prew = (t & 32) ? pre1 : pre0;
            long long base = (long long)s*H4z + slice*32 + (t & 31);
            prev0 = __ldg(&prew[base + 0*Hz]);
            prev1 = __ldg(&prew[base + 1*Hz]);
            prev2 = __ldg(&prew[base + 2*Hz]);
            prev3 = __ldg(&prew[base + 3*Hz]);
        }
        if (ts > 0){
            unsigned mb = lmb0 + ((ts-1) & 1)*8u;
            unsigned par = ((unsigned)(ts-1) >> 1) & 1u;
            unsigned done = 0;
            while (!done){
                asm volatile(
                    "{\n\t.reg .pred p;\n\t"
                    "mbarrier.try_wait.parity.acquire.cluster.shared::cta.b64 p, [%1], %2, 0x989680;\n\t"
                    "selp.b32 %0, 1, 0, p;\n\t}"
                    : "=r"(done) : "r"(mb), "r"(par) : "memory");
            }
        }
        int buf = ts & 1;
        // pull this warp's h slice from rank kw (broadcast loads, both batches)
        unsigned a0 = rh0base + (unsigned)((buf*2 + 0)*Hz)*4u;
        unsigned a1 = rh0base + (unsigned)((buf*2 + 1)*Hz)*4u;
        float4 hv0[8], hv1[8];
        #pragma unroll
        for (int k4 = 0; k4 < 8; k4++) hv0[k4] = ldsm_cluster4(a0 + (unsigned)k4*16u);
        #pragma unroll
        for (int k4 = 0; k4 < 8; k4++) hv1[k4] = ldsm_cluster4(a1 + (unsigned)k4*16u);

        unsigned long long a00=0, a01=0, a02=0, a03=0;
        unsigned long long a10=0, a11=0, a12=0, a13=0;
        #pragma unroll
        for (int k4 = 0; k4 < 8; k4++){
            float4 v0 = hv0[k4];
            float4 v1 = hv1[k4];
            unsigned long long h0a = pk2(v0.x, v0.y), h0b = pk2(v0.z, v0.w);
            unsigned long long h1a = pk2(v1.x, v1.y), h1b = pk2(v1.z, v1.w);
            a00 = ffma2(wrp[0][2*k4+0], h0a, a00);
            a01 = ffma2(wrp[1][2*k4+0], h0a, a01);
            a02 = ffma2(wrp[2][2*k4+0], h0a, a02);
            a03 = ffma2(wrp[3][2*k4+0], h0a, a03);
            a10 = ffma2(wrp[0][2*k4+0], h1a, a10);
            a11 = ffma2(wrp[1][2*k4+0], h1a, a11);
            a12 = ffma2(wrp[2][2*k4+0], h1a, a12);
            a13 = ffma2(wrp[3][2*k4+0], h1a, a13);
            a00 = ffma2(wrp[0][2*k4+1], h0b, a00);
            a01 = ffma2(wrp[1][2*k4+1], h0b, a01);
            a02 = ffma2(wrp[2][2*k4+1], h0b, a02);
            a03 = ffma2(wrp[3][2*k4+1], h0b, a03);
            a10 = ffma2(wrp[0][2*k4+1], h1b, a10);
            a11 = ffma2(wrp[1][2*k4+1], h1b, a11);
            a12 = ffma2(wrp[2][2*k4+1], h1b, a12);
            a13 = ffma2(wrp[3][2*k4+1], h1b, a13);
        }
        float lo, hi;
        upk2(lo, hi, a00); part[0][kw][4*l+0] = lo + hi;
        upk2(lo, hi, a01); part[0][kw][4*l+1] = lo + hi;
        upk2(lo, hi, a02); part[0][kw][4*l+2] = lo + hi;
        upk2(lo, hi, a03); part[0][kw][4*l+3] = lo + hi;
        upk2(lo, hi, a10); part[1][kw][4*l+0] = lo + hi;
        upk2(lo, hi, a11); part[1][kw][4*l+1] = lo + hi;
        upk2(lo, hi, a12); part[1][kw][4*l+2] = lo + hi;
        upk2(lo, hi, a13); part[1][kw][4*l+3] = lo + hi;
        __syncthreads();
        if (t < 64){
            int w = t >> 5, u = t & 31;
            float t0=prev0, t1=prev1, t2=prev2, t3=prev3;
            #pragma unroll
            for (int w2 = 0; w2 < 8; w2++){
                t0 += part[w][w2][u];
                t1 += part[w][w2][32+u];
                t2 += part[w][w2][64+u];
                t3 += part[w][w2][96+u];
            }
            float iv = fsig(t0);
            float fv = fsig(t1);
            float gv = ftanh(t2);
            float ov = fsig(t3);
            c = fv*c + iv*gv;
            float h = ov*ftanh(c);
            hlast = h;
            if (!stage){
                float* hsw = w ? hs1 : hs0;
                hsw[(long long)s*Hz + slice*32 + u] = h;
            }
            if (ts < Sz-1)
                hsm[(ts+1) & 1][w][slice*32 + u] = h;   // LOCAL store only
        }
        if (ts < Sz-1){
            __syncthreads();            // orders all reads + h stores before arrive
            if (t == 0 || t == 32){     // 2 arrivals/CTA x 8 CTAs = 16 per mbar
                unsigned slotoff = (unsigned)(ts & 1)*8u;
                #pragma unroll
                for (int rb = 0; rb < 8; rb++){
                    asm volatile("mbarrier.arrive.shared::cluster.b64 _, [%0];"
                                 :: "r"(rmb[rb] + slotoff) : "memory");
                }
            }
        }
    }
    if (stage && t < 64){
        int w = t >> 5, u = t & 31;
        int b = bpair*2 + w;
        g_s[OFF_HT + (long long)(grp*2+dir)*Bz*Hz + (long long)b*Hz + slice*32 + u] = hlast;
    }
}

// fused: plain norm + 10 weighted norms per (arr, r)
__global__ void norms_all_kernel(const float* __restrict__ w3, const float* __restrict__ w4){
    int id = blockIdx.x;                 // 4*B*S
    int arr = id / (Bz*Sz), r = id % (Bz*Sz);
    const float* w = (arr & 1) ? w4 : w3;
    __shared__ float red[Lz+1][8];
    int tid = threadIdx.x, wp = tid >> 5, lane = tid & 31;
    float x = g_s[OFF_HS + (long long)arr*BSH + (long long)r*Hz + tid];
    float vv = x*x;
    float s0 = warp_sum(vv);
    if (lane == 0) red[Lz][wp] = s0;
    for (int l = 0; l < Lz; l++){
        float wv = __ldg(&w[l*Hz + tid]);
        float s = warp_sum(wv*wv*vv);
        if (lane == 0) red[l][wp] = s;
    }
    __syncthreads();
    if (tid < Lz){
        float s = 0.f;
        #pragma unroll
        for (int i = 0; i < 8; i++) s += red[tid][i];
        g_s[OFF_NLW + (long long)(arr*Bz*Sz + r)*Lz + tid] = sqrtf(s);
    }
    if (tid == Lz){
        float s = 0.f;
        #pragma unroll
        for (int i = 0; i < 8; i++) s += red[Lz][i];
        g_s[OFF_NRM + (long long)arr*Bz*Sz + r] = sqrtf(s);
    }
}

// cosine attention + fused row max/sum
__global__ void att_kernel(){
    int id = blockIdx.x;                 // 2*B*S
    int dir = id / (Bz*Sz), r = id % (Bz*Sz);
    int b = r / Sz;
    __shared__ float v1s[Hz];
    __shared__ float sbs[8], sbm[8];
    int tid = threadIdx.x, w = tid >> 5, lane = tid & 31;
    v1s[tid] = g_s[OFF_HS + (long long)dir*BSH + (long long)r*Hz + tid];
    __syncthreads();
    const float4* v2 = (const float4*)(g_s + OFF_HS + (long long)(2+dir)*BSH + (long long)(b*Sz + tid)*Hz);
    float acc = 0.f;
    #pragma unroll 8
    for (int h4 = 0; h4 < Hz/4; h4++){
        float4 o = v2[h4];
        acc = fmaf(v1s[4*h4+0], o.x, acc);
        acc = fmaf(v1s[4*h4+1], o.y, acc);
        acc = fmaf(v1s[4*h4+2], o.z, acc);
        acc = fmaf(v1s[4*h4+3], o.w, acc);
    }
    float n1 = g_s[OFF_NRM + (long long)dir*Bz*Sz + r];
    float n2 = g_s[OFF_NRM + (long long)(2+dir)*Bz*Sz + b*Sz + tid];
    float d = n1*n2;
    float a = acc / (d > EPSf ? d : EPSf);
    g_s[OFF_ATT + (long long)dir*BSS + (long long)r*Sz + tid] = a;
    float ssum = warp_sum(a);
    float smax = warp_max(a);
    if (lane == 0){ sbs[w] = ssum; sbm[w] = smax; }
    __syncthreads();
    if (tid == 0){
        float tots = 0.f, totm = -3.4e38f;
        #pragma unroll
        for (int i = 0; i < 8; i++){ tots += sbs[i]; totm = fmaxf(totm, sbm[i]); }
        g_s[OFF_ROWSUM + (long long)dir*Bz*Sz + r] = tots;
        if (dir == 0){
            float* mp = g_s + OFF_MVP + (long long)r*AGGz;
            mp[0] = totm;
            mp[1] = tots / (float)Sz;
        }
    }
}

// mean_h / max_h, tiled: 8 p-rows per block; grid 2*B*32
__global__ void statsrow_kernel(){
    int id = blockIdx.x;
    int dir = id / (Bz*32); int rem = id % (Bz*32);
    int b = rem / 32, pt = rem % 32;
    __shared__ float arow[8][Sz];
    int tid = threadIdx.x;
    const float* att = g_s + OFF_ATT + (long long)dir*BSS + (long long)(b*Sz + pt*8)*Sz;
    for (int i = tid; i < 8*Sz; i += 256)
        arow[i >> 8][i & 255] = att[(long long)(i >> 8)*Sz + (i & 255)];
    __syncthreads();
    const float* vh = g_s + OFF_HS + (long long)(2+dir)*BSH + (long long)b*Sz*Hz;
    float sm[8], mx[8];
    #pragma unroll
    for (int p = 0; p < 8; p++){ sm[p] = 0.f; mx[p] = -3.4e38f; }
    for (int q = 0; q < Sz; q++){
        float vhv = vh[(long long)q*Hz + tid];
        #pragma unroll
        for (int p = 0; p < 8; p++){
            float pr = arow[p][q]*vhv;
            sm[p] += pr; mx[p] = fmaxf(mx[p], pr);
        }
    }
    #pragma unroll
    for (int p = 0; p < 8; p++){
        int rr = b*Sz + pt*8 + p;
        float rs = g_s[OFF_ROWSUM + (long long)dir*Bz*Sz + rr];
        g_s[OFF_STATS + (long long)(0*2+dir)*BSH + (long long)rr*Hz + tid] = sm[p] / (rs > EPSf ? rs : EPSf);
        g_s[OFF_STATS + (long long)(1*2+dir)*BSH + (long long)rr*Hz + tid] = mx[p];
    }
}

// mean_p / max_p, tiled: 8 q-cols per block; grid 2*B*32.
// Also computes col sum/max internally (colstats kernel folded in).
__global__ void statscol_kernel(){
    int id = blockIdx.x;
    int dir = id / (Bz*32); int rem = id % (Bz*32);
    int b = rem / 32, qt = rem % 32;
    __shared__ float acol[8][Sz];
    int tid = threadIdx.x;
    const float* att = g_s + OFF_ATT + (long long)dir*BSS + (long long)b*Sz*Sz;
    for (int i = tid; i < 8*Sz; i += 256){
        int p = i >> 3, j = i & 7;
        acol[j][p] = att[(long long)p*Sz + qt*8 + j];
    }
    __syncthreads();
    const float* vp = g_s + OFF_HS + (long long)dir*BSH + (long long)b*Sz*Hz;
    float sm[8], mx[8], cs[8], cm[8];
    #pragma unroll
    for (int j = 0; j < 8; j++){ sm[j] = 0.f; mx[j] = -3.4e38f; cs[j] = 0.f; cm[j] = -3.4e38f; }
    for (int p = 0; p < Sz; p++){
        float vpv = vp[(long long)p*Hz + tid];
        #pragma unroll
        for (int j = 0; j < 8; j++){
            float av = acol[j][p];
            cs[j] += av; cm[j] = fmaxf(cm[j], av);
            float pr = av*vpv;
            sm[j] += pr; mx[j] = fmaxf(mx[j], pr);
        }
    }
    #pragma unroll
    for (int j = 0; j < 8; j++){
        int rr = b*Sz + qt*8 + j;
        g_s[OFF_STATS + (long long)(2*2+dir)*BSH + (long long)rr*Hz + tid] = sm[j] / (cs[j] > EPSf ? cs[j] : EPSf);
        g_s[OFF_STATS + (long long)(3*2+dir)*BSH + (long long)rr*Hz + tid] = mx[j];
    }
    if (tid == 0 && dir == 0){
        #pragma unroll
        for (int j = 0; j < 8; j++){
            float* mh = g_s + OFF_MVH + (long long)(b*Sz + qt*8 + j)*AGGz;
            mh[0] = cm[j];
            mh[1] = cs[j] / (float)Sz;
        }
    }
}

// pairwise matching, single pass: row-max -> mv_p; spill mm -> scratch for colmax
__global__ void __launch_bounds__(256) pairwise_kernel(const float* __restrict__ w3, const float* __restrict__ w4){
    int id = blockIdx.x;                 // 2*B*S
    int dir = id / (Bz*Sz), r = id % (Bz*Sz);
    int b = r / Sz, s = r % Sz;
    const float* w = dir ? w4 : w3;
    __shared__ float w2s[Lz*Hz];
    __shared__ float vrow[Hz];
    __shared__ float red[Lz][8];
    int tid = threadIdx.x, wp = tid >> 5, lane = tid & 31;
    for (int i = tid; i < Lz*Hz; i += 256){ float x = w[i]; w2s[i] = x*x; }
    vrow[tid] = g_s[OFF_HS + (long long)dir*BSH + (long long)r*Hz + tid];
    __syncthreads();
    const float4* other = (const float4*)(g_s + OFF_HS + (long long)(2+dir)*BSH + (long long)(b*Sz + tid)*Hz);
    float acc[Lz];
    #pragma unroll
    for (int l = 0; l < Lz; l++) acc[l] = 0.f;
    for (int h4 = 0; h4 < Hz/4; h4++){
        float4 o = other[h4];
        float p0 = vrow[4*h4+0]*o.x, p1 = vrow[4*h4+1]*o.y;
        float p2 = vrow[4*h4+2]*o.z, p3 = vrow[4*h4+3]*o.w;
        #pragma unroll
        for (int l = 0; l < Lz; l++){
            acc[l] = fmaf(w2s[l*Hz + 4*h4+0], p0, acc[l]);
            acc[l] = fmaf(w2s[l*Hz + 4*h4+1], p1, acc[l]);
            acc[l] = fmaf(w2s[l*Hz + 4*h4+2], p2, acc[l]);
            acc[l] = fmaf(w2s[l*Hz + 4*h4+3], p3, acc[l]);
        }
    }
    const float* nfix = g_s + OFF_NLW + (long long)((0*2+dir)*Bz*Sz + b*Sz + s)*Lz;
    const float* nstr = g_s + OFF_NLW + (long long)((1*2+dir)*Bz*Sz + b*Sz + tid)*Lz;
    float* mmS = g_s + OFF_MMS + (long long)((dir*Bz + b)*Lz)*Sz*Sz;
    #pragma unroll
    for (int l = 0; l < Lz; l++){
        float d = nfix[l]*nstr[l];
        float v = acc[l] / (d > EPSf ? d : EPSf);
        mmS[(long long)l*Sz*Sz + (long long)s*Sz + tid] = v;
        float m = warp_max(v);
        if (lane == 0) red[l][wp] = m;
    }
    __syncthreads();
    if (tid < Lz){
        float m = red[tid][0];
        #pragma unroll
        for (int i = 1; i < 8; i++) m = fmaxf(m, red[tid][i]);
        g_s[OFF_MVP + (long long)(b*Sz + s)*AGGz + 2 + dir*10 + tid] = m;
    }
}

// column max of mm over p -> mv_h.  grid 2*B*L, 256 threads (tid = q)
__global__ void colmax_kernel(){
    int id = blockIdx.x;
    int dir = id / (Bz*Lz); int rem = id % (Bz*Lz);
    int b = rem / Lz, l = rem % Lz;
    int q = threadIdx.x;
    const float* mmS = g_s + OFF_MMS + ((long long)((dir*Bz + b)*Lz) + l)*Sz*Sz;
    float m = -3.4e38f;
    for (int p = 0; p < Sz; p++) m = fmaxf(m, mmS[(long long)p*Sz + q]);
    g_s[OFF_MVH + (long long)(b*Sz + q)*AGGz + 2 + dir*10 + l] = m;
}

// attentive / max-attentive mp_match, 8 combos
__global__ void mpmatch_kernel(const float* __restrict__ w5, const float* __restrict__ w6,
                               const float* __restrict__ w7, const float* __restrict__ w8){
    int id = blockIdx.x;                 // 8*B*S
    int k = id / (Bz*Sz), r = id % (Bz*Sz);
    int b = r / Sz, s = r % Sz;
    int dir = k & 1;
    int side = k >> 2;
    int arr  = side ? (2+dir) : dir;
    int kind = side ? ((k & 2) ? 3 : 2) : ((k & 2) ? 1 : 0);
    int wsel = k & 3;
    const float* w = (wsel==0) ? w5 : (wsel==1) ? w6 : (wsel==2) ? w7 : w8;
    __shared__ float rnum[Lz][8], rn1[Lz][8], rn2[Lz][8];
    int tid = threadIdx.x, wp = tid >> 5, lane = tid & 31;
    float a  = g_s[OFF_HS + (long long)arr*BSH + (long long)(b*Sz+s)*Hz + tid];
    float bb = g_s[OFF_STATS + (long long)(kind*2+dir)*BSH + (long long)(b*Sz+s)*Hz + tid];
    float ab = a*bb, aa = a*a, b2 = bb*bb;
    for (int l = 0; l < Lz; l++){
        float wv = __ldg(&w[l*Hz + tid]);
        float w2 = wv*wv;
        float num = warp_sum(w2*ab);
        float n1  = warp_sum(w2*aa);
        float n2  = warp_sum(w2*b2);
        if (lane == 0){ rnum[l][wp] = num; rn1[l][wp] = n1; rn2[l][wp] = n2; }
    }
    __syncthreads();
    if (tid < Lz){
        float N = 0.f, A = 0.f, B2 = 0.f;
        #pragma unroll
        for (int i = 0; i < 8; i++){ N += rnum[tid][i]; A += rn1[tid][i]; B2 += rn2[tid][i]; }
        g_s[(side ? OFF_MVH : OFF_MVP) + (long long)(b*Sz + s)*AGGz + 22 + wsel*10 + tid]
            = N / fmaxf(sqrtf(A)*sqrtf(B2), EPSf);
    }
}

__global__ void means_kernel(const float* __restrict__ left, const float* __restrict__ right){
    int which = blockIdx.x >> 2, b = blockIdx.x & 3;   // grid 8, 320 threads
    int d = threadIdx.x;
    if (d >= Dz) return;
    const float* x = which ? right : left;
    float s = 0.f;
    for (int t = 0; t < Sz; t++) s += x[((long long)b*Sz + t)*Dz + d];
    g_s[OFF_MEANS + (long long)which*Bz*Dz + (long long)b*Dz + d] = s / (float)Sz;
}

__global__ void fc1_kernel(const float* __restrict__ fc1_b){
    int b = blockIdx.x;                  // grid B, 512 threads
    int tid = threadIdx.x;
    __shared__ float feat[FEATN + 6];
    for (int i = tid; i < FEATN; i += 512){
        float v;
        if (i < 1024)       v = g_s[OFF_HT + (long long)(i >> 8)*Bz*Hz + (long long)b*Hz + (i & 255)];
        else if (i < 1026)  v = 0.5f;
        else if (i < 1326)  v = g_s[OFF_MEANS + (long long)b*Dz + (i - 1026)];
        else                v = g_s[OFF_MEANS + (long long)Bz*Dz + (long long)b*Dz + (i - 1326)];
        feat[i] = v;
    }
    __syncthreads();
    float acc = fc1_b[tid];
    for (int k = 0; k < FEATN; k++)
        acc = fmaf(feat[k], g_s[OFF_FC1WT + (long long)k*512 + tid], acc);
    g_s[OFF_FC1O + (long long)b*512 + tid] = tanhf(acc);
}

__global__ void fc2_kernel(const float* __restrict__ W2, const float* __restrict__ b2,
                           float* __restrict__ out){
    int b = blockIdx.x;                  // grid B, 512 threads
    int tid = threadIdx.x;
    __shared__ float y[512];
    y[tid] = g_s[OFF_FC1O + (long long)b*512 + tid];
    __syncthreads();
    if (tid < NCLSz){
        float acc = b2[tid];
        for (int o = 0; o < 512; o++) acc = fmaf(y[o], W2[(long long)tid*512 + o], acc);
        out[b*NCLSz + tid] = acc;
    }
}

extern "C" void kernel_launch(void* const* d_in, const int* in_sizes, int n_in,
                              void* d_out, int out_size){
    const float* left      = (const float*)d_in[0];
    const float* right     = (const float*)d_in[1];
    const float* ctx_Wih_f = (const float*)d_in[2];
    const float* ctx_Whh_f = (const float*)d_in[3];
    const float* ctx_b_f   = (const float*)d_in[4];
    const float* ctx_Wih_b = (const float*)d_in[5];
    const float* ctx_Whh_b = (const float*)d_in[6];
    const float* ctx_b_b   = (const float*)d_in[7];
    const float* agg_Wih_f = (const float*)d_in[8];
    const float* agg_Whh_f = (const float*)d_in[9];
    const float* agg_b_f   = (const float*)d_in[10];
    const float* agg_Wih_b = (const float*)d_in[11];
    const float* agg_Whh_b = (const float*)d_in[12];
    const float* agg_b_b   = (const float*)d_in[13];
    const float* mp_w3     = (const float*)d_in[14];
    const float* mp_w4     = (const float*)d_in[15];
    const float* mp_w5     = (const float*)d_in[16];
    const float* mp_w6     = (const float*)d_in[17];
    const float* mp_w7     = (const float*)d_in[18];
    const float* mp_w8     = (const float*)d_in[19];
    const float* fc1_W     = (const float*)d_in[20];
    const float* fc1_b     = (const float*)d_in[21];
    const float* fc2_W     = (const float*)d_in[22];
    const float* fc2_b     = (const float*)d_in[23];
    float* out = (float*)d_out;

    // weight transposes: 2 launches (lstm6 stays launch #4 for ncu)
    transpose2_kernel<<<dim3(128,1,2),256>>>(ctx_Wih_f, ctx_Wih_b, OFF_WIHT_CF, OFF_WIHT_CB, H4z, Dz);
    transpose3_kernel<<<dim3(128,1,3),256>>>(agg_Wih_f, agg_Wih_b, fc1_W,
        OFF_WIHT_AF, OFF_WIHT_AB, OFF_FC1WT, H4z, AGGz, 512, FEATN);

    // ctx pre-activation GEMMs, batched over z (left f/b, right f/b)
    gemm4_kernel<<<dim3(16,16,4),256>>>(left, right, 0, 0,
        OFF_WIHT_CF, (long long)Dz*H4z, ctx_b_f, ctx_b_b,
        OFF_PRE_CTX, Bz*Sz, H4z, Dz);

    lstm6_kernel<<<64,256>>>(0, ctx_Whh_f, ctx_Whh_b);

    norms_all_kernel<<<4*Bz*Sz,256>>>(mp_w3, mp_w4);
    att_kernel<<<2*Bz*Sz,256>>>();
    statsrow_kernel<<<2*Bz*32,256>>>();
    statscol_kernel<<<2*Bz*32,256>>>();
    pairwise_kernel<<<2*Bz*Sz,256>>>(mp_w3, mp_w4);
    colmax_kernel<<<2*Bz*Lz,256>>>();
    mpmatch_kernel<<<8*Bz*Sz,256>>>(mp_w5, mp_w6, mp_w7, mp_w8);
    means_kernel<<<8,320>>>(left, right);

    // agg pre-activation GEMMs, batched over z (mv_p f/b, mv_h f/b)
    gemm4_kernel<<<dim3(16,16,4),256>>>(nullptr, nullptr, OFF_MVP, OFF_MVH,
        OFF_WIHT_AF, (long long)AGGz*H4z, agg_b_f, agg_b_b,
        OFF_PRE_AGG, Bz*Sz, H4z, AGGz);

    lstm6_kernel<<<64,256>>>(1, agg_Whh_f, agg_Whh_b);

    fc1_kernel<<<Bz,512>>>(fc1_b);
    fc2_kernel<<<Bz,512>>>(fc2_W, fc2_b, out);
}

// round 15
// speedup vs baseline: 1.4595x; 1.0125x over previous
#include <cuda_runtime.h>
#include <math.h>

// ---------------- problem constants ----------------
#define Bz   4
#define Sz   256
#define Dz   300
#define Hz   256
#define H4z  1024
#define Lz   10
#define AGGz 62
#define NCLSz 22
#define FEATN 1626          // 4*H + 2 + 2*D
#define BSH  (Bz*Sz*Hz)     // 262144
#define BSS  (Bz*Sz*Sz)     // 262144
#define EPSf 1e-8f

// ---------------- scratch layout (floats) ----------------
constexpr long long OFF_WIHT_CF = 0;
constexpr long long OFF_WIHT_CB = OFF_WIHT_CF + (long long)Dz*H4z;
constexpr long long OFF_WIHT_AF = OFF_WIHT_CB + (long long)Dz*H4z;
constexpr long long OFF_WIHT_AB = OFF_WIHT_AF + (long long)AGGz*H4z;
constexpr long long OFF_FC1WT   = OFF_WIHT_AB + (long long)AGGz*H4z;
constexpr long long OFF_PRE_CTX = OFF_FC1WT + (long long)FEATN*512;
constexpr long long OFF_HS      = OFF_PRE_CTX + 4LL*Bz*Sz*H4z;   // p_fw,p_bw,h_fw,h_bw
constexpr long long OFF_NRM     = OFF_HS + 4LL*BSH;              // (4,B,S)
constexpr long long OFF_ATT     = OFF_NRM + 4LL*Bz*Sz;           // (2,B,S,S)
constexpr long long OFF_ROWSUM  = OFF_ATT + 2LL*BSS;             // (2,B,S)
constexpr long long OFF_COLSUM  = OFF_ROWSUM + 2LL*Bz*Sz;        // (2,B,S) [unused]
constexpr long long OFF_STATS   = OFF_COLSUM + 2LL*Bz*Sz;        // (4 kinds x 2 dirs, B,S,H)
constexpr long long OFF_NLW     = OFF_STATS + 8LL*BSH;           // (arr, B,S,L)
constexpr long long OFF_MVP     = OFF_NLW + 4LL*Bz*Sz*Lz;        // (B,S,62)
constexpr long long OFF_MVH     = OFF_MVP + (long long)Bz*Sz*AGGz;
constexpr long long OFF_PRE_AGG = OFF_MVH + (long long)Bz*Sz*AGGz;
constexpr long long OFF_HT      = OFF_PRE_AGG + 4LL*Bz*Sz*H4z;   // (4,B,H)
constexpr long long OFF_MEANS   = OFF_HT + 4LL*Bz*Hz;            // (2,B,D)
constexpr long long OFF_FC1O    = OFF_MEANS + 2LL*Bz*Dz;         // (B,512)
constexpr long long OFF_MMS     = OFF_FC1O + (long long)Bz*512;  // (2,B,L,P,Q) mm spill
constexpr long long SCRATCH_N   = OFF_MMS + 2LL*Bz*Lz*Sz*Sz + 64;

__device__ __align__(256) float g_s[SCRATCH_N];

__device__ __forceinline__ float warp_sum(float v){
    #pragma unroll
    for (int o = 16; o > 0; o >>= 1) v += __shfl_down_sync(0xffffffffu, v, o);
    return v;
}
__device__ __forceinline__ float warp_max(float v){
    #pragma unroll
    for (int o = 16; o > 0; o >>= 1) v = fmaxf(v, __shfl_down_sync(0xffffffffu, v, o));
    return v;
}
__device__ __forceinline__ unsigned smem_u32(const void* p){
    unsigned r;
    asm("{ .reg .u64 t; cvta.to.shared.u64 t, %1; cvt.u32.u64 %0, t; }" : "=r"(r) : "l"(p));
    return r;
}
// fast, inf-safe sigmoid / tanh via MUFU-based __expf (~1e-7 rel err)
__device__ __forceinline__ float fsig(float x){ return __fdividef(1.f, 1.f + __expf(-x)); }
__device__ __forceinline__ float ftanh(float x){ return 1.f - __fdividef(2.f, 1.f + __expf(2.f*x)); }

__device__ __forceinline__ unsigned long long pk2(float a, float b){
    unsigned long long r;
    asm("mov.b64 %0, {%1, %2};" : "=l"(r) : "f"(a), "f"(b));
    return r;
}
__device__ __forceinline__ void upk2(float& lo, float& hi, unsigned long long v){
    asm("mov.b64 {%0, %1}, %2;" : "=f"(lo), "=f"(hi) : "l"(v));
}
__device__ __forceinline__ unsigned long long ffma2(unsigned long long a,
        unsigned long long b, unsigned long long c){
    unsigned long long d;
    asm("fma.rn.f32x2 %0, %1, %2, %3;" : "=l"(d) : "l"(a), "l"(b), "l"(c));
    return d;
}
__device__ __forceinline__ float4 ldsm_cluster4(unsigned addr){
    float4 v;
    asm volatile("ld.shared::cluster.v4.f32 {%0,%1,%2,%3}, [%4];"
        : "=f"(v.x), "=f"(v.y), "=f"(v.z), "=f"(v.w) : "r"(addr) : "memory");
    return v;
}

// two transposes in one launch
__global__ void transpose2_kernel(const float* __restrict__ s0, const float* __restrict__ s1,
                                  long long d0, long long d1, int R, int C){
    const float* src = blockIdx.z ? s1 : s0;
    long long dst = blockIdx.z ? d1 : d0;
    long long total = (long long)R*C;
    for (long long i = blockIdx.x*(long long)blockDim.x + threadIdx.x; i < total;
         i += (long long)gridDim.x*blockDim.x){
        int r = (int)(i / C), c = (int)(i % C);
        g_s[dst + (long long)c*R + r] = src[i];
    }
}

// three transposes in one launch (agg_f, agg_b, fc1)
__global__ void transpose3_kernel(const float* __restrict__ s0, const float* __restrict__ s1,
                                  const float* __restrict__ s2,
                                  long long d0, long long d1, long long d2,
                                  int R01, int C01, int R2, int C2){
    int z = blockIdx.z;
    const float* src = (z==0) ? s0 : (z==1) ? s1 : s2;
    long long dst = (z==0) ? d0 : (z==1) ? d1 : d2;
    int R = (z<2) ? R01 : R2, C = (z<2) ? C01 : C2;
    long long total = (long long)R*C;
    for (long long i = blockIdx.x*(long long)blockDim.x + threadIdx.x; i < total;
         i += (long long)gridDim.x*blockDim.x){
        int r = (int)(i / C), c = (int)(i % C);
        g_s[dst + (long long)c*R + r] = src[i];
    }
}

// Batched GEMM over z=0..3 with register double-buffered tile loads.
__global__ void __launch_bounds__(256) gemm4_kernel(
        const float* __restrict__ A0, const float* __restrict__ A1,
        long long a0_off, long long a1_off,
        long long bt_base, long long bt_stride,
        const float* __restrict__ biasF, const float* __restrict__ biasB,
        long long c_off, int M, int N, int K){
    int z = blockIdx.z;
    const float* A  = (z < 2) ? (A0 ? A0 : (g_s + a0_off)) : (A1 ? A1 : (g_s + a1_off));
    const float* Bt = g_s + bt_base + (long long)(z & 1)*bt_stride;
    const float* bias = (z & 1) ? biasB : biasF;
    float* C = g_s + c_off + (long long)z*M*N;
    __shared__ float As[16][68];
    __shared__ float Bs[16][68];
    int bm = blockIdx.y*64, bn = blockIdx.x*64;
    int tid = threadIdx.x;
    int tr = tid >> 4, tc = tid & 15;
    float acc[4][4] = {};
    float ra[4], rb[4];

    #pragma unroll
    for (int ii = 0; ii < 4; ii++){
        int i = tid + ii*256;
        int m = i >> 4, k = i & 15;
        ra[ii] = (k < K) ? A[(long long)(bm+m)*K + k] : 0.f;
    }
    #pragma unroll
    for (int ii = 0; ii < 4; ii++){
        int i = tid + ii*256;
        int k = i >> 6, n = i & 63;
        rb[ii] = (k < K) ? Bt[(long long)k*N + bn + n] : 0.f;
    }

    for (int k0 = 0; k0 < K; k0 += 16){
        #pragma unroll
        for (int ii = 0; ii < 4; ii++){
            int i = tid + ii*256;
            As[i & 15][i >> 4] = ra[ii];
        }
        #pragma unroll
        for (int ii = 0; ii < 4; ii++){
            int i = tid + ii*256;
            Bs[i >> 6][i & 63] = rb[ii];
        }
        __syncthreads();
        int kn = k0 + 16;
        if (kn < K){
            #pragma unroll
            for (int ii = 0; ii < 4; ii++){
                int i = tid + ii*256;
                int m = i >> 4, k = i & 15;
                ra[ii] = (kn+k < K) ? A[(long long)(bm+m)*K + kn + k] : 0.f;
            }
            #pragma unroll
            for (int ii = 0; ii < 4; ii++){
                int i = tid + ii*256;
                int k = i >> 6, n = i & 63;
                rb[ii] = (kn+k < K) ? Bt[(long long)(kn+k)*N + bn + n] : 0.f;
            }
        }
        #pragma unroll
        for (int k = 0; k < 16; k++){
            float4 av = *(const float4*)&As[k][tr*4];
            float4 bv = *(const float4*)&Bs[k][tc*4];
            float a[4] = {av.x, av.y, av.z, av.w};
            float bb[4] = {bv.x, bv.y, bv.z, bv.w};
            #pragma unroll
            for (int i = 0; i < 4; i++)
                #pragma unroll
                for (int j = 0; j < 4; j++) acc[i][j] = fmaf(a[i], bb[j], acc[i][j]);
        }
        __syncthreads();
    }
    #pragma unroll
    for (int i = 0; i < 4; i++){
        int m = bm + tr*4 + i;
        #pragma unroll
        for (int j = 0; j < 4; j++){
            int n = bn + tc*4 + j;
            C[(long long)m*N + n] = acc[i][j] + bias[n];
        }
    }
}

// Cluster LSTM v7: pull protocol; single __syncthreads per step —
// the mbarrier wait doubles as the second barrier (own-CTA cell arrivals
// gate part[] reuse and hsm buf reuse transitively).
__global__ void __cluster_dims__(8,1,1) __launch_bounds__(256,1) lstm7_kernel(int stage,
        const float* __restrict__ Whh_f, const float* __restrict__ Whh_b){
    int slice;
    asm("mov.u32 %0, %%cluster_ctarank;" : "=r"(slice));
    int cid = blockIdx.x >> 3;           // 0..7
    int grpdir = cid >> 1;               // 0..3
    int bpair  = cid & 1;                // batches {2*bpair, 2*bpair+1}
    int grp = grpdir >> 1, dir = grpdir & 1;
    long long chunk0 = (long long)(grp*2 + dir)*Bz + (bpair*2 + 0);
    long long chunk1 = (long long)(grp*2 + dir)*Bz + (bpair*2 + 1);
    long long preBase = stage ? OFF_PRE_AGG : OFF_PRE_CTX;
    const float* pre0 = g_s + preBase + chunk0*(long long)Sz*H4z;
    const float* pre1 = g_s + preBase + chunk1*(long long)Sz*H4z;
    const float* Whh = dir ? Whh_b : Whh_f;
    float* hs0 = g_s + OFF_HS + chunk0*(long long)Sz*Hz;
    float* hs1 = g_s + OFF_HS + chunk1*(long long)Sz*Hz;

    int t = threadIdx.x;
    int kw = t >> 5, l = t & 31;

    // weight tile -> packed f32x2 registers: rows rho=4l..4l+3, k in [kw*32,+32)
    unsigned long long wrp[4][16];
    #pragma unroll
    for (int j = 0; j < 4; j++){
        int rho = 4*l + j;
        int G = (rho >> 5)*Hz + slice*32 + (rho & 31);
        const float4* row = (const float4*)(Whh + (long long)G*Hz) + kw*8;
        #pragma unroll
        for (int k4 = 0; k4 < 8; k4++){
            float4 v = row[k4];
            wrp[j][2*k4+0] = pk2(v.x, v.y);
            wrp[j][2*k4+1] = pk2(v.z, v.w);
        }
    }

    __shared__ float hsm[2][2][Hz];      // [buf][batch][h] — only own slice written
    __shared__ float part[2][8][128];
    __shared__ __align__(8) unsigned long long mbarS[2];

    hsm[0][0][t] = 0.f;
    hsm[0][1][t] = 0.f;
    if (t == 0){
        unsigned mb0 = smem_u32(&mbarS[0]);
        asm volatile("mbarrier.init.shared.b64 [%0], 16;" :: "r"(mb0) : "memory");
        asm volatile("mbarrier.init.shared.b64 [%0], 16;" :: "r"(mb0 + 8) : "memory");
    }
    unsigned rbase[8], rmb[8];
    {
        unsigned lbase = smem_u32(&hsm[0][0][0]);
        unsigned lmb   = smem_u32(&mbarS[0]);
        #pragma unroll
        for (int rb = 0; rb < 8; rb++){
            asm("mapa.shared::cluster.u32 %0, %1, %2;" : "=r"(rbase[rb]) : "r"(lbase), "r"(rb));
            asm("mapa.shared::cluster.u32 %0, %1, %2;" : "=r"(rmb[rb])   : "r"(lmb),   "r"(rb));
        }
    }
    // this warp's k-range [kw*32, kw*32+32) lives in rank kw's smem
    unsigned rh0base = rbase[kw] + (unsigned)(kw*32)*4u;
    float c = 0.f, hlast = 0.f;
    __syncthreads();
    asm volatile("barrier.cluster.arrive.aligned;" ::: "memory");
    asm volatile("barrier.cluster.wait.aligned;" ::: "memory");

    unsigned lmb0 = smem_u32(&mbarS[0]);

    for (int ts = 0; ts < Sz; ts++){
        int s = dir ? (Sz-1-ts) : ts;
        float prev0=0.f, prev1=0.f, prev2=0.f, prev3=0.f;
        if (t < 64){
            const float* prew = (t & 32) ? pre1 : pre0;
            long long base = (long long)s*H4z + slice*32 + (t & 31);
            prev0 = __ldg(&prew[base + 0*Hz]);
            prev1 = __ldg(&prew[base + 1*Hz]);
            prev2 = __ldg(&prew[base + 2*Hz]);
            prev3 = __ldg(&prew[base + 3*Hz]);
        }
        if (ts > 0){
            unsigned mb = lmb0 + ((ts-1) & 1)*8u;
            unsigned par = ((unsigned)(ts-1) >> 1) & 1u;
            unsigned done = 0;
            while (!done){
                asm volatile(
                    "{\n\t.reg .pred p;\n\t"
                    "mbarrier.try_wait.parity.acquire.cluster.shared::cta.b64 p, [%1], %2, 0x989680;\n\t"
                    "selp.b32 %0, 1, 0, p;\n\t}"
                    : "=r"(done) : "r"(mb), "r"(par) : "memory");
            }
        }
        int buf = ts & 1;
        // pull this warp's h slice from rank kw (broadcast loads, both batches)
        unsigned a0 = rh0base + (unsigned)((buf*2 + 0)*Hz)*4u;
        unsigned a1 = rh0base + (unsigned)((buf*2 + 1)*Hz)*4u;
        float4 hv0[8], hv1[8];
        #pragma unroll
        for (int k4 = 0; k4 < 8; k4++) hv0[k4] = ldsm_cluster4(a0 + (unsigned)k4*16u);
        #pragma unroll
        for (int k4 = 0; k4 < 8; k4++) hv1[k4] = ldsm_cluster4(a1 + (unsigned)k4*16u);

        unsigned long long a00=0, a01=0, a02=0, a03=0;
        unsigned long long a10=0, a11=0, a12=0, a13=0;
        #pragma unroll
        for (int k4 = 0; k4 < 8; k4++){
            float4 v0 = hv0[k4];
            float4 v1 = hv1[k4];
            unsigned long long h0a = pk2(v0.x, v0.y), h0b = pk2(v0.z, v0.w);
            unsigned long long h1a = pk2(v1.x, v1.y), h1b = pk2(v1.z, v1.w);
            a00 = ffma2(wrp[0][2*k4+0], h0a, a00);
            a01 = ffma2(wrp[1][2*k4+0], h0a, a01);
            a02 = ffma2(wrp[2][2*k4+0], h0a, a02);
            a03 = ffma2(wrp[3][2*k4+0], h0a, a03);
            a10 = ffma2(wrp[0][2*k4+0], h1a, a10);
            a11 = ffma2(wrp[1][2*k4+0], h1a, a11);
            a12 = ffma2(wrp[2][2*k4+0], h1a, a12);
            a13 = ffma2(wrp[3][2*k4+0], h1a, a13);
            a00 = ffma2(wrp[0][2*k4+1], h0b, a00);
            a01 = ffma2(wrp[1][2*k4+1], h0b, a01);
            a02 = ffma2(wrp[2][2*k4+1], h0b, a02);
            a03 = ffma2(wrp[3][2*k4+1], h0b, a03);
            a10 = ffma2(wrp[0][2*k4+1], h1b, a10);
            a11 = ffma2(wrp[1][2*k4+1], h1b, a11);
            a12 = ffma2(wrp[2][2*k4+1], h1b, a12);
            a13 = ffma2(wrp[3][2*k4+1], h1b, a13);
        }
        float lo, hi;
        upk2(lo, hi, a00); part[0][kw][4*l+0] = lo + hi;
        upk2(lo, hi, a01); part[0][kw][4*l+1] = lo + hi;
        upk2(lo, hi, a02); part[0][kw][4*l+2] = lo + hi;
        upk2(lo, hi, a03); part[0][kw][4*l+3] = lo + hi;
        upk2(lo, hi, a10); part[1][kw][4*l+0] = lo + hi;
        upk2(lo, hi, a11); part[1][kw][4*l+1] = lo + hi;
        upk2(lo, hi, a12); part[1][kw][4*l+2] = lo + hi;
        upk2(lo, hi, a13); part[1][kw][4*l+3] = lo + hi;
        __syncthreads();   // orders: all DSMEM reads + part writes (single barrier/step)
        if (t < 64){
            int w = t >> 5, u = t & 31;
            float t0=prev0, t1=prev1, t2=prev2, t3=prev3;
            #pragma unroll
            for (int w2 = 0; w2 < 8; w2++){
                t0 += part[w][w2][u];
                t1 += part[w][w2][32+u];
                t2 += part[w][w2][64+u];
                t3 += part[w][w2][96+u];
            }
            float iv = fsig(t0);
            float fv = fsig(t1);
            float gv = ftanh(t2);
            float ov = fsig(t3);
            c = fv*c + iv*gv;
            float h = ov*ftanh(c);
            hlast = h;
            if (ts < Sz-1)
                hsm[(ts+1) & 1][w][slice*32 + u] = h;   // LOCAL store only
            if (!stage){
                float* hsw = w ? hs1 : hs0;
                hsw[(long long)s*Hz + slice*32 + u] = h;
            }
            if (ts < Sz-1){
                __syncwarp(0xffffffffu);                 // warp stores visible
                if (u == 0){                             // t==0 and t==32 arrive
                    unsigned slotoff = (unsigned)(ts & 1)*8u;
                    #pragma unroll
                    for (int rb = 0; rb < 8; rb++){
                        asm volatile("mbarrier.arrive.shared::cluster.b64 _, [%0];"
                                     :: "r"(rmb[rb] + slotoff) : "memory");
                    }
                }
            }
        }
        // no second __syncthreads: next-step mbar wait (needs own-CTA cell
        // arrivals, which follow the part reads above) provides the ordering.
    }
    if (stage && t < 64){
        int w = t >> 5, u = t & 31;
        int b = bpair*2 + w;
        g_s[OFF_HT + (long long)(grp*2+dir)*Bz*Hz + (long long)b*Hz + slice*32 + u] = hlast;
    }
}

// fused: plain norm + 10 weighted norms per (arr, r)
__global__ void norms_all_kernel(const float* __restrict__ w3, const float* __restrict__ w4){
    int id = blockIdx.x;                 // 4*B*S
    int arr = id / (Bz*Sz), r = id % (Bz*Sz);
    const float* w = (arr & 1) ? w4 : w3;
    __shared__ float red[Lz+1][8];
    int tid = threadIdx.x, wp = tid >> 5, lane = tid & 31;
    float x = g_s[OFF_HS + (long long)arr*BSH + (long long)r*Hz + tid];
    float vv = x*x;
    float s0 = warp_sum(vv);
    if (lane == 0) red[Lz][wp] = s0;
    for (int l = 0; l < Lz; l++){
        float wv = __ldg(&w[l*Hz + tid]);
        float s = warp_sum(wv*wv*vv);
        if (lane == 0) red[l][wp] = s;
    }
    __syncthreads();
    if (tid < Lz){
        float s = 0.f;
        #pragma unroll
        for (int i = 0; i < 8; i++) s += red[tid][i];
        g_s[OFF_NLW + (long long)(arr*Bz*Sz + r)*Lz + tid] = sqrtf(s);
    }
    if (tid == Lz){
        float s = 0.f;
        #pragma unroll
        for (int i = 0; i < 8; i++) s += red[Lz][i];
        g_s[OFF_NRM + (long long)arr*Bz*Sz + r] = sqrtf(s);
    }
}

// cosine attention + fused row max/sum
__global__ void att_kernel(){
    int id = blockIdx.x;                 // 2*B*S
    int dir = id / (Bz*Sz), r = id % (Bz*Sz);
    int b = r / Sz;
    __shared__ float v1s[Hz];
    __shared__ float sbs[8], sbm[8];
    int tid = threadIdx.x, w = tid >> 5, lane = tid & 31;
    v1s[tid] = g_s[OFF_HS + (long long)dir*BSH + (long long)r*Hz + tid];
    __syncthreads();
    const float4* v2 = (const float4*)(g_s + OFF_HS + (long long)(2+dir)*BSH + (long long)(b*Sz + tid)*Hz);
    float acc = 0.f;
    #pragma unroll 8
    for (int h4 = 0; h4 < Hz/4; h4++){
        float4 o = v2[h4];
        acc = fmaf(v1s[4*h4+0], o.x, acc);
        acc = fmaf(v1s[4*h4+1], o.y, acc);
        acc = fmaf(v1s[4*h4+2], o.z, acc);
        acc = fmaf(v1s[4*h4+3], o.w, acc);
    }
    float n1 = g_s[OFF_NRM + (long long)dir*Bz*Sz + r];
    float n2 = g_s[OFF_NRM + (long long)(2+dir)*Bz*Sz + b*Sz + tid];
    float d = n1*n2;
    float a = acc / (d > EPSf ? d : EPSf);
    g_s[OFF_ATT + (long long)dir*BSS + (long long)r*Sz + tid] = a;
    float ssum = warp_sum(a);
    float smax = warp_max(a);
    if (lane == 0){ sbs[w] = ssum; sbm[w] = smax; }
    __syncthreads();
    if (tid == 0){
        float tots = 0.f, totm = -3.4e38f;
        #pragma unroll
        for (int i = 0; i < 8; i++){ tots += sbs[i]; totm = fmaxf(totm, sbm[i]); }
        g_s[OFF_ROWSUM + (long long)dir*Bz*Sz + r] = tots;
        if (dir == 0){
            float* mp = g_s + OFF_MVP + (long long)r*AGGz;
            mp[0] = totm;
            mp[1] = tots / (float)Sz;
        }
    }
}

// merged row/col attentive stats: gridDim.y = 2 (0 = row side, 1 = col side)
__global__ void stats_kernel(){
    int id = blockIdx.x;                 // 2*B*32
    int mode = blockIdx.y;
    int dir = id / (Bz*32); int rem = id % (Bz*32);
    int b = rem / 32, tt = rem % 32;
    __shared__ float atile[8][Sz];
    int tid = threadIdx.x;
    const float* att = g_s + OFF_ATT + (long long)dir*BSS + (long long)b*Sz*Sz;
    if (mode == 0){
        // rows pt*8..pt*8+7
        const float* arow = att + (long long)(tt*8)*Sz;
        for (int i = tid; i < 8*Sz; i += 256)
            atile[i >> 8][i & 255] = arow[(long long)(i >> 8)*Sz + (i & 255)];
    } else {
        // cols qt*8..qt*8+7: atile[j][p] = att[p][qt*8+j]
        for (int i = tid; i < 8*Sz; i += 256){
            int p = i >> 3, j = i & 7;
            atile[j][p] = att[(long long)p*Sz + tt*8 + j];
        }
    }
    __syncthreads();
    const float* v = g_s + OFF_HS + (long long)((mode ? dir : (2+dir)))*BSH + (long long)b*Sz*Hz;
    float sm[8], mx[8], cs[8], cm[8];
    #pragma unroll
    for (int j = 0; j < 8; j++){ sm[j] = 0.f; mx[j] = -3.4e38f; cs[j] = 0.f; cm[j] = -3.4e38f; }
    for (int p = 0; p < Sz; p++){
        float vv = v[(long long)p*Hz + tid];
        #pragma unroll
        for (int j = 0; j < 8; j++){
            float av = atile[j][p];
            cs[j] += av; cm[j] = fmaxf(cm[j], av);
            float pr = av*vv;
            sm[j] += pr; mx[j] = fmaxf(mx[j], pr);
        }
    }
    if (mode == 0){
        #pragma unroll
        for (int j = 0; j < 8; j++){
            int rr = b*Sz + tt*8 + j;
            float rs = g_s[OFF_ROWSUM + (long long)dir*Bz*Sz + rr];
            g_s[OFF_STATS + (long long)(0*2+dir)*BSH + (long long)rr*Hz + tid] = sm[j] / (rs > EPSf ? rs : EPSf);
            g_s[OFF_STATS + (long long)(1*2+dir)*BSH + (long long)rr*Hz + tid] = mx[j];
        }
    } else {
        #pragma unroll
        for (int j = 0; j < 8; j++){
            int rr = b*Sz + tt*8 + j;
            g_s[OFF_STATS + (long long)(2*2+dir)*BSH + (long long)rr*Hz + tid] = sm[j] / (cs[j] > EPSf ? cs[j] : EPSf);
            g_s[OFF_STATS + (long long)(3*2+dir)*BSH + (long long)rr*Hz + tid] = mx[j];
        }
        if (tid == 0 && dir == 0){
            #pragma unroll
            for (int j = 0; j < 8; j++){
                float* mh = g_s + OFF_MVH + (long long)(b*Sz + tt*8 + j)*AGGz;
                mh[0] = cm[j];
                mh[1] = cs[j] / (float)Sz;
            }
        }
    }
}

// pairwise matching, single pass: row-max -> mv_p; spill mm -> scratch for colmax
__global__ void __launch_bounds__(256) pairwise_kernel(const float* __restrict__ w3, const float* __restrict__ w4){
    int id = blockIdx.x;                 // 2*B*S
    int dir = id / (Bz*Sz), r = id % (Bz*Sz);
    int b = r / Sz, s = r % Sz;
    const float* w = dir ? w4 : w3;
    __shared__ float w2s[Lz*Hz];
    __shared__ float vrow[Hz];
    __shared__ float red[Lz][8];
    int tid = threadIdx.x, wp = tid >> 5, lane = tid & 31;
    for (int i = tid; i < Lz*Hz; i += 256){ float x = w[i]; w2s[i] = x*x; }
    vrow[tid] = g_s[OFF_HS + (long long)dir*BSH + (long long)r*Hz + tid];
    __syncthreads();
    const float4* other = (const float4*)(g_s + OFF_HS + (long long)(2+dir)*BSH + (long long)(b*Sz + tid)*Hz);
    float acc[Lz];
    #pragma unroll
    for (int l = 0; l < Lz; l++) acc[l] = 0.f;
    for (int h4 = 0; h4 < Hz/4; h4++){
        float4 o = other[h4];
        float p0 = vrow[4*h4+0]*o.x, p1 = vrow[4*h4+1]*o.y;
        float p2 = vrow[4*h4+2]*o.z, p3 = vrow[4*h4+3]*o.w;
        #pragma unroll
        for (int l = 0; l < Lz; l++){
            acc[l] = fmaf(w2s[l*Hz + 4*h4+0], p0, acc[l]);
            acc[l] = fmaf(w2s[l*Hz + 4*h4+1], p1, acc[l]);
            acc[l] = fmaf(w2s[l*Hz + 4*h4+2], p2, acc[l]);
            acc[l] = fmaf(w2s[l*Hz + 4*h4+3], p3, acc[l]);
        }
    }
    const float* nfix = g_s + OFF_NLW + (long long)((0*2+dir)*Bz*Sz + b*Sz + s)*Lz;
    const float* nstr = g_s + OFF_NLW + (long long)((1*2+dir)*Bz*Sz + b*Sz + tid)*Lz;
    float* mmS = g_s + OFF_MMS + (long long)((dir*Bz + b)*Lz)*Sz*Sz;
    #pragma unroll
    for (int l = 0; l < Lz; l++){
        float d = nfix[l]*nstr[l];
        float v = acc[l] / (d > EPSf ? d : EPSf);
        mmS[(long long)l*Sz*Sz + (long long)s*Sz + tid] = v;
        float m = warp_max(v);
        if (lane == 0) red[l][wp] = m;
    }
    __syncthreads();
    if (tid < Lz){
        float m = red[tid][0];
        #pragma unroll
        for (int i = 1; i < 8; i++) m = fmaxf(m, red[tid][i]);
        g_s[OFF_MVP + (long long)(b*Sz + s)*AGGz + 2 + dir*10 + tid] = m;
    }
}

// column max of mm over p -> mv_h.  grid 2*B*L, 256 threads (tid = q)
__global__ void colmax_kernel(){
    int id = blockIdx.x;
    int dir = id / (Bz*Lz); int rem = id % (Bz*Lz);
    int b = rem / Lz, l = rem % Lz;
    int q = threadIdx.x;
    const float* mmS = g_s + OFF_MMS + ((long long)((dir*Bz + b)*Lz) + l)*Sz*Sz;
    float m = -3.4e38f;
    for (int p = 0; p < Sz; p++) m = fmaxf(m, mmS[(long long)p*Sz + q]);
    g_s[OFF_MVH + (long long)(b*Sz + q)*AGGz + 2 + dir*10 + l] = m;
}

// attentive / max-attentive mp_match: 4 combos folded per block (grid 2*B*S)
__global__ void mpmatch_kernel(const float* __restrict__ w5, const float* __restrict__ w6,
                               const float* __restrict__ w7, const float* __restrict__ w8){
    int id = blockIdx.x;                 // 2*B*S
    int dir = id / (Bz*Sz), r = id % (Bz*Sz);
    int b = r / Sz, s = r % Sz;
    __shared__ float red[2][Lz][3][8];   // [side][l][num,n1,n2][warp]
    int tid = threadIdx.x, wp = tid >> 5, lane = tid & 31;
    long long rowOff = (long long)(b*Sz+s)*Hz + tid;
    float a0 = g_s[OFF_HS + (long long)dir*BSH + rowOff];        // side 0 (p-side)
    float a1 = g_s[OFF_HS + (long long)(2+dir)*BSH + rowOff];    // side 1 (h-side)
    #pragma unroll
    for (int kk = 0; kk < 2; kk++){
        int wsel = kk*2 + dir;
        const float* w = (wsel==0) ? w5 : (wsel==1) ? w6 : (wsel==2) ? w7 : w8;
        int kind0 = kk ? 1 : 0;
        int kind1 = kk ? 3 : 2;
        float bb0 = g_s[OFF_STATS + (long long)(kind0*2+dir)*BSH + rowOff];
        float bb1 = g_s[OFF_STATS + (long long)(kind1*2+dir)*BSH + rowOff];
        for (int l = 0; l < Lz; l++){
            float wv = __ldg(&w[l*Hz + tid]);
            float w2 = wv*wv;
            float n0 = warp_sum(w2*a0*bb0);
            float s0 = warp_sum(w2*a0*a0);
            float q0 = warp_sum(w2*bb0*bb0);
            float n1 = warp_sum(w2*a1*bb1);
            float s1 = warp_sum(w2*a1*a1);
            float q1 = warp_sum(w2*bb1*bb1);
            if (lane == 0){
                red[0][l][0][wp] = n0; red[0][l][1][wp] = s0; red[0][l][2][wp] = q0;
                red[1][l][0][wp] = n1; red[1][l][1][wp] = s1; red[1][l][2][wp] = q1;
            }
        }
        __syncthreads();
        if (tid < Lz){
            float N=0.f, A=0.f, B2=0.f;
            #pragma unroll
            for (int i = 0; i < 8; i++){ N += red[0][tid][0][i]; A += red[0][tid][1][i]; B2 += red[0][tid][2][i]; }
            g_s[OFF_MVP + (long long)(b*Sz + s)*AGGz + 22 + wsel*10 + tid]
                = N / fmaxf(sqrtf(A)*sqrtf(B2), EPSf);
        } else if (tid >= 32 && tid < 32 + Lz){
            int ll = tid - 32;
            float N=0.f, A=0.f, B2=0.f;
            #pragma unroll
            for (int i = 0; i < 8; i++){ N += red[1][ll][0][i]; A += red[1][ll][1][i]; B2 += red[1][ll][2][i]; }
            g_s[OFF_MVH + (long long)(b*Sz + s)*AGGz + 22 + wsel*10 + ll]
                = N / fmaxf(sqrtf(A)*sqrtf(B2), EPSf);
        }
        __syncthreads();   // red reused next kk
    }
}

__global__ void means_kernel(const float* __restrict__ left, const float* __restrict__ right){
    int which = blockIdx.x >> 2, b = blockIdx.x & 3;   // grid 8, 320 threads
    int d = threadIdx.x;
    if (d >= Dz) return;
    const float* x = which ? right : left;
    float s = 0.f;
    for (int t = 0; t < Sz; t++) s += x[((long long)b*Sz + t)*Dz + d];
    g_s[OFF_MEANS + (long long)which*Bz*Dz + (long long)b*Dz + d] = s / (float)Sz;
}

__global__ void fc1_kernel(const float* __restrict__ fc1_b){
    int b = blockIdx.x;                  // grid B, 512 threads
    int tid = threadIdx.x;
    __shared__ float feat[FEATN + 6];
    for (int i = tid; i < FEATN; i += 512){
        float v;
        if (i < 1024)       v = g_s[OFF_HT + (long long)(i >> 8)*Bz*Hz + (long long)b*Hz + (i & 255)];
        else if (i < 1026)  v = 0.5f;
        else if (i < 1326)  v = g_s[OFF_MEANS + (long long)b*Dz + (i - 1026)];
        else                v = g_s[OFF_MEANS + (long long)Bz*Dz + (long long)b*Dz + (i - 1326)];
        feat[i] = v;
    }
    __syncthreads();
    float acc = fc1_b[tid];
    for (int k = 0; k < FEATN; k++)
        acc = fmaf(feat[k], g_s[OFF_FC1WT + (long long)k*512 + tid], acc);
    g_s[OFF_FC1O + (long long)b*512 + tid] = tanhf(acc);
}

__global__ void fc2_kernel(const float* __restrict__ W2, const float* __restrict__ b2,
                           float* __restrict__ out){
    int b = blockIdx.x;                  // grid B, 512 threads
    int tid = threadIdx.x;
    __shared__ float y[512];
    y[tid] = g_s[OFF_FC1O + (long long)b*512 + tid];
    __syncthreads();
    if (tid < NCLSz){
        float acc = b2[tid];
        for (int o = 0; o < 512; o++) acc = fmaf(y[o], W2[(long long)tid*512 + o], acc);
        out[b*NCLSz + tid] = acc;
    }
}

extern "C" void kernel_launch(void* const* d_in, const int* in_sizes, int n_in,
                              void* d_out, int out_size){
    const float* left      = (const float*)d_in[0];
    const float* right     = (const float*)d_in[1];
    const float* ctx_Wih_f = (const float*)d_in[2];
    const float* ctx_Whh_f = (const float*)d_in[3];
    const float* ctx_b_f   = (const float*)d_in[4];
    const float* ctx_Wih_b = (const float*)d_in[5];
    const float* ctx_Whh_b = (const float*)d_in[6];
    const float* ctx_b_b   = (const float*)d_in[7];
    const float* agg_Wih_f = (const float*)d_in[8];
    const float* agg_Whh_f = (const float*)d_in[9];
    const float* agg_b_f   = (const float*)d_in[10];
    const float* agg_Wih_b = (const float*)d_in[11];
    const float* agg_Whh_b = (const float*)d_in[12];
    const float* agg_b_b   = (const float*)d_in[13];
    const float* mp_w3     = (const float*)d_in[14];
    const float* mp_w4     = (const float*)d_in[15];
    const float* mp_w5     = (const float*)d_in[16];
    const float* mp_w6     = (const float*)d_in[17];
    const float* mp_w7     = (const float*)d_in[18];
    const float* mp_w8     = (const float*)d_in[19];
    const float* fc1_W     = (const float*)d_in[20];
    const float* fc1_b     = (const float*)d_in[21];
    const float* fc2_W     = (const float*)d_in[22];
    const float* fc2_b     = (const float*)d_in[23];
    float* out = (float*)d_out;

    // weight transposes: 2 launches (lstm7 stays launch #4 for ncu)
    transpose2_kernel<<<dim3(128,1,2),256>>>(ctx_Wih_f, ctx_Wih_b, OFF_WIHT_CF, OFF_WIHT_CB, H4z, Dz);
    transpose3_kernel<<<dim3(128,1,3),256>>>(agg_Wih_f, agg_Wih_b, fc1_W,
        OFF_WIHT_AF, OFF_WIHT_AB, OFF_FC1WT, H4z, AGGz, 512, FEATN);

    // ctx pre-activation GEMMs, batched over z (left f/b, right f/b)
    gemm4_kernel<<<dim3(16,16,4),256>>>(left, right, 0, 0,
        OFF_WIHT_CF, (long long)Dz*H4z, ctx_b_f, ctx_b_b,
        OFF_PRE_CTX, Bz*Sz, H4z, Dz);

    lstm7_kernel<<<64,256>>>(0, ctx_Whh_f, ctx_Whh_b);

    norms_all_kernel<<<4*Bz*Sz,256>>>(mp_w3, mp_w4);
    att_kernel<<<2*Bz*Sz,256>>>();
    stats_kernel<<<dim3(2*Bz*32,2),256>>>();
    pairwise_kernel<<<2*Bz*Sz,256>>>(mp_w3, mp_w4);
    colmax_kernel<<<2*Bz*Lz,256>>>();
    mpmatch_kernel<<<2*Bz*Sz,256>>>(mp_w5, mp_w6, mp_w7, mp_w8);
    means_kernel<<<8,320>>>(left, right);

    // agg pre-activation GEMMs, batched over z (mv_p f/b, mv_h f/b)
    gemm4_kernel<<<dim3(16,16,4),256>>>(nullptr, nullptr, OFF_MVP, OFF_MVH,
        OFF_WIHT_AF, (long long)AGGz*H4z, agg_b_f, agg_b_b,
        OFF_PRE_AGG, Bz*Sz, H4z, AGGz);

    lstm7_kernel<<<64,256>>>(1, agg_Whh_f, agg_Whh_b);

    fc1_kernel<<<Bz,512>>>(fc1_b);
    fc2_kernel<<<Bz,512>>>(fc2_W, fc2_b, out);
}

// round 16
// speedup vs baseline: 1.5606x; 1.0693x over previous
#include <cuda_runtime.h>
#include <math.h>

// ---------------- problem constants ----------------
#define Bz   4
#define Sz   256
#define Dz   300
#define Hz   256
#define H4z  1024
#define Lz   10
#define AGGz 62
#define NCLSz 22
#define FEATN 1626          // 4*H + 2 + 2*D
#define BSH  (Bz*Sz*Hz)     // 262144
#define BSS  (Bz*Sz*Sz)     // 262144
#define EPSf 1e-8f

// ---------------- scratch layout (floats) ----------------
constexpr long long OFF_WIHT_CF = 0;
constexpr long long OFF_WIHT_CB = OFF_WIHT_CF + (long long)Dz*H4z;
constexpr long long OFF_WIHT_AF = OFF_WIHT_CB + (long long)Dz*H4z;
constexpr long long OFF_WIHT_AB = OFF_WIHT_AF + (long long)AGGz*H4z;
constexpr long long OFF_FC1WT   = OFF_WIHT_AB + (long long)AGGz*H4z;
constexpr long long OFF_PRE_CTX = OFF_FC1WT + (long long)FEATN*512;
constexpr long long OFF_HS      = OFF_PRE_CTX + 4LL*Bz*Sz*H4z;   // p_fw,p_bw,h_fw,h_bw
constexpr long long OFF_NRM     = OFF_HS + 4LL*BSH;              // (4,B,S)
constexpr long long OFF_ATT     = OFF_NRM + 4LL*Bz*Sz;           // (2,B,S,S)
constexpr long long OFF_ROWSUM  = OFF_ATT + 2LL*BSS;             // (2,B,S)
constexpr long long OFF_COLSUM  = OFF_ROWSUM + 2LL*Bz*Sz;        // (2,B,S) [unused]
constexpr long long OFF_STATS   = OFF_COLSUM + 2LL*Bz*Sz;        // (4 kinds x 2 dirs, B,S,H)
constexpr long long OFF_NLW     = OFF_STATS + 8LL*BSH;           // (arr, B,S,L)
constexpr long long OFF_MVP     = OFF_NLW + 4LL*Bz*Sz*Lz;        // (B,S,62)
constexpr long long OFF_MVH     = OFF_MVP + (long long)Bz*Sz*AGGz;
constexpr long long OFF_PRE_AGG = OFF_MVH + (long long)Bz*Sz*AGGz;
constexpr long long OFF_HT      = OFF_PRE_AGG + 4LL*Bz*Sz*H4z;   // (4,B,H)
constexpr long long OFF_MEANS   = OFF_HT + 4LL*Bz*Hz;            // (2,B,D)
constexpr long long OFF_FC1O    = OFF_MEANS + 2LL*Bz*Dz;         // (B,512)
constexpr long long OFF_MMS     = OFF_FC1O + (long long)Bz*512;  // (2,B,L,P,Q) mm spill
constexpr long long SCRATCH_N   = OFF_MMS + 2LL*Bz*Lz*Sz*Sz + 64;

__device__ __align__(256) float g_s[SCRATCH_N];

__device__ __forceinline__ float warp_sum(float v){
    #pragma unroll
    for (int o = 16; o > 0; o >>= 1) v += __shfl_down_sync(0xffffffffu, v, o);
    return v;
}
__device__ __forceinline__ float warp_max(float v){
    #pragma unroll
    for (int o = 16; o > 0; o >>= 1) v = fmaxf(v, __shfl_down_sync(0xffffffffu, v, o));
    return v;
}
__device__ __forceinline__ unsigned smem_u32(const void* p){
    unsigned r;
    asm("{ .reg .u64 t; cvta.to.shared.u64 t, %1; cvt.u32.u64 %0, t; }" : "=r"(r) : "l"(p));
    return r;
}
// fast, inf-safe sigmoid / tanh via MUFU-based __expf (~1e-7 rel err)
__device__ __forceinline__ float fsig(float x){ return __fdividef(1.f, 1.f + __expf(-x)); }
__device__ __forceinline__ float ftanh(float x){ return 1.f - __fdividef(2.f, 1.f + __expf(2.f*x)); }

__device__ __forceinline__ unsigned long long pk2(float a, float b){
    unsigned long long r;
    asm("mov.b64 %0, {%1, %2};" : "=l"(r) : "f"(a), "f"(b));
    return r;
}
__device__ __forceinline__ void upk2(float& lo, float& hi, unsigned long long v){
    asm("mov.b64 {%0, %1}, %2;" : "=f"(lo), "=f"(hi) : "l"(v));
}
__device__ __forceinline__ unsigned long long ffma2(unsigned long long a,
        unsigned long long b, unsigned long long c){
    unsigned long long d;
    asm("fma.rn.f32x2 %0, %1, %2, %3;" : "=l"(d) : "l"(a), "l"(b), "l"(c));
    return d;
}
__device__ __forceinline__ float4 ldsm_cluster4(unsigned addr){
    float4 v;
    asm volatile("ld.shared::cluster.v4.f32 {%0,%1,%2,%3}, [%4];"
        : "=f"(v.x), "=f"(v.y), "=f"(v.z), "=f"(v.w) : "r"(addr) : "memory");
    return v;
}

// two transposes in one launch
__global__ void transpose2_kernel(const float* __restrict__ s0, const float* __restrict__ s1,
                                  long long d0, long long d1, int R, int C){
    const float* src = blockIdx.z ? s1 : s0;
    long long dst = blockIdx.z ? d1 : d0;
    long long total = (long long)R*C;
    for (long long i = blockIdx.x*(long long)blockDim.x + threadIdx.x; i < total;
         i += (long long)gridDim.x*blockDim.x){
        int r = (int)(i / C), c = (int)(i % C);
        g_s[dst + (long long)c*R + r] = src[i];
    }
}

// three transposes in one launch (agg_f, agg_b, fc1)
__global__ void transpose3_kernel(const float* __restrict__ s0, const float* __restrict__ s1,
                                  const float* __restrict__ s2,
                                  long long d0, long long d1, long long d2,
                                  int R01, int C01, int R2, int C2){
    int z = blockIdx.z;
    const float* src = (z==0) ? s0 : (z==1) ? s1 : s2;
    long long dst = (z==0) ? d0 : (z==1) ? d1 : d2;
    int R = (z<2) ? R01 : R2, C = (z<2) ? C01 : C2;
    long long total = (long long)R*C;
    for (long long i = blockIdx.x*(long long)blockDim.x + threadIdx.x; i < total;
         i += (long long)gridDim.x*blockDim.x){
        int r = (int)(i / C), c = (int)(i % C);
        g_s[dst + (long long)c*R + r] = src[i];
    }
}

// Batched GEMM over z=0..3 with register double-buffered tile loads.
__global__ void __launch_bounds__(256) gemm4_kernel(
        const float* __restrict__ A0, const float* __restrict__ A1,
        long long a0_off, long long a1_off,
        long long bt_base, long long bt_stride,
        const float* __restrict__ biasF, const float* __restrict__ biasB,
        long long c_off, int M, int N, int K){
    int z = blockIdx.z;
    const float* A  = (z < 2) ? (A0 ? A0 : (g_s + a0_off)) : (A1 ? A1 : (g_s + a1_off));
    const float* Bt = g_s + bt_base + (long long)(z & 1)*bt_stride;
    const float* bias = (z & 1) ? biasB : biasF;
    float* C = g_s + c_off + (long long)z*M*N;
    __shared__ float As[16][68];
    __shared__ float Bs[16][68];
    int bm = blockIdx.y*64, bn = blockIdx.x*64;
    int tid = threadIdx.x;
    int tr = tid >> 4, tc = tid & 15;
    float acc[4][4] = {};
    float ra[4], rb[4];

    #pragma unroll
    for (int ii = 0; ii < 4; ii++){
        int i = tid + ii*256;
        int m = i >> 4, k = i & 15;
        ra[ii] = (k < K) ? A[(long long)(bm+m)*K + k] : 0.f;
    }
    #pragma unroll
    for (int ii = 0; ii < 4; ii++){
        int i = tid + ii*256;
        int k = i >> 6, n = i & 63;
        rb[ii] = (k < K) ? Bt[(long long)k*N + bn + n] : 0.f;
    }

    for (int k0 = 0; k0 < K; k0 += 16){
        #pragma unroll
        for (int ii = 0; ii < 4; ii++){
            int i = tid + ii*256;
            As[i & 15][i >> 4] = ra[ii];
        }
        #pragma unroll
        for (int ii = 0; ii < 4; ii++){
            int i = tid + ii*256;
            Bs[i >> 6][i & 63] = rb[ii];
        }
        __syncthreads();
        int kn = k0 + 16;
        if (kn < K){
            #pragma unroll
            for (int ii = 0; ii < 4; ii++){
                int i = tid + ii*256;
                int m = i >> 4, k = i & 15;
                ra[ii] = (kn+k < K) ? A[(long long)(bm+m)*K + kn + k] : 0.f;
            }
            #pragma unroll
            for (int ii = 0; ii < 4; ii++){
                int i = tid + ii*256;
                int k = i >> 6, n = i & 63;
                rb[ii] = (kn+k < K) ? Bt[(long long)(kn+k)*N + bn + n] : 0.f;
            }
        }
        #pragma unroll
        for (int k = 0; k < 16; k++){
            float4 av = *(const float4*)&As[k][tr*4];
            float4 bv = *(const float4*)&Bs[k][tc*4];
            float a[4] = {av.x, av.y, av.z, av.w};
            float bb[4] = {bv.x, bv.y, bv.z, bv.w};
            #pragma unroll
            for (int i = 0; i < 4; i++)
                #pragma unroll
                for (int j = 0; j < 4; j++) acc[i][j] = fmaf(a[i], bb[j], acc[i][j]);
        }
        __syncthreads();
    }
    #pragma unroll
    for (int i = 0; i < 4; i++){
        int m = bm + tr*4 + i;
        #pragma unroll
        for (int j = 0; j < 4; j++){
            int n = bn + tc*4 + j;
            C[(long long)m*N + n] = acc[i][j] + bias[n];
        }
    }
}

// Cluster LSTM v7: pull protocol; single __syncthreads per step.
__global__ void __cluster_dims__(8,1,1) __launch_bounds__(256,1) lstm7_kernel(int stage,
        const float* __restrict__ Whh_f, const float* __restrict__ Whh_b){
    int slice;
    asm("mov.u32 %0, %%cluster_ctarank;" : "=r"(slice));
    int cid = blockIdx.x >> 3;           // 0..7
    int grpdir = cid >> 1;               // 0..3
    int bpair  = cid & 1;                // batches {2*bpair, 2*bpair+1}
    int grp = grpdir >> 1, dir = grpdir & 1;
    long long chunk0 = (long long)(grp*2 + dir)*Bz + (bpair*2 + 0);
    long long chunk1 = (long long)(grp*2 + dir)*Bz + (bpair*2 + 1);
    long long preBase = stage ? OFF_PRE_AGG : OFF_PRE_CTX;
    const float* pre0 = g_s + preBase + chunk0*(long long)Sz*H4z;
    const float* pre1 = g_s + preBase + chunk1*(long long)Sz*H4z;
    const float* Whh = dir ? Whh_b : Whh_f;
    float* hs0 = g_s + OFF_HS + chunk0*(long long)Sz*Hz;
    float* hs1 = g_s + OFF_HS + chunk1*(long long)Sz*Hz;

    int t = threadIdx.x;
    int kw = t >> 5, l = t & 31;

    unsigned long long wrp[4][16];
    #pragma unroll
    for (int j = 0; j < 4; j++){
        int rho = 4*l + j;
        int G = (rho >> 5)*Hz + slice*32 + (rho & 31);
        const float4* row = (const float4*)(Whh + (long long)G*Hz) + kw*8;
        #pragma unroll
        for (int k4 = 0; k4 < 8; k4++){
            float4 v = row[k4];
            wrp[j][2*k4+0] = pk2(v.x, v.y);
            wrp[j][2*k4+1] = pk2(v.z, v.w);
        }
    }

    __shared__ float hsm[2][2][Hz];
    __shared__ float part[2][8][128];
    __shared__ __align__(8) unsigned long long mbarS[2];

    hsm[0][0][t] = 0.f;
    hsm[0][1][t] = 0.f;
    if (t == 0){
        unsigned mb0 = smem_u32(&mbarS[0]);
        asm volatile("mbarrier.init.shared.b64 [%0], 16;" :: "r"(mb0) : "memory");
        asm volatile("mbarrier.init.shared.b64 [%0], 16;" :: "r"(mb0 + 8) : "memory");
    }
    unsigned rbase[8], rmb[8];
    {
        unsigned lbase = smem_u32(&hsm[0][0][0]);
        unsigned lmb   = smem_u32(&mbarS[0]);
        #pragma unroll
        for (int rb = 0; rb < 8; rb++){
            asm("mapa.shared::cluster.u32 %0, %1, %2;" : "=r"(rbase[rb]) : "r"(lbase), "r"(rb));
            asm("mapa.shared::cluster.u32 %0, %1, %2;" : "=r"(rmb[rb])   : "r"(lmb),   "r"(rb));
        }
    }
    unsigned rh0base = rbase[kw] + (unsigned)(kw*32)*4u;
    float c = 0.f, hlast = 0.f;
    __syncthreads();
    asm volatile("barrier.cluster.arrive.aligned;" ::: "memory");
    asm volatile("barrier.cluster.wait.aligned;" ::: "memory");

    unsigned lmb0 = smem_u32(&mbarS[0]);

    for (int ts = 0; ts < Sz; ts++){
        int s = dir ? (Sz-1-ts) : ts;
        float prev0=0.f, prev1=0.f, prev2=0.f, prev3=0.f;
        if (t < 64){
            const float* prew = (t & 32) ? pre1 : pre0;
            long long base = (long long)s*H4z + slice*32 + (t & 31);
            prev0 = __ldg(&prew[base + 0*Hz]);
            prev1 = __ldg(&prew[base + 1*Hz]);
            prev2 = __ldg(&prew[base + 2*Hz]);
            prev3 = __ldg(&prew[base + 3*Hz]);
        }
        if (ts > 0){
            unsigned mb = lmb0 + ((ts-1) & 1)*8u;
            unsigned par = ((unsigned)(ts-1) >> 1) & 1u;
            unsigned done = 0;
            while (!done){
                asm volatile(
                    "{\n\t.reg .pred p;\n\t"
                    "mbarrier.try_wait.parity.acquire.cluster.shared::cta.b64 p, [%1], %2, 0x989680;\n\t"
                    "selp.b32 %0, 1, 0, p;\n\t}"
                    : "=r"(done) : "r"(mb), "r"(par) : "memory");
            }
        }
        int buf = ts & 1;
        unsigned a0 = rh0base + (unsigned)((buf*2 + 0)*Hz)*4u;
        unsigned a1 = rh0base + (unsigned)((buf*2 + 1)*Hz)*4u;
        float4 hv0[8], hv1[8];
        #pragma unroll
        for (int k4 = 0; k4 < 8; k4++) hv0[k4] = ldsm_cluster4(a0 + (unsigned)k4*16u);
        #pragma unroll
        for (int k4 = 0; k4 < 8; k4++) hv1[k4] = ldsm_cluster4(a1 + (unsigned)k4*16u);

        unsigned long long a00=0, a01=0, a02=0, a03=0;
        unsigned long long a10=0, a11=0, a12=0, a13=0;
        #pragma unroll
        for (int k4 = 0; k4 < 8; k4++){
            float4 v0 = hv0[k4];
            float4 v1 = hv1[k4];
            unsigned long long h0a = pk2(v0.x, v0.y), h0b = pk2(v0.z, v0.w);
            unsigned long long h1a = pk2(v1.x, v1.y), h1b = pk2(v1.z, v1.w);
            a00 = ffma2(wrp[0][2*k4+0], h0a, a00);
            a01 = ffma2(wrp[1][2*k4+0], h0a, a01);
            a02 = ffma2(wrp[2][2*k4+0], h0a, a02);
            a03 = ffma2(wrp[3][2*k4+0], h0a, a03);
            a10 = ffma2(wrp[0][2*k4+0], h1a, a10);
            a11 = ffma2(wrp[1][2*k4+0], h1a, a11);
            a12 = ffma2(wrp[2][2*k4+0], h1a, a12);
            a13 = ffma2(wrp[3][2*k4+0], h1a, a13);
            a00 = ffma2(wrp[0][2*k4+1], h0b, a00);
            a01 = ffma2(wrp[1][2*k4+1], h0b, a01);
            a02 = ffma2(wrp[2][2*k4+1], h0b, a02);
            a03 = ffma2(wrp[3][2*k4+1], h0b, a03);
            a10 = ffma2(wrp[0][2*k4+1], h1b, a10);
            a11 = ffma2(wrp[1][2*k4+1], h1b, a11);
            a12 = ffma2(wrp[2][2*k4+1], h1b, a12);
            a13 = ffma2(wrp[3][2*k4+1], h1b, a13);
        }
        float lo, hi;
        upk2(lo, hi, a00); part[0][kw][4*l+0] = lo + hi;
        upk2(lo, hi, a01); part[0][kw][4*l+1] = lo + hi;
        upk2(lo, hi, a02); part[0][kw][4*l+2] = lo + hi;
        upk2(lo, hi, a03); part[0][kw][4*l+3] = lo + hi;
        upk2(lo, hi, a10); part[1][kw][4*l+0] = lo + hi;
        upk2(lo, hi, a11); part[1][kw][4*l+1] = lo + hi;
        upk2(lo, hi, a12); part[1][kw][4*l+2] = lo + hi;
        upk2(lo, hi, a13); part[1][kw][4*l+3] = lo + hi;
        __syncthreads();
        if (t < 64){
            int w = t >> 5, u = t & 31;
            float t0=prev0, t1=prev1, t2=prev2, t3=prev3;
            #pragma unroll
            for (int w2 = 0; w2 < 8; w2++){
                t0 += part[w][w2][u];
                t1 += part[w][w2][32+u];
                t2 += part[w][w2][64+u];
                t3 += part[w][w2][96+u];
            }
            float iv = fsig(t0);
            float fv = fsig(t1);
            float gv = ftanh(t2);
            float ov = fsig(t3);
            c = fv*c + iv*gv;
            float h = ov*ftanh(c);
            hlast = h;
            if (ts < Sz-1)
                hsm[(ts+1) & 1][w][slice*32 + u] = h;
            if (!stage){
                float* hsw = w ? hs1 : hs0;
                hsw[(long long)s*Hz + slice*32 + u] = h;
            }
            if (ts < Sz-1){
                __syncwarp(0xffffffffu);
                if (u == 0){
                    unsigned slotoff = (unsigned)(ts & 1)*8u;
                    #pragma unroll
                    for (int rb = 0; rb < 8; rb++){
                        asm volatile("mbarrier.arrive.shared::cluster.b64 _, [%0];"
                                     :: "r"(rmb[rb] + slotoff) : "memory");
                    }
                }
            }
        }
    }
    if (stage && t < 64){
        int w = t >> 5, u = t & 31;
        int b = bpair*2 + w;
        g_s[OFF_HT + (long long)(grp*2+dir)*Bz*Hz + (long long)b*Hz + slice*32 + u] = hlast;
    }
}

// fused: plain norm + 10 weighted norms per (arr, r)
__global__ void norms_all_kernel(const float* __restrict__ w3, const float* __restrict__ w4){
    int id = blockIdx.x;                 // 4*B*S
    int arr = id / (Bz*Sz), r = id % (Bz*Sz);
    const float* w = (arr & 1) ? w4 : w3;
    __shared__ float red[Lz+1][8];
    int tid = threadIdx.x, wp = tid >> 5, lane = tid & 31;
    float x = g_s[OFF_HS + (long long)arr*BSH + (long long)r*Hz + tid];
    float vv = x*x;
    float s0 = warp_sum(vv);
    if (lane == 0) red[Lz][wp] = s0;
    for (int l = 0; l < Lz; l++){
        float wv = __ldg(&w[l*Hz + tid]);
        float s = warp_sum(wv*wv*vv);
        if (lane == 0) red[l][wp] = s;
    }
    __syncthreads();
    if (tid < Lz){
        float s = 0.f;
        #pragma unroll
        for (int i = 0; i < 8; i++) s += red[tid][i];
        g_s[OFF_NLW + (long long)(arr*Bz*Sz + r)*Lz + tid] = sqrtf(s);
    }
    if (tid == Lz){
        float s = 0.f;
        #pragma unroll
        for (int i = 0; i < 8; i++) s += red[Lz][i];
        g_s[OFF_NRM + (long long)arr*Bz*Sz + r] = sqrtf(s);
    }
}

// merged row/col attentive stats: gridDim.y = 2 (0 = row side, 1 = col side)
__global__ void stats_kernel(){
    int id = blockIdx.x;                 // 2*B*32
    int mode = blockIdx.y;
    int dir = id / (Bz*32); int rem = id % (Bz*32);
    int b = rem / 32, tt = rem % 32;
    __shared__ float atile[8][Sz];
    int tid = threadIdx.x;
    const float* att = g_s + OFF_ATT + (long long)dir*BSS + (long long)b*Sz*Sz;
    if (mode == 0){
        const float* arow = att + (long long)(tt*8)*Sz;
        for (int i = tid; i < 8*Sz; i += 256)
            atile[i >> 8][i & 255] = arow[(long long)(i >> 8)*Sz + (i & 255)];
    } else {
        for (int i = tid; i < 8*Sz; i += 256){
            int p = i >> 3, j = i & 7;
            atile[j][p] = att[(long long)p*Sz + tt*8 + j];
        }
    }
    __syncthreads();
    const float* v = g_s + OFF_HS + (long long)((mode ? dir : (2+dir)))*BSH + (long long)b*Sz*Hz;
    float sm[8], mx[8], cs[8], cm[8];
    #pragma unroll
    for (int j = 0; j < 8; j++){ sm[j] = 0.f; mx[j] = -3.4e38f; cs[j] = 0.f; cm[j] = -3.4e38f; }
    for (int p = 0; p < Sz; p++){
        float vv = v[(long long)p*Hz + tid];
        #pragma unroll
        for (int j = 0; j < 8; j++){
            float av = atile[j][p];
            cs[j] += av; cm[j] = fmaxf(cm[j], av);
            float pr = av*vv;
            sm[j] += pr; mx[j] = fmaxf(mx[j], pr);
        }
    }
    if (mode == 0){
        #pragma unroll
        for (int j = 0; j < 8; j++){
            int rr = b*Sz + tt*8 + j;
            float rs = g_s[OFF_ROWSUM + (long long)dir*Bz*Sz + rr];
            g_s[OFF_STATS + (long long)(0*2+dir)*BSH + (long long)rr*Hz + tid] = sm[j] / (rs > EPSf ? rs : EPSf);
            g_s[OFF_STATS + (long long)(1*2+dir)*BSH + (long long)rr*Hz + tid] = mx[j];
        }
    } else {
        #pragma unroll
        for (int j = 0; j < 8; j++){
            int rr = b*Sz + tt*8 + j;
            g_s[OFF_STATS + (long long)(2*2+dir)*BSH + (long long)rr*Hz + tid] = sm[j] / (cs[j] > EPSf ? cs[j] : EPSf);
            g_s[OFF_STATS + (long long)(3*2+dir)*BSH + (long long)rr*Hz + tid] = mx[j];
        }
        if (tid == 0 && dir == 0){
            #pragma unroll
            for (int j = 0; j < 8; j++){
                float* mh = g_s + OFF_MVH + (long long)(b*Sz + tt*8 + j)*AGGz;
                mh[0] = cm[j];
                mh[1] = cs[j] / (float)Sz;
            }
        }
    }
}

// FUSED cosine-attention + pairwise matching (att is the 11th, unweighted,
// perspective). Writes att matrix + rowsum + mv_p[0..1] + mv_p[2+dir*10+l]
// + mm spill for colmax. Grid 2*B*S.
__global__ void __launch_bounds__(256) attpair_kernel(const float* __restrict__ w3, const float* __restrict__ w4){
    int id = blockIdx.x;                 // 2*B*S
    int dir = id / (Bz*Sz), r = id % (Bz*Sz);
    int b = r / Sz, s = r % Sz;
    const float* w = dir ? w4 : w3;
    __shared__ float w2s[Lz*Hz];
    __shared__ float vrow[Hz];
    __shared__ float red[Lz+2][8];       // Lz maxes + att sum + att max
    int tid = threadIdx.x, wp = tid >> 5, lane = tid & 31;
    for (int i = tid; i < Lz*Hz; i += 256){ float x = w[i]; w2s[i] = x*x; }
    vrow[tid] = g_s[OFF_HS + (long long)dir*BSH + (long long)r*Hz + tid];
    __syncthreads();
    const float4* other = (const float4*)(g_s + OFF_HS + (long long)(2+dir)*BSH + (long long)(b*Sz + tid)*Hz);
    float acc[Lz];
    float accA = 0.f;                    // unweighted dot (cosine numerator)
    #pragma unroll
    for (int l = 0; l < Lz; l++) acc[l] = 0.f;
    for (int h4 = 0; h4 < Hz/4; h4++){
        float4 o = other[h4];
        float p0 = vrow[4*h4+0]*o.x, p1 = vrow[4*h4+1]*o.y;
        float p2 = vrow[4*h4+2]*o.z, p3 = vrow[4*h4+3]*o.w;
        accA += p0 + p1 + p2 + p3;
        #pragma unroll
        for (int l = 0; l < Lz; l++){
            acc[l] = fmaf(w2s[l*Hz + 4*h4+0], p0, acc[l]);
            acc[l] = fmaf(w2s[l*Hz + 4*h4+1], p1, acc[l]);
            acc[l] = fmaf(w2s[l*Hz + 4*h4+2], p2, acc[l]);
            acc[l] = fmaf(w2s[l*Hz + 4*h4+3], p3, acc[l]);
        }
    }
    // cosine attention value for (r, q=tid)
    float n1 = g_s[OFF_NRM + (long long)dir*Bz*Sz + r];
    float n2 = g_s[OFF_NRM + (long long)(2+dir)*Bz*Sz + b*Sz + tid];
    float dA = n1*n2;
    float aV = accA / (dA > EPSf ? dA : EPSf);
    g_s[OFF_ATT + (long long)dir*BSS + (long long)r*Sz + tid] = aV;
    {
        float ss = warp_sum(aV);
        float smx = warp_max(aV);
        if (lane == 0){ red[Lz][wp] = ss; red[Lz+1][wp] = smx; }
    }
    const float* nfix = g_s + OFF_NLW + (long long)((0*2+dir)*Bz*Sz + b*Sz + s)*Lz;
    const float* nstr = g_s + OFF_NLW + (long long)((1*2+dir)*Bz*Sz + b*Sz + tid)*Lz;
    float* mmS = g_s + OFF_MMS + (long long)((dir*Bz + b)*Lz)*Sz*Sz;
    #pragma unroll
    for (int l = 0; l < Lz; l++){
        float d = nfix[l]*nstr[l];
        float v = acc[l] / (d > EPSf ? d : EPSf);
        mmS[(long long)l*Sz*Sz + (long long)s*Sz + tid] = v;
        float m = warp_max(v);
        if (lane == 0) red[l][wp] = m;
    }
    __syncthreads();
    if (tid < Lz){
        float m = red[tid][0];
        #pragma unroll
        for (int i = 1; i < 8; i++) m = fmaxf(m, red[tid][i]);
        g_s[OFF_MVP + (long long)(b*Sz + s)*AGGz + 2 + dir*10 + tid] = m;
    } else if (tid == Lz){
        float tots = 0.f;
        #pragma unroll
        for (int i = 0; i < 8; i++) tots += red[Lz][i];
        g_s[OFF_ROWSUM + (long long)dir*Bz*Sz + r] = tots;
        if (dir == 0) g_s[OFF_MVP + (long long)r*AGGz + 1] = tots / (float)Sz;
    } else if (tid == Lz+1 && dir == 0){
        float totm = -3.4e38f;
        #pragma unroll
        for (int i = 0; i < 8; i++) totm = fmaxf(totm, red[Lz+1][i]);
        g_s[OFF_MVP + (long long)r*AGGz + 0] = totm;
    }
}

// column max of mm over p -> mv_h.  grid 2*B*L, 256 threads (tid = q)
__global__ void colmax_kernel(){
    int id = blockIdx.x;
    int dir = id / (Bz*Lz); int rem = id % (Bz*Lz);
    int b = rem / Lz, l = rem % Lz;
    int q = threadIdx.x;
    const float* mmS = g_s + OFF_MMS + ((long long)((dir*Bz + b)*Lz) + l)*Sz*Sz;
    float m = -3.4e38f;
    for (int p = 0; p < Sz; p++) m = fmaxf(m, mmS[(long long)p*Sz + q]);
    g_s[OFF_MVH + (long long)(b*Sz + q)*AGGz + 2 + dir*10 + l] = m;
}

// attentive / max-attentive mp_match: 4 combos folded per block (grid 2*B*S)
__global__ void mpmatch_kernel(const float* __restrict__ w5, const float* __restrict__ w6,
                               const float* __restrict__ w7, const float* __restrict__ w8){
    int id = blockIdx.x;                 // 2*B*S
    int dir = id / (Bz*Sz), r = id % (Bz*Sz);
    int b = r / Sz, s = r % Sz;
    __shared__ float red[2][Lz][3][8];   // [side][l][num,n1,n2][warp]
    int tid = threadIdx.x, wp = tid >> 5, lane = tid & 31;
    long long rowOff = (long long)(b*Sz+s)*Hz + tid;
    float a0 = g_s[OFF_HS + (long long)dir*BSH + rowOff];        // side 0 (p-side)
    float a1 = g_s[OFF_HS + (long long)(2+dir)*BSH + rowOff];    // side 1 (h-side)
    #pragma unroll
    for (int kk = 0; kk < 2; kk++){
        int wsel = kk*2 + dir;
        const float* w = (wsel==0) ? w5 : (wsel==1) ? w6 : (wsel==2) ? w7 : w8;
        int kind0 = kk ? 1 : 0;
        int kind1 = kk ? 3 : 2;
        float bb0 = g_s[OFF_STATS + (long long)(kind0*2+dir)*BSH + rowOff];
        float bb1 = g_s[OFF_STATS + (long long)(kind1*2+dir)*BSH + rowOff];
        for (int l = 0; l < Lz; l++){
            float wv = __ldg(&w[l*Hz + tid]);
            float w2 = wv*wv;
            float n0 = warp_sum(w2*a0*bb0);
            float s0 = warp_sum(w2*a0*a0);
            float q0 = warp_sum(w2*bb0*bb0);
            float n1 = warp_sum(w2*a1*bb1);
            float s1 = warp_sum(w2*a1*a1);
            float q1 = warp_sum(w2*bb1*bb1);
            if (lane == 0){
                red[0][l][0][wp] = n0; red[0][l][1][wp] = s0; red[0][l][2][wp] = q0;
                red[1][l][0][wp] = n1; red[1][l][1][wp] = s1; red[1][l][2][wp] = q1;
            }
        }
        __syncthreads();
        if (tid < Lz){
            float N=0.f, A=0.f, B2=0.f;
            #pragma unroll
            for (int i = 0; i < 8; i++){ N += red[0][tid][0][i]; A += red[0][tid][1][i]; B2 += red[0][tid][2][i]; }
            g_s[OFF_MVP + (long long)(b*Sz + s)*AGGz + 22 + wsel*10 + tid]
                = N / fmaxf(sqrtf(A)*sqrtf(B2), EPSf);
        } else if (tid >= 32 && tid < 32 + Lz){
            int ll = tid - 32;
            float N=0.f, A=0.f, B2=0.f;
            #pragma unroll
            for (int i = 0; i < 8; i++){ N += red[1][ll][0][i]; A += red[1][ll][1][i]; B2 += red[1][ll][2][i]; }
            g_s[OFF_MVH + (long long)(b*Sz + s)*AGGz + 22 + wsel*10 + ll]
                = N / fmaxf(sqrtf(A)*sqrtf(B2), EPSf);
        }
        __syncthreads();   // red reused next kk
    }
}

__global__ void means_kernel(const float* __restrict__ left, const float* __restrict__ right){
    int which = blockIdx.x >> 2, b = blockIdx.x & 3;   // grid 8, 320 threads
    int d = threadIdx.x;
    if (d >= Dz) return;
    const float* x = which ? right : left;
    float s = 0.f;
    for (int t = 0; t < Sz; t++) s += x[((long long)b*Sz + t)*Dz + d];
    g_s[OFF_MEANS + (long long)which*Bz*Dz + (long long)b*Dz + d] = s / (float)Sz;
}

__global__ void fc1_kernel(const float* __restrict__ fc1_b){
    int b = blockIdx.x;                  // grid B, 512 threads
    int tid = threadIdx.x;
    __shared__ float feat[FEATN + 6];
    for (int i = tid; i < FEATN; i += 512){
        float v;
        if (i < 1024)       v = g_s[OFF_HT + (long long)(i >> 8)*Bz*Hz + (long long)b*Hz + (i & 255)];
        else if (i < 1026)  v = 0.5f;
        else if (i < 1326)  v = g_s[OFF_MEANS + (long long)b*Dz + (i - 1026)];
        else                v = g_s[OFF_MEANS + (long long)Bz*Dz + (long long)b*Dz + (i - 1326)];
        feat[i] = v;
    }
    __syncthreads();
    float acc = fc1_b[tid];
    for (int k = 0; k < FEATN; k++)
        acc = fmaf(feat[k], g_s[OFF_FC1WT + (long long)k*512 + tid], acc);
    g_s[OFF_FC1O + (long long)b*512 + tid] = tanhf(acc);
}

__global__ void fc2_kernel(const float* __restrict__ W2, const float* __restrict__ b2,
                           float* __restrict__ out){
    int b = blockIdx.x;                  // grid B, 512 threads
    int tid = threadIdx.x;
    __shared__ float y[512];
    y[tid] = g_s[OFF_FC1O + (long long)b*512 + tid];
    __syncthreads();
    if (tid < NCLSz){
        float acc = b2[tid];
        for (int o = 0; o < 512; o++) acc = fmaf(y[o], W2[(long long)tid*512 + o], acc);
        out[b*NCLSz + tid] = acc;
    }
}

extern "C" void kernel_launch(void* const* d_in, const int* in_sizes, int n_in,
                              void* d_out, int out_size){
    const float* left      = (const float*)d_in[0];
    const float* right     = (const float*)d_in[1];
    const float* ctx_Wih_f = (const float*)d_in[2];
    const float* ctx_Whh_f = (const float*)d_in[3];
    const float* ctx_b_f   = (const float*)d_in[4];
    const float* ctx_Wih_b = (const float*)d_in[5];
    const float* ctx_Whh_b = (const float*)d_in[6];
    const float* ctx_b_b   = (const float*)d_in[7];
    const float* agg_Wih_f = (const float*)d_in[8];
    const float* agg_Whh_f = (const float*)d_in[9];
    const float* agg_b_f   = (const float*)d_in[10];
    const float* agg_Wih_b = (const float*)d_in[11];
    const float* agg_Whh_b = (const float*)d_in[12];
    const float* agg_b_b   = (const float*)d_in[13];
    const float* mp_w3     = (const float*)d_in[14];
    const float* mp_w4     = (const float*)d_in[15];
    const float* mp_w5     = (const float*)d_in[16];
    const float* mp_w6     = (const float*)d_in[17];
    const float* mp_w7     = (const float*)d_in[18];
    const float* mp_w8     = (const float*)d_in[19];
    const float* fc1_W     = (const float*)d_in[20];
    const float* fc1_b     = (const float*)d_in[21];
    const float* fc2_W     = (const float*)d_in[22];
    const float* fc2_b     = (const float*)d_in[23];
    float* out = (float*)d_out;

    // weight transposes: 2 launches (lstm7 stays launch #4 for ncu)
    transpose2_kernel<<<dim3(128,1,2),256>>>(ctx_Wih_f, ctx_Wih_b, OFF_WIHT_CF, OFF_WIHT_CB, H4z, Dz);
    transpose3_kernel<<<dim3(128,1,3),256>>>(agg_Wih_f, agg_Wih_b, fc1_W,
        OFF_WIHT_AF, OFF_WIHT_AB, OFF_FC1WT, H4z, AGGz, 512, FEATN);

    // ctx pre-activation GEMMs, batched over z (left f/b, right f/b)
    gemm4_kernel<<<dim3(16,16,4),256>>>(left, right, 0, 0,
        OFF_WIHT_CF, (long long)Dz*H4z, ctx_b_f, ctx_b_b,
        OFF_PRE_CTX, Bz*Sz, H4z, Dz);

    lstm7_kernel<<<64,256>>>(0, ctx_Whh_f, ctx_Whh_b);

    norms_all_kernel<<<4*Bz*Sz,256>>>(mp_w3, mp_w4);
    attpair_kernel<<<2*Bz*Sz,256>>>(mp_w3, mp_w4);
    stats_kernel<<<dim3(2*Bz*32,2),256>>>();
    colmax_kernel<<<2*Bz*Lz,256>>>();
    mpmatch_kernel<<<2*Bz*Sz,256>>>(mp_w5, mp_w6, mp_w7, mp_w8);
    means_kernel<<<8,320>>>(left, right);

    // agg pre-activation GEMMs, batched over z (mv_p f/b, mv_h f/b)
    gemm4_kernel<<<dim3(16,16,4),256>>>(nullptr, nullptr, OFF_MVP, OFF_MVH,
        OFF_WIHT_AF, (long long)AGGz*H4z, agg_b_f, agg_b_b,
        OFF_PRE_AGG, Bz*Sz, H4z, AGGz);

    lstm7_kernel<<<64,256>>>(1, agg_Whh_f, agg_Whh_b);

    fc1_kernel<<<Bz,512>>>(fc1_b);
    fc2_kernel<<<Bz,512>>>(fc2_W, fc2_b, out);
}